// round 4
// baseline (speedup 1.0000x reference)
#include <cuda_runtime.h>
#include <cstdint>
#include <math.h>

// ---------------------------------------------------------------------------
// SanaBlock: LN+adaLN -> LiteLA -> cross-attn -> GLUMBConv, B=2,N=4096,C=1152
// R4: mma tf32 GEMM with CTA 256x128 / warp 64x64 / 3-stage cp.async;
//     smem-tiled depthwise+GLU; zero_vk moved first so ncu captures qkv GEMM.
// ---------------------------------------------------------------------------
constexpr int Bb   = 2;
constexpr int Nn   = 4096;
constexpr int Cc   = 1152;
constexpr int Mkv  = 300;
constexpr int HIDd = 2880;
constexpr int HLA  = 36;
constexpr int HX   = 16;

__device__ float g_big[47185920];
__device__ float g_sh [(size_t)Bb * Nn * Cc];
__device__ float g_x1 [(size_t)Bb * Nn * Cc];
__device__ float g_x2 [(size_t)Bb * Nn * Cc];
__device__ float g_glu[(size_t)Bb * Nn * HIDd];
__device__ float g_kvb[(size_t)Bb * Mkv * 2 * Cc];
__device__ float g_vk [Bb * HLA * 33 * 32];
__device__ float g_mb [Bb * 6 * Cc];

// ---------------------------------------------------------------------------
// helpers
// ---------------------------------------------------------------------------
__device__ __forceinline__ uint32_t smem_u32(const void* p){
    uint32_t a;
    asm("{ .reg .u64 t; cvta.to.shared.u64 t, %1; cvt.u32.u64 %0, t; }"
        : "=r"(a) : "l"(p));
    return a;
}
__device__ __forceinline__ void cp16(uint32_t dst, const void* src, int srcsz){
    asm volatile("cp.async.cg.shared.global [%0], [%1], 16, %2;"
        ::"r"(dst),"l"(src),"r"(srcsz):"memory");
}
#define CP_COMMIT() asm volatile("cp.async.commit_group;":::"memory")
#define CP_WAIT2()  asm volatile("cp.async.wait_group 2;":::"memory")

__device__ __forceinline__ uint32_t f2tf(float f){
    uint32_t u; asm("cvt.rna.tf32.f32 %0, %1;" : "=r"(u) : "f"(f)); return u;
}
__device__ __forceinline__ void mma8(float* d, const uint32_t* a, const uint32_t* b){
    asm volatile("mma.sync.aligned.m16n8k8.row.col.f32.tf32.tf32.f32 "
        "{%0,%1,%2,%3},{%4,%5,%6,%7},{%8,%9},{%0,%1,%2,%3};"
        : "+f"(d[0]),"+f"(d[1]),"+f"(d[2]),"+f"(d[3])
        : "r"(a[0]),"r"(a[1]),"r"(a[2]),"r"(a[3]),"r"(b[0]),"r"(b[1]));
}

// ---------------------------------------------------------------------------
// tf32 mma NT GEMM: O[M,N] = epi(A[M,K]*B[N,K]^T + bias)
// CTA 256x128x32, 8 warps (4M x 2N), warp tile 64x64, 3-stage cp.async.
// smem rows padded to 36 floats for conflict-free fragment loads.
// EPI: 0 none, 1 silu, 2 +res, 3 +res+gate*v
// ---------------------------------------------------------------------------
constexpr int LDP      = 36;
constexpr int TILE_A_F = 256 * LDP;            // 9216 floats
constexpr int TILE_B_F = 128 * LDP;            // 4608 floats
constexpr int STAGE_F  = TILE_A_F + TILE_B_F;  // 13824 floats
constexpr int MM_SMEM  = 3 * STAGE_F * 4;      // 165888 bytes

template<bool BIAS, int EPI>
__global__ __launch_bounds__(256)
void mma_gemm(const float* __restrict__ A, const float* __restrict__ Bw,
              const float* __restrict__ bias, const float* __restrict__ res,
              const float* __restrict__ gate, float* __restrict__ O,
              int Mrows, int Nout, int K, int gateStride)
{
    extern __shared__ float smf[];
    uint32_t sbase = smem_u32(smf);
    int tid = threadIdx.x, wid = tid >> 5, lane = tid & 31;
    int warpM = wid >> 1, warpN = wid & 1;
    int m0 = blockIdx.y * 256, n0 = blockIdx.x * 128;

    const int T = K >> 5;      // K % 32 == 0 at all call sites

    auto load_tile = [&](int t, int buf) {
        uint32_t base = sbase + (uint32_t)buf * STAGE_F * 4;
        int k0 = t << 5;
        #pragma unroll
        for (int i = 0; i < 8; i++) {              // A: 256 rows
            int c = tid + (i << 8);                // 0..2047
            int row = c >> 3, kc = c & 7;
            uint32_t dst = base + (uint32_t)(row * LDP + kc * 4) * 4;
            const float* ga = A + (size_t)(m0 + row) * K + k0 + kc * 4;
            cp16(dst, ga, (m0 + row) < Mrows ? 16 : 0);
        }
        #pragma unroll
        for (int i = 0; i < 4; i++) {              // B: 128 rows
            int c = tid + (i << 8);                // 0..1023
            int row = c >> 3, kc = c & 7;
            uint32_t dst = base + (uint32_t)(TILE_A_F + row * LDP + kc * 4) * 4;
            const float* gb = Bw + (size_t)(n0 + row) * K + k0 + kc * 4;
            cp16(dst, gb, (n0 + row) < Nout ? 16 : 0);
        }
    };

    float acc[4][8][4];
    #pragma unroll
    for (int mt = 0; mt < 4; mt++)
        #pragma unroll
        for (int nt = 0; nt < 8; nt++)
            #pragma unroll
            for (int q = 0; q < 4; q++) acc[mt][nt][q] = 0.f;

    load_tile(0, 0); CP_COMMIT();
    load_tile(1, 1); CP_COMMIT();

    int rA = warpM * 64 + (lane >> 2);
    int rB = warpN * 64 + (lane >> 2);
    int kq = lane & 3;

    for (int t = 0; t < T; t++) {
        int buf = t % 3;
        if (t + 2 < T) load_tile(t + 2, (t + 2) % 3);
        CP_COMMIT();               // uniform one group per iter
        CP_WAIT2();                // tile t resident
        __syncthreads();

        const float* sA = smf + buf * STAGE_F;
        const float* sB = sA + TILE_A_F;

        #pragma unroll
        for (int kk = 0; kk < 4; kk++) {
            int c0 = kk * 8 + kq;
            uint32_t af[4][4];
            #pragma unroll
            for (int mt = 0; mt < 4; mt++) {
                int r = rA + mt * 16;
                af[mt][0] = f2tf(sA[r * LDP + c0]);
                af[mt][1] = f2tf(sA[(r + 8) * LDP + c0]);
                af[mt][2] = f2tf(sA[r * LDP + c0 + 4]);
                af[mt][3] = f2tf(sA[(r + 8) * LDP + c0 + 4]);
            }
            uint32_t bf[8][2];
            #pragma unroll
            for (int nt = 0; nt < 8; nt++) {
                int r = rB + nt * 8;
                bf[nt][0] = f2tf(sB[r * LDP + c0]);
                bf[nt][1] = f2tf(sB[r * LDP + c0 + 4]);
            }
            #pragma unroll
            for (int mt = 0; mt < 4; mt++)
                #pragma unroll
                for (int nt = 0; nt < 8; nt++)
                    mma8(acc[mt][nt], af[mt], bf[nt]);
        }
        __syncthreads();
    }

    #pragma unroll
    for (int mt = 0; mt < 4; mt++) {
        #pragma unroll
        for (int half = 0; half < 2; half++) {
            int row = m0 + warpM * 64 + mt * 16 + (lane >> 2) + half * 8;
            if (row >= Mrows) continue;
            int bI = (row >= Nn) ? 1 : 0;
            #pragma unroll
            for (int nt = 0; nt < 8; nt++) {
                int col = n0 + warpN * 64 + nt * 8 + (lane & 3) * 2;
                float v0 = acc[mt][nt][half * 2];
                float v1 = acc[mt][nt][half * 2 + 1];
                if (BIAS) { v0 += bias[col]; v1 += bias[col + 1]; }
                if (EPI == 1) {
                    v0 = v0 / (1.f + __expf(-v0));
                    v1 = v1 / (1.f + __expf(-v1));
                }
                if (EPI == 2) {
                    v0 += res[(size_t)row * Nout + col];
                    v1 += res[(size_t)row * Nout + col + 1];
                }
                if (EPI == 3) {
                    v0 = res[(size_t)row * Nout + col]     + gate[bI * gateStride + col]     * v0;
                    v1 = res[(size_t)row * Nout + col + 1] + gate[bI * gateStride + col + 1] * v1;
                }
                *(float2*)&O[(size_t)row * Nout + col] = make_float2(v0, v1);
            }
        }
    }
}

// ---------------------------------------------------------------------------
// m = sst + t
// ---------------------------------------------------------------------------
__global__ void mod_kernel(const float* __restrict__ t, const float* __restrict__ sst)
{
    int i = blockIdx.x * 256 + threadIdx.x;
    if (i < Bb * 6 * Cc) g_mb[i] = sst[i % (6 * Cc)] + t[i];
}

// ---------------------------------------------------------------------------
// LayerNorm + adaLN modulate
// ---------------------------------------------------------------------------
__global__ __launch_bounds__(256)
void ln_mod_kernel(const float* __restrict__ in, float* __restrict__ out,
                   int scRow, int shRow)
{
    int row = blockIdx.x;
    int b   = row / Nn;
    const float* xr = in + (size_t)row * Cc;

    float s = 0.f, s2 = 0.f;
    for (int c = threadIdx.x; c < Cc; c += blockDim.x) {
        float v = xr[c]; s += v; s2 += v * v;
    }
    __shared__ float sh1[8], sh2[8];
    int lane = threadIdx.x & 31, wid = threadIdx.x >> 5;
    #pragma unroll
    for (int o = 16; o > 0; o >>= 1) {
        s  += __shfl_down_sync(0xffffffffu, s,  o);
        s2 += __shfl_down_sync(0xffffffffu, s2, o);
    }
    if (lane == 0) { sh1[wid] = s; sh2[wid] = s2; }
    __syncthreads();
    if (wid == 0) {
        s  = (lane < 8) ? sh1[lane] : 0.f;
        s2 = (lane < 8) ? sh2[lane] : 0.f;
        #pragma unroll
        for (int o = 4; o > 0; o >>= 1) {
            s  += __shfl_down_sync(0xffffffffu, s,  o);
            s2 += __shfl_down_sync(0xffffffffu, s2, o);
        }
        if (lane == 0) { sh1[0] = s; sh2[0] = s2; }
    }
    __syncthreads();
    float mu   = sh1[0] * (1.f / Cc);
    float var  = sh2[0] * (1.f / Cc) - mu * mu;
    float rstd = rsqrtf(var + 1e-6f);
    const float* mbp = g_mb + (size_t)b * 6 * Cc;
    for (int c = threadIdx.x; c < Cc; c += blockDim.x) {
        float sc = mbp[scRow * Cc + c];
        float sv = mbp[shRow * Cc + c];
        out[(size_t)row * Cc + c] = (xr[c] - mu) * rstd * (1.f + sc) + sv;
    }
}

// ---------------------------------------------------------------------------
// SIMT GEMM (attention batched GEMMs)
// ---------------------------------------------------------------------------
template<bool TRANSB, bool BIAS, int EPI>
__global__ __launch_bounds__(256)
void gemm_k(const float* __restrict__ A, const float* __restrict__ Bm,
            const float* __restrict__ bias, const float* __restrict__ res,
            const float* __restrict__ gate, float* __restrict__ O,
            int Mrows, int Nout, int K, int lda, int ldb, int ldo,
            int HB, long aBs, long aHs, long bBs, long bHs, long oBs, long oHs,
            int gateStride)
{
    __shared__ float As[8][128];
    __shared__ float Bs[8][128];
    if (gridDim.z > 1) {
        int z = blockIdx.z;
        int bI = z / HB, hI = z % HB;
        A  += bI * aBs + hI * aHs;
        Bm += bI * bBs + hI * bHs;
        O  += bI * oBs + hI * oHs;
    }
    int m0  = blockIdx.y * 128;
    int n0  = blockIdx.x * 128;
    int tid = threadIdx.x;
    int tx  = tid & 15, ty = tid >> 4;
    int lr  = tid >> 1;
    int lk  = (tid & 1) * 4;
    int nk  = tid >> 5;
    int nj  = (tid & 31) * 4;

    float acc[8][8];
    #pragma unroll
    for (int i = 0; i < 8; i++)
        #pragma unroll
        for (int j = 0; j < 8; j++) acc[i][j] = 0.f;

    for (int k0 = 0; k0 < K; k0 += 8) {
        {
            int gr = m0 + lr;
            #pragma unroll
            for (int i = 0; i < 4; i++) {
                int gk = k0 + lk + i;
                As[lk + i][lr] = (gr < Mrows && gk < K) ? A[(long)gr * lda + gk] : 0.f;
            }
        }
        if (TRANSB) {
            int gj = n0 + lr;
            #pragma unroll
            for (int i = 0; i < 4; i++) {
                int gk = k0 + lk + i;
                Bs[lk + i][lr] = (gj < Nout && gk < K) ? Bm[(long)gj * ldb + gk] : 0.f;
            }
        } else {
            int gk = k0 + nk;
            #pragma unroll
            for (int i = 0; i < 4; i++) {
                int gj = n0 + nj + i;
                Bs[nk][nj + i] = (gk < K && gj < Nout) ? Bm[(long)gk * ldb + gj] : 0.f;
            }
        }
        __syncthreads();
        #pragma unroll
        for (int kk = 0; kk < 8; kk++) {
            float af[8], bf[8];
            *(float4*)&af[0] = *(const float4*)&As[kk][ty * 8];
            *(float4*)&af[4] = *(const float4*)&As[kk][ty * 8 + 4];
            *(float4*)&bf[0] = *(const float4*)&Bs[kk][tx * 8];
            *(float4*)&bf[4] = *(const float4*)&Bs[kk][tx * 8 + 4];
            #pragma unroll
            for (int i = 0; i < 8; i++)
                #pragma unroll
                for (int j = 0; j < 8; j++)
                    acc[i][j] = fmaf(af[i], bf[j], acc[i][j]);
        }
        __syncthreads();
    }

    #pragma unroll
    for (int i = 0; i < 8; i++) {
        int row = m0 + ty * 8 + i;
        if (row >= Mrows) continue;
        #pragma unroll
        for (int j = 0; j < 8; j++) {
            int col = n0 + tx * 8 + j;
            if (col >= Nout) continue;
            float v = acc[i][j];
            if (BIAS) v += bias[col];
            if (EPI == 1) v = v / (1.f + __expf(-v));
            if (EPI == 2) v = res[(long)row * ldo + col] + v;
            if (EPI == 3) {
                int bI = row / Nn;
                v = res[(long)row * ldo + col] + gate[bI * gateStride + col] * v;
            }
            O[(long)row * ldo + col] = v;
        }
    }
}

// ---------------------------------------------------------------------------
// LiteLA vk accumulation + epilogue
// ---------------------------------------------------------------------------
__global__ void zero_vk_kernel()
{
    int i = blockIdx.x * 256 + threadIdx.x;
    if (i < Bb * HLA * 33 * 32) g_vk[i] = 0.f;
}

__global__ __launch_bounds__(256)
void vk_kernel(const float* __restrict__ qkv, float* __restrict__ vkout)
{
    int bh = blockIdx.x;
    int b  = bh / HLA, h = bh % HLA;
    int split = blockIdx.y;
    __shared__ float ks[32][33];
    __shared__ float vs[32][33];
    float acc[5] = {0.f, 0.f, 0.f, 0.f, 0.f};
    int tid = threadIdx.x;
    const size_t base = (size_t)b * Nn * 3 * Cc;
    int nStart = split * (Nn / 16);
    for (int n0 = nStart; n0 < nStart + Nn / 16; n0 += 32) {
        for (int li = tid; li < 1024; li += 256) {
            int nn = li >> 5, dc = li & 31;
            size_t off = base + (size_t)(n0 + nn) * 3 * Cc + h * 32 + dc;
            ks[nn][dc] = fmaxf(qkv[off + Cc], 0.f);
            vs[nn][dc] = qkv[off + 2 * Cc];
        }
        __syncthreads();
        #pragma unroll
        for (int u = 0; u < 5; u++) {
            int idx = tid + 256 * u;
            if (idx < 1056) {
                int e = idx >> 5, dc = idx & 31;
                float a = acc[u];
                if (e == 32) {
                    #pragma unroll
                    for (int nn = 0; nn < 32; nn++) a += ks[nn][dc];
                } else {
                    #pragma unroll
                    for (int nn = 0; nn < 32; nn++) a += vs[nn][e] * ks[nn][dc];
                }
                acc[u] = a;
            }
        }
        __syncthreads();
    }
    #pragma unroll
    for (int u = 0; u < 5; u++) {
        int idx = tid + 256 * u;
        if (idx < 1056) {
            int e = idx >> 5, dc = idx & 31;
            atomicAdd(&vkout[((size_t)bh * 33 + e) * 32 + dc], acc[u]);
        }
    }
}

__global__ __launch_bounds__(256)
void la_out_kernel(const float* __restrict__ qkv, const float* __restrict__ vk,
                   float* __restrict__ out)
{
    int row = blockIdx.x;
    int b   = row / Nn;
    __shared__ float q[Cc];
    __shared__ float den[HLA];
    const float* qr = qkv + (size_t)row * 3 * Cc;
    for (int c = threadIdx.x; c < Cc; c += blockDim.x) q[c] = fmaxf(qr[c], 0.f);
    __syncthreads();
    if (threadIdx.x < HLA) {
        int h = threadIdx.x;
        const float* vkh = vk + ((size_t)(b * HLA + h) * 33 + 32) * 32;
        float s = 0.f;
        #pragma unroll
        for (int d = 0; d < 32; d++) s += vkh[d] * q[h * 32 + d];
        den[h] = s + 1e-8f;
    }
    __syncthreads();
    for (int c = threadIdx.x; c < Cc; c += blockDim.x) {
        int h = c >> 5, dd = c & 31;
        const float* vkr = vk + ((size_t)(b * HLA + h) * 33 + dd) * 32;
        const float* qh  = q + h * 32;
        float s = 0.f;
        #pragma unroll
        for (int d = 0; d < 32; d++) s += vkr[d] * qh[d];
        out[(size_t)row * Cc + c] = s / den[h];
    }
}

// ---------------------------------------------------------------------------
// Cross-attn softmax (one warp per row)
// ---------------------------------------------------------------------------
__global__ __launch_bounds__(256)
void softmax_kernel(float* __restrict__ s, long rows)
{
    long gw  = ((long)blockIdx.x * blockDim.x + threadIdx.x) >> 5;
    int lane = threadIdx.x & 31;
    if (gw >= rows) return;
    float* r = s + gw * Mkv;
    const float scale = 0.11785113019775793f;
    float v[10];
    float mx = -1e30f;
    #pragma unroll
    for (int i = 0; i < 10; i++) {
        int m = lane + 32 * i;
        v[i] = (m < Mkv) ? r[m] * scale : -1e30f;
        mx = fmaxf(mx, v[i]);
    }
    #pragma unroll
    for (int o = 16; o > 0; o >>= 1) mx = fmaxf(mx, __shfl_xor_sync(0xffffffffu, mx, o));
    float sum = 0.f;
    #pragma unroll
    for (int i = 0; i < 10; i++) { v[i] = __expf(v[i] - mx); sum += v[i]; }
    #pragma unroll
    for (int o = 16; o > 0; o >>= 1) sum += __shfl_xor_sync(0xffffffffu, sum, o);
    float inv = 1.f / sum;
    #pragma unroll
    for (int i = 0; i < 10; i++) {
        int m = lane + 32 * i;
        if (m < Mkv) r[m] = v[i] * inv;
    }
}

// ---------------------------------------------------------------------------
// depthwise 3x3 + bias + GLU, smem-tiled: 8x8 spatial x 64 ch per CTA.
// grid: (HID/64, 64 tiles, Bb), block 256.
// ---------------------------------------------------------------------------
__global__ __launch_bounds__(256)
void dwglu_kernel(const float* __restrict__ h, const float* __restrict__ dww,
                  const float* __restrict__ dwb, float* __restrict__ out)
{
    __shared__ float sa[100][64];
    __shared__ float sg[100][64];
    int tid = threadIdx.x;
    int c0  = blockIdx.x * 64;
    int y0  = (blockIdx.y >> 3) * 8, x0 = (blockIdx.y & 7) * 8;
    int b   = blockIdx.z;

    // per-thread fixed channel
    int ch = tid & 63;
    float wA[9], wG[9];
    #pragma unroll
    for (int tp = 0; tp < 9; tp++) {
        wA[tp] = dww[(size_t)(c0 + ch) * 9 + tp];
        wG[tp] = dww[(size_t)(c0 + ch + HIDd) * 9 + tp];
    }
    float bA = dwb[c0 + ch], bG = dwb[c0 + ch + HIDd];

    // load 10x10 halo tile, both halves, float4 over channels
    for (int li = tid; li < 1600; li += 256) {
        int pos = li >> 4, q = li & 15;
        int py = pos / 10, px = pos % 10;
        int yy = y0 + py - 1, xx = x0 + px - 1;
        float4 va = make_float4(0.f, 0.f, 0.f, 0.f), vg = va;
        if (yy >= 0 && yy < 64 && xx >= 0 && xx < 64) {
            const float* src = h + ((size_t)b * Nn + yy * 64 + xx) * (2 * HIDd) + c0 + q * 4;
            va = *(const float4*)src;
            vg = *(const float4*)(src + HIDd);
        }
        *(float4*)&sa[pos][q * 4] = va;
        *(float4*)&sg[pos][q * 4] = vg;
    }
    __syncthreads();

    #pragma unroll
    for (int i = 0; i < 16; i++) {
        int pos = (tid >> 6) + i * 4;        // 0..63
        int py = pos >> 3, px = pos & 7;
        int s0 = (py + 1) * 10 + (px + 1);
        float accA = bA, accG = bG;
        #pragma unroll
        for (int dy = -1; dy <= 1; dy++)
            #pragma unroll
            for (int dx = -1; dx <= 1; dx++) {
                int s = s0 + dy * 10 + dx;
                int tp = (dy + 1) * 3 + (dx + 1);
                accA = fmaf(sa[s][ch], wA[tp], accA);
                accG = fmaf(sg[s][ch], wG[tp], accG);
            }
        int n = (y0 + py) * 64 + (x0 + px);
        out[((size_t)b * Nn + n) * HIDd + c0 + ch] = accA * (accG / (1.f + __expf(-accG)));
    }
}

// ---------------------------------------------------------------------------
extern "C" void kernel_launch(void* const* d_in, const int* /*in_sizes*/, int /*n_in*/,
                              void* d_out, int /*out_size*/)
{
    const float* x       = (const float*)d_in[0];
    const float* y       = (const float*)d_in[1];
    const float* t       = (const float*)d_in[2];
    const float* sst     = (const float*)d_in[3];
    const float* qkv_w   = (const float*)d_in[4];
    const float* aproj_w = (const float*)d_in[5];
    const float* aproj_b = (const float*)d_in[6];
    const float* q_w     = (const float*)d_in[7];
    const float* q_b     = (const float*)d_in[8];
    const float* kv_w    = (const float*)d_in[9];
    const float* kv_b    = (const float*)d_in[10];
    const float* cproj_w = (const float*)d_in[11];
    const float* cproj_b = (const float*)d_in[12];
    const float* inv_w   = (const float*)d_in[13];
    const float* inv_b   = (const float*)d_in[14];
    const float* dw_w    = (const float*)d_in[15];
    const float* dw_b    = (const float*)d_in[16];
    const float* pw_w    = (const float*)d_in[17];
    float* out = (float*)d_out;

    float *p_big, *p_sh, *p_x1, *p_x2, *p_glu, *p_kv, *p_vk, *p_m;
    cudaGetSymbolAddress((void**)&p_big, g_big);
    cudaGetSymbolAddress((void**)&p_sh,  g_sh);
    cudaGetSymbolAddress((void**)&p_x1,  g_x1);
    cudaGetSymbolAddress((void**)&p_x2,  g_x2);
    cudaGetSymbolAddress((void**)&p_glu, g_glu);
    cudaGetSymbolAddress((void**)&p_kv,  g_kvb);
    cudaGetSymbolAddress((void**)&p_vk,  g_vk);
    cudaGetSymbolAddress((void**)&p_m,   g_mb);

    cudaFuncSetAttribute(mma_gemm<false,0>, cudaFuncAttributeMaxDynamicSharedMemorySize, MM_SMEM);
    cudaFuncSetAttribute(mma_gemm<true, 0>, cudaFuncAttributeMaxDynamicSharedMemorySize, MM_SMEM);
    cudaFuncSetAttribute(mma_gemm<true, 1>, cudaFuncAttributeMaxDynamicSharedMemorySize, MM_SMEM);
    cudaFuncSetAttribute(mma_gemm<true, 2>, cudaFuncAttributeMaxDynamicSharedMemorySize, MM_SMEM);
    cudaFuncSetAttribute(mma_gemm<true, 3>, cudaFuncAttributeMaxDynamicSharedMemorySize, MM_SMEM);
    cudaFuncSetAttribute(mma_gemm<false,3>, cudaFuncAttributeMaxDynamicSharedMemorySize, MM_SMEM);

    const int ROWS = Bb * Nn;  // 8192

    // zero_vk first: shifts the ncu capture point onto the qkv mma_gemm
    zero_vk_kernel<<<(Bb * HLA * 33 * 32 + 255) / 256, 256>>>();
    mod_kernel<<<(Bb * 6 * Cc + 255) / 256, 256>>>(t, sst);
    ln_mod_kernel<<<ROWS, 256>>>(x, p_sh, 1, 0);

    // qkv = xmod1 @ qkv_w.T
    mma_gemm<false,0><<<dim3(27, 32), 256, MM_SMEM>>>(
        p_sh, qkv_w, nullptr, nullptr, nullptr, p_big, ROWS, 3 * Cc, Cc, 0);

    vk_kernel<<<dim3(Bb * HLA, 16), 256>>>(p_big, p_vk);
    la_out_kernel<<<ROWS, 256>>>(p_big, p_vk, p_sh);

    // x1 = x + g_a * (la @ aproj_w.T + b)
    mma_gemm<true,3><<<dim3(9, 32), 256, MM_SMEM>>>(
        p_sh, aproj_w, aproj_b, x, p_m + 2 * Cc, p_x1, ROWS, Cc, Cc, 6 * Cc);

    // q = x1 @ q_w.T + q_b
    mma_gemm<true,0><<<dim3(9, 32), 256, MM_SMEM>>>(
        p_x1, q_w, q_b, nullptr, nullptr, p_sh, ROWS, Cc, Cc, 0);

    // kv = y @ kv_w.T + kv_b
    mma_gemm<true,0><<<dim3(18, 3), 256, MM_SMEM>>>(
        y, kv_w, kv_b, nullptr, nullptr, p_kv, Bb * Mkv, 2 * Cc, Cc, 0);

    // scores[b,h] = q @ k.T (batched, SIMT)
    gemm_k<true, false, 0><<<dim3(3, 32, Bb * HX), 256>>>(
        p_sh, p_kv, nullptr, nullptr, nullptr, p_big,
        Nn, Mkv, 72, Cc, 2 * Cc, Mkv,
        HX, (long)Nn * Cc, 72, (long)Mkv * 2 * Cc, 72,
        (long)HX * Nn * Mkv, (long)Nn * Mkv, 0);

    softmax_kernel<<<(Bb * HX * Nn) / 8, 256>>>(p_big, (long)Bb * HX * Nn);

    // o[b,h] = a @ v (batched NN, SIMT)
    gemm_k<false, false, 0><<<dim3(1, 32, Bb * HX), 256>>>(
        p_big, p_kv + Cc, nullptr, nullptr, nullptr, p_sh,
        Nn, 72, Mkv, Mkv, 2 * Cc, Cc,
        HX, (long)HX * Nn * Mkv, (long)Nn * Mkv, (long)Mkv * 2 * Cc, 72,
        (long)Nn * Cc, 72, 0);

    // x2 = x1 + o @ cproj_w.T + b
    mma_gemm<true,2><<<dim3(9, 32), 256, MM_SMEM>>>(
        p_sh, cproj_w, cproj_b, p_x1, nullptr, p_x2, ROWS, Cc, Cc, 0);

    ln_mod_kernel<<<ROWS, 256>>>(p_x2, p_sh, 4, 3);

    // h = silu(xmod2 @ inv_w.T + b)
    mma_gemm<true,1><<<dim3(45, 32), 256, MM_SMEM>>>(
        p_sh, inv_w, inv_b, nullptr, nullptr, p_big, ROWS, 2 * HIDd, Cc, 0);

    // depthwise 3x3 + GLU (smem-tiled)
    dwglu_kernel<<<dim3(HIDd / 64, 64, Bb), 256>>>(p_big, dw_w, dw_b, p_glu);

    // out = x2 + g_m * (glu @ pw_w.T)
    mma_gemm<false,3><<<dim3(9, 32), 256, MM_SMEM>>>(
        p_glu, pw_w, nullptr, p_x2, p_m + 5 * Cc, out, ROWS, Cc, HIDd, 6 * Cc);
}

// round 5
// speedup vs baseline: 1.8870x; 1.8870x over previous
#include <cuda_runtime.h>
#include <cstdint>
#include <math.h>

// ---------------------------------------------------------------------------
// SanaBlock: LN+adaLN -> LiteLA -> cross-attn -> GLUMBConv, B=2,N=4096,C=1152
// R5: R3-proven 128x128 tf32 mma GEMM generalized (lda/ldb/batch/K-tail) and
//     used for cross-attention too (scores K=72, o K=320 via v^T); tiled dwglu.
// ---------------------------------------------------------------------------
constexpr int Bb   = 2;
constexpr int Nn   = 4096;
constexpr int Cc   = 1152;
constexpr int Mkv  = 300;
constexpr int HIDd = 2880;
constexpr int HLA  = 36;
constexpr int HX   = 16;
constexpr int SLD  = 320;   // scores row stride (300 padded to 320)

__device__ float g_big[47185920];   // qkv -> scores(ld320) -> h
__device__ float g_sh [(size_t)Bb * Nn * Cc];
__device__ float g_x1 [(size_t)Bb * Nn * Cc];
__device__ float g_x2 [(size_t)Bb * Nn * Cc];
__device__ float g_glu[(size_t)Bb * Nn * HIDd];
__device__ float g_kvb[(size_t)Bb * Mkv * 2 * Cc];
__device__ float g_vt [(size_t)Bb * HX * 72 * SLD];
__device__ float g_vk [Bb * HLA * 33 * 32];
__device__ float g_mb [Bb * 6 * Cc];

// ---------------------------------------------------------------------------
// helpers
// ---------------------------------------------------------------------------
__device__ __forceinline__ uint32_t smem_u32(const void* p){
    uint32_t a;
    asm("{ .reg .u64 t; cvta.to.shared.u64 t, %1; cvt.u32.u64 %0, t; }"
        : "=r"(a) : "l"(p));
    return a;
}
__device__ __forceinline__ void cp16(uint32_t dst, const void* src, int srcsz){
    asm volatile("cp.async.cg.shared.global [%0], [%1], 16, %2;"
        ::"r"(dst),"l"(src),"r"(srcsz):"memory");
}
#define CP_COMMIT() asm volatile("cp.async.commit_group;":::"memory")
#define CP_WAIT1()  asm volatile("cp.async.wait_group 1;":::"memory")

__device__ __forceinline__ uint32_t f2tf(float f){
    uint32_t u; asm("cvt.rna.tf32.f32 %0, %1;" : "=r"(u) : "f"(f)); return u;
}
__device__ __forceinline__ void mma8(float* d, const uint32_t* a, const uint32_t* b){
    asm volatile("mma.sync.aligned.m16n8k8.row.col.f32.tf32.tf32.f32 "
        "{%0,%1,%2,%3},{%4,%5,%6,%7},{%8,%9},{%0,%1,%2,%3};"
        : "+f"(d[0]),"+f"(d[1]),"+f"(d[2]),"+f"(d[3])
        : "r"(a[0]),"r"(a[1]),"r"(a[2]),"r"(a[3]),"r"(b[0]),"r"(b[1]));
}

// ---------------------------------------------------------------------------
// tf32 mma NT GEMM: O[M,N] = epi(A[M,K]*B[NloadB,K]^T + bias)
// CTA 128x128x32, 8 warps (4M x 2N), warp tile 32x64, 2-stage cp.async.
// K-tail (K not multiple of 32) handled by zero-filled smem (zeros are no-ops).
// B rows >= NloadB zero-filled; stores guarded by col < Nstore.
// Batched via blockIdx.z (bI=z/HB, hI=z%HB).
// EPI: 0 none, 1 silu, 2 +res, 3 +res+gate*v
// ---------------------------------------------------------------------------
constexpr int LDP     = 36;
constexpr int TILE_F  = 128 * LDP;
constexpr int STAGE_F = 2 * TILE_F;
constexpr int MM_SMEM = 2 * STAGE_F * 4;   // 73728 bytes

template<bool BIAS, int EPI>
__global__ __launch_bounds__(256)
void mma_gemm(const float* __restrict__ A, const float* __restrict__ Bw,
              const float* __restrict__ bias, const float* __restrict__ res,
              const float* __restrict__ gate, float* __restrict__ O,
              int Mrows, int NloadB, int Nstore, int K,
              int lda, int ldb, int ldo,
              int HB, long aBs, long aHs, long bBs, long bHs, long oBs, long oHs,
              int gateStride)
{
    extern __shared__ float smf[];
    uint32_t sbase = smem_u32(smf);
    int tid = threadIdx.x, wid = tid >> 5, lane = tid & 31;
    int warpM = wid >> 1, warpN = wid & 1;
    int m0 = blockIdx.y * 128, n0 = blockIdx.x * 128;

    if (gridDim.z > 1) {
        int z = blockIdx.z;
        int bI = z / HB, hI = z % HB;
        A  += bI * aBs + hI * aHs;
        Bw += bI * bBs + hI * bHs;
        O  += bI * oBs + hI * oHs;
    }

    const int T = (K + 31) >> 5;

    auto load_tile = [&](int t, int buf) {
        uint32_t base = sbase + (uint32_t)buf * STAGE_F * 4;
        int k0 = t << 5;
        #pragma unroll
        for (int i = 0; i < 4; i++) {
            int c = tid + (i << 8);           // 0..1023
            int row = c >> 3, kc = c & 7;
            int gk = k0 + kc * 4;
            uint32_t dst = base + (uint32_t)(row * LDP + kc * 4) * 4;
            const float* ga = A + (size_t)(m0 + row) * lda + gk;
            cp16(dst, ga, ((m0 + row) < Mrows && gk < K) ? 16 : 0);
            uint32_t dstB = dst + TILE_F * 4;
            const float* gb = Bw + (size_t)(n0 + row) * ldb + gk;
            cp16(dstB, gb, ((n0 + row) < NloadB && gk < K) ? 16 : 0);
        }
    };

    float acc[2][8][4];
    #pragma unroll
    for (int mt = 0; mt < 2; mt++)
        #pragma unroll
        for (int nt = 0; nt < 8; nt++)
            #pragma unroll
            for (int q = 0; q < 4; q++) acc[mt][nt][q] = 0.f;

    load_tile(0, 0); CP_COMMIT();

    int rA = warpM * 32 + (lane >> 2);
    int rB = warpN * 64 + (lane >> 2);
    int kq = lane & 3;

    for (int t = 0; t < T; t++) {
        int buf = t & 1;
        if (t + 1 < T) load_tile(t + 1, buf ^ 1);
        CP_COMMIT();
        CP_WAIT1();
        __syncthreads();

        const float* sA = smf + buf * STAGE_F;
        const float* sB = sA + TILE_F;

        #pragma unroll
        for (int kk = 0; kk < 4; kk++) {
            int c0 = kk * 8 + kq;
            uint32_t af[2][4];
            #pragma unroll
            for (int mt = 0; mt < 2; mt++) {
                int r = rA + mt * 16;
                af[mt][0] = f2tf(sA[r * LDP + c0]);
                af[mt][1] = f2tf(sA[(r + 8) * LDP + c0]);
                af[mt][2] = f2tf(sA[r * LDP + c0 + 4]);
                af[mt][3] = f2tf(sA[(r + 8) * LDP + c0 + 4]);
            }
            uint32_t bf[8][2];
            #pragma unroll
            for (int nt = 0; nt < 8; nt++) {
                int r = rB + nt * 8;
                bf[nt][0] = f2tf(sB[r * LDP + c0]);
                bf[nt][1] = f2tf(sB[r * LDP + c0 + 4]);
            }
            #pragma unroll
            for (int mt = 0; mt < 2; mt++)
                #pragma unroll
                for (int nt = 0; nt < 8; nt++)
                    mma8(acc[mt][nt], af[mt], bf[nt]);
        }
        __syncthreads();
    }

    #pragma unroll
    for (int mt = 0; mt < 2; mt++) {
        #pragma unroll
        for (int half = 0; half < 2; half++) {
            int row = m0 + warpM * 32 + mt * 16 + (lane >> 2) + half * 8;
            if (row >= Mrows) continue;
            int bI = (row >= Nn) ? 1 : 0;
            #pragma unroll
            for (int nt = 0; nt < 8; nt++) {
                int col = n0 + warpN * 64 + nt * 8 + (lane & 3) * 2;
                if (col >= Nstore) continue;
                float v0 = acc[mt][nt][half * 2];
                float v1 = acc[mt][nt][half * 2 + 1];
                if (BIAS) { v0 += bias[col]; v1 += bias[col + 1]; }
                if (EPI == 1) {
                    v0 = v0 / (1.f + __expf(-v0));
                    v1 = v1 / (1.f + __expf(-v1));
                }
                if (EPI == 2) {
                    v0 += res[(size_t)row * ldo + col];
                    v1 += res[(size_t)row * ldo + col + 1];
                }
                if (EPI == 3) {
                    v0 = res[(size_t)row * ldo + col]     + gate[bI * gateStride + col]     * v0;
                    v1 = res[(size_t)row * ldo + col + 1] + gate[bI * gateStride + col + 1] * v1;
                }
                *(float2*)&O[(size_t)row * ldo + col] = make_float2(v0, v1);
            }
        }
    }
}

// ---------------------------------------------------------------------------
// m = sst + t
// ---------------------------------------------------------------------------
__global__ void mod_kernel(const float* __restrict__ t, const float* __restrict__ sst)
{
    int i = blockIdx.x * 256 + threadIdx.x;
    if (i < Bb * 6 * Cc) g_mb[i] = sst[i % (6 * Cc)] + t[i];
}

// ---------------------------------------------------------------------------
// LayerNorm + adaLN modulate
// ---------------------------------------------------------------------------
__global__ __launch_bounds__(256)
void ln_mod_kernel(const float* __restrict__ in, float* __restrict__ out,
                   int scRow, int shRow)
{
    int row = blockIdx.x;
    int b   = row / Nn;
    const float* xr = in + (size_t)row * Cc;

    float s = 0.f, s2 = 0.f;
    for (int c = threadIdx.x; c < Cc; c += blockDim.x) {
        float v = xr[c]; s += v; s2 += v * v;
    }
    __shared__ float sh1[8], sh2[8];
    int lane = threadIdx.x & 31, wid = threadIdx.x >> 5;
    #pragma unroll
    for (int o = 16; o > 0; o >>= 1) {
        s  += __shfl_down_sync(0xffffffffu, s,  o);
        s2 += __shfl_down_sync(0xffffffffu, s2, o);
    }
    if (lane == 0) { sh1[wid] = s; sh2[wid] = s2; }
    __syncthreads();
    if (wid == 0) {
        s  = (lane < 8) ? sh1[lane] : 0.f;
        s2 = (lane < 8) ? sh2[lane] : 0.f;
        #pragma unroll
        for (int o = 4; o > 0; o >>= 1) {
            s  += __shfl_down_sync(0xffffffffu, s,  o);
            s2 += __shfl_down_sync(0xffffffffu, s2, o);
        }
        if (lane == 0) { sh1[0] = s; sh2[0] = s2; }
    }
    __syncthreads();
    float mu   = sh1[0] * (1.f / Cc);
    float var  = sh2[0] * (1.f / Cc) - mu * mu;
    float rstd = rsqrtf(var + 1e-6f);
    const float* mbp = g_mb + (size_t)b * 6 * Cc;
    for (int c = threadIdx.x; c < Cc; c += blockDim.x) {
        float sc = mbp[scRow * Cc + c];
        float sv = mbp[shRow * Cc + c];
        out[(size_t)row * Cc + c] = (xr[c] - mu) * rstd * (1.f + sc) + sv;
    }
}

// ---------------------------------------------------------------------------
// LiteLA vk accumulation + epilogue
// ---------------------------------------------------------------------------
__global__ void zero_vk_kernel()
{
    int i = blockIdx.x * 256 + threadIdx.x;
    if (i < Bb * HLA * 33 * 32) g_vk[i] = 0.f;
}

__global__ __launch_bounds__(256)
void vk_kernel(const float* __restrict__ qkv, float* __restrict__ vkout)
{
    int bh = blockIdx.x;
    int b  = bh / HLA, h = bh % HLA;
    int split = blockIdx.y;
    __shared__ float ks[32][33];
    __shared__ float vs[32][33];
    float acc[5] = {0.f, 0.f, 0.f, 0.f, 0.f};
    int tid = threadIdx.x;
    const size_t base = (size_t)b * Nn * 3 * Cc;
    int nStart = split * (Nn / 16);
    for (int n0 = nStart; n0 < nStart + Nn / 16; n0 += 32) {
        for (int li = tid; li < 1024; li += 256) {
            int nn = li >> 5, dc = li & 31;
            size_t off = base + (size_t)(n0 + nn) * 3 * Cc + h * 32 + dc;
            ks[nn][dc] = fmaxf(qkv[off + Cc], 0.f);
            vs[nn][dc] = qkv[off + 2 * Cc];
        }
        __syncthreads();
        #pragma unroll
        for (int u = 0; u < 5; u++) {
            int idx = tid + 256 * u;
            if (idx < 1056) {
                int e = idx >> 5, dc = idx & 31;
                float a = acc[u];
                if (e == 32) {
                    #pragma unroll
                    for (int nn = 0; nn < 32; nn++) a += ks[nn][dc];
                } else {
                    #pragma unroll
                    for (int nn = 0; nn < 32; nn++) a += vs[nn][e] * ks[nn][dc];
                }
                acc[u] = a;
            }
        }
        __syncthreads();
    }
    #pragma unroll
    for (int u = 0; u < 5; u++) {
        int idx = tid + 256 * u;
        if (idx < 1056) {
            int e = idx >> 5, dc = idx & 31;
            atomicAdd(&vkout[((size_t)bh * 33 + e) * 32 + dc], acc[u]);
        }
    }
}

__global__ __launch_bounds__(256)
void la_out_kernel(const float* __restrict__ qkv, const float* __restrict__ vk,
                   float* __restrict__ out)
{
    int row = blockIdx.x;
    int b   = row / Nn;
    __shared__ float q[Cc];
    __shared__ float den[HLA];
    const float* qr = qkv + (size_t)row * 3 * Cc;
    for (int c = threadIdx.x; c < Cc; c += blockDim.x) q[c] = fmaxf(qr[c], 0.f);
    __syncthreads();
    if (threadIdx.x < HLA) {
        int h = threadIdx.x;
        const float* vkh = vk + ((size_t)(b * HLA + h) * 33 + 32) * 32;
        float s = 0.f;
        #pragma unroll
        for (int d = 0; d < 32; d++) s += vkh[d] * q[h * 32 + d];
        den[h] = s + 1e-8f;
    }
    __syncthreads();
    for (int c = threadIdx.x; c < Cc; c += blockDim.x) {
        int h = c >> 5, dd = c & 31;
        const float* vkr = vk + ((size_t)(b * HLA + h) * 33 + dd) * 32;
        const float* qh  = q + h * 32;
        float s = 0.f;
        #pragma unroll
        for (int d = 0; d < 32; d++) s += vkr[d] * qh[d];
        out[(size_t)row * Cc + c] = s / den[h];
    }
}

// ---------------------------------------------------------------------------
// v^T materialization: vt[z][d][m] = v[b, m, h*72+d], m padded to SLD w/ zeros
// ---------------------------------------------------------------------------
__global__ void vt_kernel(const float* __restrict__ kv, float* __restrict__ vt)
{
    long idx = (long)blockIdx.x * 256 + threadIdx.x;
    if (idx >= (long)Bb * HX * 72 * SLD) return;
    int  m = (int)(idx % SLD);
    long r = idx / SLD;
    int  d = (int)(r % 72);
    int  z = (int)(r / 72);
    int  b = z / HX, h = z % HX;
    float v = 0.f;
    if (m < Mkv) v = kv[((size_t)b * Mkv + m) * 2 * Cc + Cc + h * 72 + d];
    vt[idx] = v;
}

// ---------------------------------------------------------------------------
// Cross-attn softmax over M=300 (one warp per row), ld = SLD
// ---------------------------------------------------------------------------
__global__ __launch_bounds__(256)
void softmax_kernel(float* __restrict__ s, long rows)
{
    long gw  = ((long)blockIdx.x * blockDim.x + threadIdx.x) >> 5;
    int lane = threadIdx.x & 31;
    if (gw >= rows) return;
    float* r = s + gw * SLD;
    const float scale = 0.11785113019775793f;
    float v[10];
    float mx = -1e30f;
    #pragma unroll
    for (int i = 0; i < 10; i++) {
        int m = lane + 32 * i;
        v[i] = (m < Mkv) ? r[m] * scale : -1e30f;
        mx = fmaxf(mx, v[i]);
    }
    #pragma unroll
    for (int o = 16; o > 0; o >>= 1) mx = fmaxf(mx, __shfl_xor_sync(0xffffffffu, mx, o));
    float sum = 0.f;
    #pragma unroll
    for (int i = 0; i < 10; i++) { v[i] = __expf(v[i] - mx); sum += v[i]; }
    #pragma unroll
    for (int o = 16; o > 0; o >>= 1) sum += __shfl_xor_sync(0xffffffffu, sum, o);
    float inv = 1.f / sum;
    #pragma unroll
    for (int i = 0; i < 10; i++) {
        int m = lane + 32 * i;
        if (m < Mkv) r[m] = v[i] * inv;
    }
}

// ---------------------------------------------------------------------------
// depthwise 3x3 + bias + GLU, smem-tiled: 8x8 spatial x 64 ch per CTA
// ---------------------------------------------------------------------------
__global__ __launch_bounds__(256)
void dwglu_kernel(const float* __restrict__ h, const float* __restrict__ dww,
                  const float* __restrict__ dwb, float* __restrict__ out)
{
    __shared__ float sa[100][64];
    __shared__ float sg[100][64];
    int tid = threadIdx.x;
    int c0  = blockIdx.x * 64;
    int y0  = (blockIdx.y >> 3) * 8, x0 = (blockIdx.y & 7) * 8;
    int b   = blockIdx.z;

    int ch = tid & 63;
    float wA[9], wG[9];
    #pragma unroll
    for (int tp = 0; tp < 9; tp++) {
        wA[tp] = dww[(size_t)(c0 + ch) * 9 + tp];
        wG[tp] = dww[(size_t)(c0 + ch + HIDd) * 9 + tp];
    }
    float bA = dwb[c0 + ch], bG = dwb[c0 + ch + HIDd];

    for (int li = tid; li < 1600; li += 256) {
        int pos = li >> 4, q = li & 15;
        int py = pos / 10, px = pos % 10;
        int yy = y0 + py - 1, xx = x0 + px - 1;
        float4 va = make_float4(0.f, 0.f, 0.f, 0.f), vg = va;
        if (yy >= 0 && yy < 64 && xx >= 0 && xx < 64) {
            const float* src = h + ((size_t)b * Nn + yy * 64 + xx) * (2 * HIDd) + c0 + q * 4;
            va = *(const float4*)src;
            vg = *(const float4*)(src + HIDd);
        }
        *(float4*)&sa[pos][q * 4] = va;
        *(float4*)&sg[pos][q * 4] = vg;
    }
    __syncthreads();

    #pragma unroll
    for (int i = 0; i < 16; i++) {
        int pos = (tid >> 6) + i * 4;
        int py = pos >> 3, px = pos & 7;
        int s0 = (py + 1) * 10 + (px + 1);
        float accA = bA, accG = bG;
        #pragma unroll
        for (int dy = -1; dy <= 1; dy++)
            #pragma unroll
            for (int dx = -1; dx <= 1; dx++) {
                int s = s0 + dy * 10 + dx;
                int tp = (dy + 1) * 3 + (dx + 1);
                accA = fmaf(sa[s][ch], wA[tp], accA);
                accG = fmaf(sg[s][ch], wG[tp], accG);
            }
        int n = (y0 + py) * 64 + (x0 + px);
        out[((size_t)b * Nn + n) * HIDd + c0 + ch] = accA * (accG / (1.f + __expf(-accG)));
    }
}

// ---------------------------------------------------------------------------
extern "C" void kernel_launch(void* const* d_in, const int* /*in_sizes*/, int /*n_in*/,
                              void* d_out, int /*out_size*/)
{
    const float* x       = (const float*)d_in[0];
    const float* y       = (const float*)d_in[1];
    const float* t       = (const float*)d_in[2];
    const float* sst     = (const float*)d_in[3];
    const float* qkv_w   = (const float*)d_in[4];
    const float* aproj_w = (const float*)d_in[5];
    const float* aproj_b = (const float*)d_in[6];
    const float* q_w     = (const float*)d_in[7];
    const float* q_b     = (const float*)d_in[8];
    const float* kv_w    = (const float*)d_in[9];
    const float* kv_b    = (const float*)d_in[10];
    const float* cproj_w = (const float*)d_in[11];
    const float* cproj_b = (const float*)d_in[12];
    const float* inv_w   = (const float*)d_in[13];
    const float* inv_b   = (const float*)d_in[14];
    const float* dw_w    = (const float*)d_in[15];
    const float* dw_b    = (const float*)d_in[16];
    const float* pw_w    = (const float*)d_in[17];
    float* out = (float*)d_out;

    float *p_big, *p_sh, *p_x1, *p_x2, *p_glu, *p_kv, *p_vt, *p_vk, *p_m;
    cudaGetSymbolAddress((void**)&p_big, g_big);
    cudaGetSymbolAddress((void**)&p_sh,  g_sh);
    cudaGetSymbolAddress((void**)&p_x1,  g_x1);
    cudaGetSymbolAddress((void**)&p_x2,  g_x2);
    cudaGetSymbolAddress((void**)&p_glu, g_glu);
    cudaGetSymbolAddress((void**)&p_kv,  g_kvb);
    cudaGetSymbolAddress((void**)&p_vt,  g_vt);
    cudaGetSymbolAddress((void**)&p_vk,  g_vk);
    cudaGetSymbolAddress((void**)&p_m,   g_mb);

    cudaFuncSetAttribute(mma_gemm<false,0>, cudaFuncAttributeMaxDynamicSharedMemorySize, MM_SMEM);
    cudaFuncSetAttribute(mma_gemm<true, 0>, cudaFuncAttributeMaxDynamicSharedMemorySize, MM_SMEM);
    cudaFuncSetAttribute(mma_gemm<true, 1>, cudaFuncAttributeMaxDynamicSharedMemorySize, MM_SMEM);
    cudaFuncSetAttribute(mma_gemm<true, 2>, cudaFuncAttributeMaxDynamicSharedMemorySize, MM_SMEM);
    cudaFuncSetAttribute(mma_gemm<true, 3>, cudaFuncAttributeMaxDynamicSharedMemorySize, MM_SMEM);
    cudaFuncSetAttribute(mma_gemm<false,3>, cudaFuncAttributeMaxDynamicSharedMemorySize, MM_SMEM);

    const int ROWS = Bb * Nn;  // 8192

    // zero_vk first: keeps the ncu capture slot on the qkv mma_gemm
    zero_vk_kernel<<<(Bb * HLA * 33 * 32 + 255) / 256, 256>>>();
    mod_kernel<<<(Bb * 6 * Cc + 255) / 256, 256>>>(t, sst);
    ln_mod_kernel<<<ROWS, 256>>>(x, p_sh, 1, 0);

    // qkv = xmod1 @ qkv_w.T
    mma_gemm<false,0><<<dim3(27, 64), 256, MM_SMEM>>>(
        p_sh, qkv_w, nullptr, nullptr, nullptr, p_big,
        ROWS, 3 * Cc, 3 * Cc, Cc, Cc, Cc, 3 * Cc,
        1, 0, 0, 0, 0, 0, 0, 0);

    vk_kernel<<<dim3(Bb * HLA, 16), 256>>>(p_big, p_vk);
    la_out_kernel<<<ROWS, 256>>>(p_big, p_vk, p_sh);

    // x1 = x + g_a * (la @ aproj_w.T + b)
    mma_gemm<true,3><<<dim3(9, 64), 256, MM_SMEM>>>(
        p_sh, aproj_w, aproj_b, x, p_m + 2 * Cc, p_x1,
        ROWS, Cc, Cc, Cc, Cc, Cc, Cc,
        1, 0, 0, 0, 0, 0, 0, 6 * Cc);

    // q = x1 @ q_w.T + q_b
    mma_gemm<true,0><<<dim3(9, 64), 256, MM_SMEM>>>(
        p_x1, q_w, q_b, nullptr, nullptr, p_sh,
        ROWS, Cc, Cc, Cc, Cc, Cc, Cc,
        1, 0, 0, 0, 0, 0, 0, 0);

    // kv = y @ kv_w.T + kv_b
    mma_gemm<true,0><<<dim3(18, 5), 256, MM_SMEM>>>(
        y, kv_w, kv_b, nullptr, nullptr, p_kv,
        Bb * Mkv, 2 * Cc, 2 * Cc, Cc, Cc, Cc, 2 * Cc,
        1, 0, 0, 0, 0, 0, 0, 0);

    // v^T (padded K for the o-GEMM)
    vt_kernel<<<(int)(((long)Bb * HX * 72 * SLD + 255) / 256), 256>>>(p_kv, p_vt);

    // scores[z] = q_h @ k_h.T  (K=72 w/ zero tail; pad cols 300..319 -> 0)
    mma_gemm<false,0><<<dim3(3, 32, Bb * HX), 256, MM_SMEM>>>(
        p_sh, p_kv, nullptr, nullptr, nullptr, p_big,
        Nn, Mkv, SLD, 72, Cc, 2 * Cc, SLD,
        HX, (long)Nn * Cc, 72, (long)Mkv * 2 * Cc, 72,
        (long)HX * Nn * SLD, (long)Nn * SLD, 0);

    softmax_kernel<<<(Bb * HX * Nn) / 8, 256>>>(p_big, (long)Bb * HX * Nn);

    // o[z] = softmax @ v  (NT vs v^T, K=SLD incl. zero pad)
    mma_gemm<false,0><<<dim3(1, 32, Bb * HX), 256, MM_SMEM>>>(
        p_big, p_vt, nullptr, nullptr, nullptr, p_sh,
        Nn, 72, 72, SLD, SLD, SLD, Cc,
        HX, (long)HX * Nn * SLD, (long)Nn * SLD, (long)72 * SLD * HX, (long)72 * SLD,
        (long)Nn * Cc, 72, 0);

    // x2 = x1 + o @ cproj_w.T + b
    mma_gemm<true,2><<<dim3(9, 64), 256, MM_SMEM>>>(
        p_sh, cproj_w, cproj_b, p_x1, nullptr, p_x2,
        ROWS, Cc, Cc, Cc, Cc, Cc, Cc,
        1, 0, 0, 0, 0, 0, 0, 0);

    ln_mod_kernel<<<ROWS, 256>>>(p_x2, p_sh, 4, 3);

    // h = silu(xmod2 @ inv_w.T + b)
    mma_gemm<true,1><<<dim3(45, 64), 256, MM_SMEM>>>(
        p_sh, inv_w, inv_b, nullptr, nullptr, p_big,
        ROWS, 2 * HIDd, 2 * HIDd, Cc, Cc, Cc, 2 * HIDd,
        1, 0, 0, 0, 0, 0, 0, 0);

    // depthwise 3x3 + GLU (smem-tiled)
    dwglu_kernel<<<dim3(HIDd / 64, 64, Bb), 256>>>(p_big, dw_w, dw_b, p_glu);

    // out = x2 + g_m * (glu @ pw_w.T)
    mma_gemm<false,3><<<dim3(9, 64), 256, MM_SMEM>>>(
        p_glu, pw_w, nullptr, p_x2, p_m + 5 * Cc, out,
        ROWS, Cc, Cc, HIDd, HIDd, HIDd, Cc,
        1, 0, 0, 0, 0, 0, 0, 6 * Cc);
}

// round 6
// speedup vs baseline: 1.9329x; 1.0243x over previous
#include <cuda_runtime.h>
#include <cstdint>
#include <math.h>

// ---------------------------------------------------------------------------
// SanaBlock: LN+adaLN -> LiteLA -> cross-attn -> GLUMBConv, B=2,N=4096,C=1152
// R6: tf32 rounding hoisted out of GEMM hot loop (pre-rounded weights +
//     producer-side rounding); GEMM inner loop = pure LDS+MMA.
// ---------------------------------------------------------------------------
constexpr int Bb   = 2;
constexpr int Nn   = 4096;
constexpr int Cc   = 1152;
constexpr int Mkv  = 300;
constexpr int HIDd = 2880;
constexpr int HLA  = 36;
constexpr int HX   = 16;
constexpr int SLD  = 320;

__device__ float g_big[47185920];   // qkv -> scores(ld320) -> h
__device__ float g_sh [(size_t)Bb * Nn * Cc];
__device__ float g_x1 [(size_t)Bb * Nn * Cc];
__device__ float g_x2 [(size_t)Bb * Nn * Cc];
__device__ float g_glu[(size_t)Bb * Nn * HIDd];
__device__ float g_kvb[(size_t)Bb * Mkv * 2 * Cc];
__device__ float g_vt [(size_t)Bb * HX * 72 * SLD];
__device__ float g_vk [Bb * HLA * 33 * 32];
__device__ float g_mb [Bb * 6 * Cc];
__device__ float g_wts[20570112];   // tf32-rounded weight copies

// offsets into g_wts
constexpr size_t W_QKV = 0;
constexpr size_t W_APR = W_QKV + (size_t)3 * Cc * Cc;
constexpr size_t W_Q   = W_APR + (size_t)Cc * Cc;
constexpr size_t W_KV  = W_Q   + (size_t)Cc * Cc;
constexpr size_t W_CPR = W_KV  + (size_t)2 * Cc * Cc;
constexpr size_t W_INV = W_CPR + (size_t)Cc * Cc;
constexpr size_t W_PW  = W_INV + (size_t)2 * HIDd * Cc;

// ---------------------------------------------------------------------------
// helpers
// ---------------------------------------------------------------------------
__device__ __forceinline__ uint32_t smem_u32(const void* p){
    uint32_t a;
    asm("{ .reg .u64 t; cvta.to.shared.u64 t, %1; cvt.u32.u64 %0, t; }"
        : "=r"(a) : "l"(p));
    return a;
}
__device__ __forceinline__ void cp16(uint32_t dst, const void* src, int srcsz){
    asm volatile("cp.async.cg.shared.global [%0], [%1], 16, %2;"
        ::"r"(dst),"l"(src),"r"(srcsz):"memory");
}
#define CP_COMMIT() asm volatile("cp.async.commit_group;":::"memory")
#define CP_WAIT1()  asm volatile("cp.async.wait_group 1;":::"memory")

__device__ __forceinline__ uint32_t f2tf(float f){
    uint32_t u; asm("cvt.rna.tf32.f32 %0, %1;" : "=r"(u) : "f"(f)); return u;
}
__device__ __forceinline__ float tf32r(float f){ return __uint_as_float(f2tf(f)); }

__device__ __forceinline__ void mma8(float* d, const uint32_t* a, const uint32_t* b){
    asm volatile("mma.sync.aligned.m16n8k8.row.col.f32.tf32.tf32.f32 "
        "{%0,%1,%2,%3},{%4,%5,%6,%7},{%8,%9},{%0,%1,%2,%3};"
        : "+f"(d[0]),"+f"(d[1]),"+f"(d[2]),"+f"(d[3])
        : "r"(a[0]),"r"(a[1]),"r"(a[2]),"r"(a[3]),"r"(b[0]),"r"(b[1]));
}

// ---------------------------------------------------------------------------
// weight rounding: dst[i] = tf32(src[i])
// ---------------------------------------------------------------------------
__global__ void round_w_kernel(const float* __restrict__ src, float* __restrict__ dst, int n)
{
    int i = blockIdx.x * 256 + threadIdx.x;
    if (i < n) dst[i] = tf32r(src[i]);
}

// ---------------------------------------------------------------------------
// tf32 mma NT GEMM: O[M,N] = epi(A[M,K]*B[NloadB,K]^T + bias)
// CTA 128x128x32, 8 warps (4M x 2N), warp tile 32x64, 2-stage cp.async.
// B (and A unless CVTA) must be pre-rounded to tf32 format.
// EPI: 0 none, 1 silu, 2 +res, 3 +res+gate*v.  ROUT: round output to tf32.
// ---------------------------------------------------------------------------
constexpr int LDP     = 36;
constexpr int TILE_F  = 128 * LDP;
constexpr int STAGE_F = 2 * TILE_F;
constexpr int MM_SMEM = 2 * STAGE_F * 4;   // 73728 bytes

template<bool BIAS, int EPI, bool CVTA, bool ROUT>
__global__ __launch_bounds__(256)
void mma_gemm(const float* __restrict__ A, const float* __restrict__ Bw,
              const float* __restrict__ bias, const float* __restrict__ res,
              const float* __restrict__ gate, float* __restrict__ O,
              int Mrows, int NloadB, int Nstore, int K,
              int lda, int ldb, int ldo,
              int HB, long aBs, long aHs, long bBs, long bHs, long oBs, long oHs,
              int gateStride)
{
    extern __shared__ float smf[];
    uint32_t sbase = smem_u32(smf);
    int tid = threadIdx.x, wid = tid >> 5, lane = tid & 31;
    int warpM = wid >> 1, warpN = wid & 1;
    int m0 = blockIdx.y * 128, n0 = blockIdx.x * 128;

    if (gridDim.z > 1) {
        int z = blockIdx.z;
        int bI = z / HB, hI = z % HB;
        A  += bI * aBs + hI * aHs;
        Bw += bI * bBs + hI * bHs;
        O  += bI * oBs + hI * oHs;
    }

    const int T = (K + 31) >> 5;

    auto load_tile = [&](int t, int buf) {
        uint32_t base = sbase + (uint32_t)buf * STAGE_F * 4;
        int k0 = t << 5;
        #pragma unroll
        for (int i = 0; i < 4; i++) {
            int c = tid + (i << 8);
            int row = c >> 3, kc = c & 7;
            int gk = k0 + kc * 4;
            uint32_t dst = base + (uint32_t)(row * LDP + kc * 4) * 4;
            const float* ga = A + (size_t)(m0 + row) * lda + gk;
            cp16(dst, ga, ((m0 + row) < Mrows && gk < K) ? 16 : 0);
            uint32_t dstB = dst + TILE_F * 4;
            const float* gb = Bw + (size_t)(n0 + row) * ldb + gk;
            cp16(dstB, gb, ((n0 + row) < NloadB && gk < K) ? 16 : 0);
        }
    };

    float acc[2][8][4];
    #pragma unroll
    for (int mt = 0; mt < 2; mt++)
        #pragma unroll
        for (int nt = 0; nt < 8; nt++)
            #pragma unroll
            for (int q = 0; q < 4; q++) acc[mt][nt][q] = 0.f;

    load_tile(0, 0); CP_COMMIT();

    int rA = warpM * 32 + (lane >> 2);
    int rB = warpN * 64 + (lane >> 2);
    int kq = lane & 3;

    for (int t = 0; t < T; t++) {
        int buf = t & 1;
        if (t + 1 < T) load_tile(t + 1, buf ^ 1);
        CP_COMMIT();
        CP_WAIT1();
        __syncthreads();

        const float* sA = smf + buf * STAGE_F;
        const float* sB = sA + TILE_F;

        #pragma unroll
        for (int kk = 0; kk < 4; kk++) {
            int c0 = kk * 8 + kq;
            uint32_t af[2][4];
            #pragma unroll
            for (int mt = 0; mt < 2; mt++) {
                int r = rA + mt * 16;
                if (CVTA) {
                    af[mt][0] = f2tf(sA[r * LDP + c0]);
                    af[mt][1] = f2tf(sA[(r + 8) * LDP + c0]);
                    af[mt][2] = f2tf(sA[r * LDP + c0 + 4]);
                    af[mt][3] = f2tf(sA[(r + 8) * LDP + c0 + 4]);
                } else {
                    af[mt][0] = __float_as_uint(sA[r * LDP + c0]);
                    af[mt][1] = __float_as_uint(sA[(r + 8) * LDP + c0]);
                    af[mt][2] = __float_as_uint(sA[r * LDP + c0 + 4]);
                    af[mt][3] = __float_as_uint(sA[(r + 8) * LDP + c0 + 4]);
                }
            }
            uint32_t bf[8][2];
            #pragma unroll
            for (int nt = 0; nt < 8; nt++) {
                int r = rB + nt * 8;
                bf[nt][0] = __float_as_uint(sB[r * LDP + c0]);
                bf[nt][1] = __float_as_uint(sB[r * LDP + c0 + 4]);
            }
            #pragma unroll
            for (int mt = 0; mt < 2; mt++)
                #pragma unroll
                for (int nt = 0; nt < 8; nt++)
                    mma8(acc[mt][nt], af[mt], bf[nt]);
        }
        __syncthreads();
    }

    #pragma unroll
    for (int mt = 0; mt < 2; mt++) {
        #pragma unroll
        for (int half = 0; half < 2; half++) {
            int row = m0 + warpM * 32 + mt * 16 + (lane >> 2) + half * 8;
            if (row >= Mrows) continue;
            int bI = (row >= Nn) ? 1 : 0;
            #pragma unroll
            for (int nt = 0; nt < 8; nt++) {
                int col = n0 + warpN * 64 + nt * 8 + (lane & 3) * 2;
                if (col >= Nstore) continue;
                float v0 = acc[mt][nt][half * 2];
                float v1 = acc[mt][nt][half * 2 + 1];
                if (BIAS) { v0 += bias[col]; v1 += bias[col + 1]; }
                if (EPI == 1) {
                    v0 = v0 / (1.f + __expf(-v0));
                    v1 = v1 / (1.f + __expf(-v1));
                }
                if (EPI == 2) {
                    v0 += res[(size_t)row * ldo + col];
                    v1 += res[(size_t)row * ldo + col + 1];
                }
                if (EPI == 3) {
                    v0 = res[(size_t)row * ldo + col]     + gate[bI * gateStride + col]     * v0;
                    v1 = res[(size_t)row * ldo + col + 1] + gate[bI * gateStride + col + 1] * v1;
                }
                if (ROUT) { v0 = tf32r(v0); v1 = tf32r(v1); }
                *(float2*)&O[(size_t)row * ldo + col] = make_float2(v0, v1);
            }
        }
    }
}

// ---------------------------------------------------------------------------
// m = sst + t
// ---------------------------------------------------------------------------
__global__ void mod_kernel(const float* __restrict__ t, const float* __restrict__ sst)
{
    int i = blockIdx.x * 256 + threadIdx.x;
    if (i < Bb * 6 * Cc) g_mb[i] = sst[i % (6 * Cc)] + t[i];
}

// ---------------------------------------------------------------------------
// LayerNorm + adaLN modulate (output tf32-rounded; feeds GEMMs only)
// ---------------------------------------------------------------------------
__global__ __launch_bounds__(256)
void ln_mod_kernel(const float* __restrict__ in, float* __restrict__ out,
                   int scRow, int shRow)
{
    int row = blockIdx.x;
    int b   = row / Nn;
    const float* xr = in + (size_t)row * Cc;

    float s = 0.f, s2 = 0.f;
    for (int c = threadIdx.x; c < Cc; c += blockDim.x) {
        float v = xr[c]; s += v; s2 += v * v;
    }
    __shared__ float sh1[8], sh2[8];
    int lane = threadIdx.x & 31, wid = threadIdx.x >> 5;
    #pragma unroll
    for (int o = 16; o > 0; o >>= 1) {
        s  += __shfl_down_sync(0xffffffffu, s,  o);
        s2 += __shfl_down_sync(0xffffffffu, s2, o);
    }
    if (lane == 0) { sh1[wid] = s; sh2[wid] = s2; }
    __syncthreads();
    if (wid == 0) {
        s  = (lane < 8) ? sh1[lane] : 0.f;
        s2 = (lane < 8) ? sh2[lane] : 0.f;
        #pragma unroll
        for (int o = 4; o > 0; o >>= 1) {
            s  += __shfl_down_sync(0xffffffffu, s,  o);
            s2 += __shfl_down_sync(0xffffffffu, s2, o);
        }
        if (lane == 0) { sh1[0] = s; sh2[0] = s2; }
    }
    __syncthreads();
    float mu   = sh1[0] * (1.f / Cc);
    float var  = sh2[0] * (1.f / Cc) - mu * mu;
    float rstd = rsqrtf(var + 1e-6f);
    const float* mbp = g_mb + (size_t)b * 6 * Cc;
    for (int c = threadIdx.x; c < Cc; c += blockDim.x) {
        float sc = mbp[scRow * Cc + c];
        float sv = mbp[shRow * Cc + c];
        out[(size_t)row * Cc + c] = tf32r((xr[c] - mu) * rstd * (1.f + sc) + sv);
    }
}

// ---------------------------------------------------------------------------
// LiteLA vk accumulation + epilogue
// ---------------------------------------------------------------------------
__global__ void zero_vk_kernel()
{
    int i = blockIdx.x * 256 + threadIdx.x;
    if (i < Bb * HLA * 33 * 32) g_vk[i] = 0.f;
}

__global__ __launch_bounds__(256)
void vk_kernel(const float* __restrict__ qkv, float* __restrict__ vkout)
{
    int bh = blockIdx.x;
    int b  = bh / HLA, h = bh % HLA;
    int split = blockIdx.y;
    __shared__ float ks[32][33];
    __shared__ float vs[32][33];
    float acc[5] = {0.f, 0.f, 0.f, 0.f, 0.f};
    int tid = threadIdx.x;
    const size_t base = (size_t)b * Nn * 3 * Cc;
    int nStart = split * (Nn / 16);
    for (int n0 = nStart; n0 < nStart + Nn / 16; n0 += 32) {
        for (int li = tid; li < 1024; li += 256) {
            int nn = li >> 5, dc = li & 31;
            size_t off = base + (size_t)(n0 + nn) * 3 * Cc + h * 32 + dc;
            ks[nn][dc] = fmaxf(qkv[off + Cc], 0.f);
            vs[nn][dc] = qkv[off + 2 * Cc];
        }
        __syncthreads();
        #pragma unroll
        for (int u = 0; u < 5; u++) {
            int idx = tid + 256 * u;
            if (idx < 1056) {
                int e = idx >> 5, dc = idx & 31;
                float a = acc[u];
                if (e == 32) {
                    #pragma unroll
                    for (int nn = 0; nn < 32; nn++) a += ks[nn][dc];
                } else {
                    #pragma unroll
                    for (int nn = 0; nn < 32; nn++) a += vs[nn][e] * ks[nn][dc];
                }
                acc[u] = a;
            }
        }
        __syncthreads();
    }
    #pragma unroll
    for (int u = 0; u < 5; u++) {
        int idx = tid + 256 * u;
        if (idx < 1056) {
            int e = idx >> 5, dc = idx & 31;
            atomicAdd(&vkout[((size_t)bh * 33 + e) * 32 + dc], acc[u]);
        }
    }
}

// la_out output tf32-rounded (feeds aproj GEMM only)
__global__ __launch_bounds__(256)
void la_out_kernel(const float* __restrict__ qkv, const float* __restrict__ vk,
                   float* __restrict__ out)
{
    int row = blockIdx.x;
    int b   = row / Nn;
    __shared__ float q[Cc];
    __shared__ float den[HLA];
    const float* qr = qkv + (size_t)row * 3 * Cc;
    for (int c = threadIdx.x; c < Cc; c += blockDim.x) q[c] = fmaxf(qr[c], 0.f);
    __syncthreads();
    if (threadIdx.x < HLA) {
        int h = threadIdx.x;
        const float* vkh = vk + ((size_t)(b * HLA + h) * 33 + 32) * 32;
        float s = 0.f;
        #pragma unroll
        for (int d = 0; d < 32; d++) s += vkh[d] * q[h * 32 + d];
        den[h] = s + 1e-8f;
    }
    __syncthreads();
    for (int c = threadIdx.x; c < Cc; c += blockDim.x) {
        int h = c >> 5, dd = c & 31;
        const float* vkr = vk + ((size_t)(b * HLA + h) * 33 + dd) * 32;
        const float* qh  = q + h * 32;
        float s = 0.f;
        #pragma unroll
        for (int d = 0; d < 32; d++) s += vkr[d] * qh[d];
        out[(size_t)row * Cc + c] = tf32r(s / den[h]);
    }
}

// ---------------------------------------------------------------------------
// v^T materialization (kv already tf32-rounded)
// ---------------------------------------------------------------------------
__global__ void vt_kernel(const float* __restrict__ kv, float* __restrict__ vt)
{
    long idx = (long)blockIdx.x * 256 + threadIdx.x;
    if (idx >= (long)Bb * HX * 72 * SLD) return;
    int  m = (int)(idx % SLD);
    long r = idx / SLD;
    int  d = (int)(r % 72);
    int  z = (int)(r / 72);
    int  b = z / HX, h = z % HX;
    float v = 0.f;
    if (m < Mkv) v = kv[((size_t)b * Mkv + m) * 2 * Cc + Cc + h * 72 + d];
    vt[idx] = v;
}

// ---------------------------------------------------------------------------
// Cross-attn softmax (output tf32-rounded; feeds o-GEMM only)
// ---------------------------------------------------------------------------
__global__ __launch_bounds__(256)
void softmax_kernel(float* __restrict__ s, long rows)
{
    long gw  = ((long)blockIdx.x * blockDim.x + threadIdx.x) >> 5;
    int lane = threadIdx.x & 31;
    if (gw >= rows) return;
    float* r = s + gw * SLD;
    const float scale = 0.11785113019775793f;
    float v[10];
    float mx = -1e30f;
    #pragma unroll
    for (int i = 0; i < 10; i++) {
        int m = lane + 32 * i;
        v[i] = (m < Mkv) ? r[m] * scale : -1e30f;
        mx = fmaxf(mx, v[i]);
    }
    #pragma unroll
    for (int o = 16; o > 0; o >>= 1) mx = fmaxf(mx, __shfl_xor_sync(0xffffffffu, mx, o));
    float sum = 0.f;
    #pragma unroll
    for (int i = 0; i < 10; i++) { v[i] = __expf(v[i] - mx); sum += v[i]; }
    #pragma unroll
    for (int o = 16; o > 0; o >>= 1) sum += __shfl_xor_sync(0xffffffffu, sum, o);
    float inv = 1.f / sum;
    #pragma unroll
    for (int i = 0; i < 10; i++) {
        int m = lane + 32 * i;
        if (m < Mkv) r[m] = tf32r(v[i] * inv);
    }
}

// ---------------------------------------------------------------------------
// depthwise 3x3 + bias + GLU, smem-tiled (output tf32-rounded; feeds pw GEMM)
// ---------------------------------------------------------------------------
__global__ __launch_bounds__(256)
void dwglu_kernel(const float* __restrict__ h, const float* __restrict__ dww,
                  const float* __restrict__ dwb, float* __restrict__ out)
{
    __shared__ float sa[100][64];
    __shared__ float sg[100][64];
    int tid = threadIdx.x;
    int c0  = blockIdx.x * 64;
    int y0  = (blockIdx.y >> 3) * 8, x0 = (blockIdx.y & 7) * 8;
    int b   = blockIdx.z;

    int ch = tid & 63;
    float wA[9], wG[9];
    #pragma unroll
    for (int tp = 0; tp < 9; tp++) {
        wA[tp] = dww[(size_t)(c0 + ch) * 9 + tp];
        wG[tp] = dww[(size_t)(c0 + ch + HIDd) * 9 + tp];
    }
    float bA = dwb[c0 + ch], bG = dwb[c0 + ch + HIDd];

    for (int li = tid; li < 1600; li += 256) {
        int pos = li >> 4, q = li & 15;
        int py = pos / 10, px = pos % 10;
        int yy = y0 + py - 1, xx = x0 + px - 1;
        float4 va = make_float4(0.f, 0.f, 0.f, 0.f), vg = va;
        if (yy >= 0 && yy < 64 && xx >= 0 && xx < 64) {
            const float* src = h + ((size_t)b * Nn + yy * 64 + xx) * (2 * HIDd) + c0 + q * 4;
            va = *(const float4*)src;
            vg = *(const float4*)(src + HIDd);
        }
        *(float4*)&sa[pos][q * 4] = va;
        *(float4*)&sg[pos][q * 4] = vg;
    }
    __syncthreads();

    #pragma unroll
    for (int i = 0; i < 16; i++) {
        int pos = (tid >> 6) + i * 4;
        int py = pos >> 3, px = pos & 7;
        int s0 = (py + 1) * 10 + (px + 1);
        float accA = bA, accG = bG;
        #pragma unroll
        for (int dy = -1; dy <= 1; dy++)
            #pragma unroll
            for (int dx = -1; dx <= 1; dx++) {
                int s = s0 + dy * 10 + dx;
                int tp = (dy + 1) * 3 + (dx + 1);
                accA = fmaf(sa[s][ch], wA[tp], accA);
                accG = fmaf(sg[s][ch], wG[tp], accG);
            }
        int n = (y0 + py) * 64 + (x0 + px);
        out[((size_t)b * Nn + n) * HIDd + c0 + ch] =
            tf32r(accA * (accG / (1.f + __expf(-accG))));
    }
}

// ---------------------------------------------------------------------------
extern "C" void kernel_launch(void* const* d_in, const int* /*in_sizes*/, int /*n_in*/,
                              void* d_out, int /*out_size*/)
{
    const float* x       = (const float*)d_in[0];
    const float* y       = (const float*)d_in[1];
    const float* t       = (const float*)d_in[2];
    const float* sst     = (const float*)d_in[3];
    const float* qkv_w   = (const float*)d_in[4];
    const float* aproj_w = (const float*)d_in[5];
    const float* aproj_b = (const float*)d_in[6];
    const float* q_w     = (const float*)d_in[7];
    const float* q_b     = (const float*)d_in[8];
    const float* kv_w    = (const float*)d_in[9];
    const float* kv_b    = (const float*)d_in[10];
    const float* cproj_w = (const float*)d_in[11];
    const float* cproj_b = (const float*)d_in[12];
    const float* inv_w   = (const float*)d_in[13];
    const float* inv_b   = (const float*)d_in[14];
    const float* dw_w    = (const float*)d_in[15];
    const float* dw_b    = (const float*)d_in[16];
    const float* pw_w    = (const float*)d_in[17];
    float* out = (float*)d_out;

    float *p_big, *p_sh, *p_x1, *p_x2, *p_glu, *p_kv, *p_vt, *p_vk, *p_m, *p_w;
    cudaGetSymbolAddress((void**)&p_big, g_big);
    cudaGetSymbolAddress((void**)&p_sh,  g_sh);
    cudaGetSymbolAddress((void**)&p_x1,  g_x1);
    cudaGetSymbolAddress((void**)&p_x2,  g_x2);
    cudaGetSymbolAddress((void**)&p_glu, g_glu);
    cudaGetSymbolAddress((void**)&p_kv,  g_kvb);
    cudaGetSymbolAddress((void**)&p_vt,  g_vt);
    cudaGetSymbolAddress((void**)&p_vk,  g_vk);
    cudaGetSymbolAddress((void**)&p_m,   g_mb);
    cudaGetSymbolAddress((void**)&p_w,   g_wts);

    cudaFuncSetAttribute((const void*)mma_gemm<false,0,false,false>, cudaFuncAttributeMaxDynamicSharedMemorySize, MM_SMEM);
    cudaFuncSetAttribute((const void*)mma_gemm<false,0,false,true >, cudaFuncAttributeMaxDynamicSharedMemorySize, MM_SMEM);
    cudaFuncSetAttribute((const void*)mma_gemm<true, 3,false,false>, cudaFuncAttributeMaxDynamicSharedMemorySize, MM_SMEM);
    cudaFuncSetAttribute((const void*)mma_gemm<true, 0,true, true >, cudaFuncAttributeMaxDynamicSharedMemorySize, MM_SMEM);
    cudaFuncSetAttribute((const void*)mma_gemm<true, 2,false,false>, cudaFuncAttributeMaxDynamicSharedMemorySize, MM_SMEM);
    cudaFuncSetAttribute((const void*)mma_gemm<true, 1,false,false>, cudaFuncAttributeMaxDynamicSharedMemorySize, MM_SMEM);
    cudaFuncSetAttribute((const void*)mma_gemm<false,3,false,false>, cudaFuncAttributeMaxDynamicSharedMemorySize, MM_SMEM);

    const int ROWS = Bb * Nn;  // 8192

    // zero_vk first: keeps the ncu capture slot on the qkv mma_gemm
    zero_vk_kernel<<<(Bb * HLA * 33 * 32 + 255) / 256, 256>>>();
    mod_kernel<<<(Bb * 6 * Cc + 255) / 256, 256>>>(t, sst);

    // tf32-round weight copies
    {
        int n;
        n = 3 * Cc * Cc;     round_w_kernel<<<(n + 255) / 256, 256>>>(qkv_w,   p_w + W_QKV, n);
        n = Cc * Cc;         round_w_kernel<<<(n + 255) / 256, 256>>>(aproj_w, p_w + W_APR, n);
        n = Cc * Cc;         round_w_kernel<<<(n + 255) / 256, 256>>>(q_w,     p_w + W_Q,   n);
        n = 2 * Cc * Cc;     round_w_kernel<<<(n + 255) / 256, 256>>>(kv_w,    p_w + W_KV,  n);
        n = Cc * Cc;         round_w_kernel<<<(n + 255) / 256, 256>>>(cproj_w, p_w + W_CPR, n);
        n = 2 * HIDd * Cc;   round_w_kernel<<<(n + 255) / 256, 256>>>(inv_w,   p_w + W_INV, n);
        n = Cc * HIDd;       round_w_kernel<<<(n + 255) / 256, 256>>>(pw_w,    p_w + W_PW,  n);
    }

    ln_mod_kernel<<<ROWS, 256>>>(x, p_sh, 1, 0);

    // qkv = xmod1 @ qkv_w.T
    mma_gemm<false,0,false,false><<<dim3(27, 64), 256, MM_SMEM>>>(
        p_sh, p_w + W_QKV, nullptr, nullptr, nullptr, p_big,
        ROWS, 3 * Cc, 3 * Cc, Cc, Cc, Cc, 3 * Cc,
        1, 0, 0, 0, 0, 0, 0, 0);

    vk_kernel<<<dim3(Bb * HLA, 16), 256>>>(p_big, p_vk);
    la_out_kernel<<<ROWS, 256>>>(p_big, p_vk, p_sh);

    // x1 = x + g_a * (la @ aproj_w.T + b)
    mma_gemm<true,3,false,false><<<dim3(9, 64), 256, MM_SMEM>>>(
        p_sh, p_w + W_APR, aproj_b, x, p_m + 2 * Cc, p_x1,
        ROWS, Cc, Cc, Cc, Cc, Cc, Cc,
        1, 0, 0, 0, 0, 0, 0, 6 * Cc);

    // q = x1 @ q_w.T + q_b   (A unrounded -> CVTA; out rounded)
    mma_gemm<true,0,true,true><<<dim3(9, 64), 256, MM_SMEM>>>(
        p_x1, p_w + W_Q, q_b, nullptr, nullptr, p_sh,
        ROWS, Cc, Cc, Cc, Cc, Cc, Cc,
        1, 0, 0, 0, 0, 0, 0, 0);

    // kv = y @ kv_w.T + kv_b (A=y unrounded -> CVTA; out rounded)
    mma_gemm<true,0,true,true><<<dim3(18, 5), 256, MM_SMEM>>>(
        y, p_w + W_KV, kv_b, nullptr, nullptr, p_kv,
        Bb * Mkv, 2 * Cc, 2 * Cc, Cc, Cc, Cc, 2 * Cc,
        1, 0, 0, 0, 0, 0, 0, 0);

    vt_kernel<<<(int)(((long)Bb * HX * 72 * SLD + 255) / 256), 256>>>(p_kv, p_vt);

    // scores[z] = q_h @ k_h.T
    mma_gemm<false,0,false,false><<<dim3(3, 32, Bb * HX), 256, MM_SMEM>>>(
        p_sh, p_kv, nullptr, nullptr, nullptr, p_big,
        Nn, Mkv, SLD, 72, Cc, 2 * Cc, SLD,
        HX, (long)Nn * Cc, 72, (long)Mkv * 2 * Cc, 72,
        (long)HX * Nn * SLD, (long)Nn * SLD, 0);

    softmax_kernel<<<(Bb * HX * Nn) / 8, 256>>>(p_big, (long)Bb * HX * Nn);

    // o[z] = softmax @ v  (out rounded -> feeds cproj)
    mma_gemm<false,0,false,true><<<dim3(1, 32, Bb * HX), 256, MM_SMEM>>>(
        p_big, p_vt, nullptr, nullptr, nullptr, p_sh,
        Nn, 72, 72, SLD, SLD, SLD, Cc,
        HX, (long)HX * Nn * SLD, (long)Nn * SLD, (long)72 * SLD * HX, (long)72 * SLD,
        (long)Nn * Cc, 72, 0);

    // x2 = x1 + o @ cproj_w.T + b
    mma_gemm<true,2,false,false><<<dim3(9, 64), 256, MM_SMEM>>>(
        p_sh, p_w + W_CPR, cproj_b, p_x1, nullptr, p_x2,
        ROWS, Cc, Cc, Cc, Cc, Cc, Cc,
        1, 0, 0, 0, 0, 0, 0, 0);

    ln_mod_kernel<<<ROWS, 256>>>(p_x2, p_sh, 4, 3);

    // h = silu(xmod2 @ inv_w.T + b)
    mma_gemm<true,1,false,false><<<dim3(45, 64), 256, MM_SMEM>>>(
        p_sh, p_w + W_INV, inv_b, nullptr, nullptr, p_big,
        ROWS, 2 * HIDd, 2 * HIDd, Cc, Cc, Cc, 2 * HIDd,
        1, 0, 0, 0, 0, 0, 0, 0);

    dwglu_kernel<<<dim3(HIDd / 64, 64, Bb), 256>>>(p_big, dw_w, dw_b, p_glu);

    // out = x2 + g_m * (glu @ pw_w.T)
    mma_gemm<false,3,false,false><<<dim3(9, 64), 256, MM_SMEM>>>(
        p_glu, p_w + W_PW, nullptr, p_x2, p_m + 5 * Cc, out,
        ROWS, Cc, Cc, HIDd, HIDd, HIDd, Cc,
        1, 0, 0, 0, 0, 0, 0, 6 * Cc);
}

// round 7
// speedup vs baseline: 2.4642x; 1.2748x over previous
#include <cuda_runtime.h>
#include <cuda_fp16.h>
#include <cstdint>
#include <math.h>

// ---------------------------------------------------------------------------
// SanaBlock: LN+adaLN -> LiteLA -> cross-attn -> GLUMBConv, B=2,N=4096,C=1152
// R7: dense GEMMs on fp16 mma.m16n8k16 (same 11-bit significand as tf32,
//     half the instructions + half the smem/gmem traffic). Scores stay fp32.
// ---------------------------------------------------------------------------
constexpr int Bb   = 2;
constexpr int Nn   = 4096;
constexpr int Cc   = 1152;
constexpr int Mkv  = 300;
constexpr int HIDd = 2880;
constexpr int HLA  = 36;
constexpr int HX   = 16;
constexpr int SLD  = 320;

// float scratch: qkv(half view) -> scores(float) -> h(half view)
__device__ __align__(256) float  g_big [47185920];
__device__ __align__(256) __half g_shh [(size_t)Bb * Nn * Cc];      // xmod/la/q/o/xmod2
__device__ __align__(256) float  g_x1  [(size_t)Bb * Nn * Cc];
__device__ __align__(256) __half g_x1h [(size_t)Bb * Nn * Cc];
__device__ __align__(256) float  g_x2  [(size_t)Bb * Nn * Cc];
__device__ __align__(256) __half g_glu [(size_t)Bb * Nn * HIDd];
__device__ __align__(256) __half g_kvb [(size_t)Bb * Mkv * 2 * Cc];
__device__ __align__(256) __half g_vt  [(size_t)Bb * HX * 72 * SLD];
__device__ __align__(256) __half g_prb [(size_t)Bb * HX * Nn * SLD];
__device__ __align__(256) __half g_yh  [(size_t)Bb * Mkv * Cc];
__device__ __align__(256) __half g_wts [20570112];
__device__ float g_vk [Bb * HLA * 33 * 32];
__device__ float g_mb [Bb * 6 * Cc];

// weight offsets (halves)
constexpr size_t W_QKV = 0;
constexpr size_t W_APR = W_QKV + (size_t)3 * Cc * Cc;
constexpr size_t W_Q   = W_APR + (size_t)Cc * Cc;
constexpr size_t W_KV  = W_Q   + (size_t)Cc * Cc;
constexpr size_t W_CPR = W_KV  + (size_t)2 * Cc * Cc;
constexpr size_t W_INV = W_CPR + (size_t)Cc * Cc;
constexpr size_t W_PW  = W_INV + (size_t)2 * HIDd * Cc;

// ---------------------------------------------------------------------------
// helpers
// ---------------------------------------------------------------------------
__device__ __forceinline__ uint32_t smem_u32(const void* p){
    uint32_t a;
    asm("{ .reg .u64 t; cvta.to.shared.u64 t, %1; cvt.u32.u64 %0, t; }"
        : "=r"(a) : "l"(p));
    return a;
}
__device__ __forceinline__ void cp16(uint32_t dst, const void* src, int srcsz){
    asm volatile("cp.async.cg.shared.global [%0], [%1], 16, %2;"
        ::"r"(dst),"l"(src),"r"(srcsz):"memory");
}
#define CP_COMMIT() asm volatile("cp.async.commit_group;":::"memory")
#define CP_WAIT1()  asm volatile("cp.async.wait_group 1;":::"memory")

__device__ __forceinline__ void mma16(float* d, const uint32_t* a, const uint32_t* b){
    asm volatile("mma.sync.aligned.m16n8k16.row.col.f32.f16.f16.f32 "
        "{%0,%1,%2,%3},{%4,%5,%6,%7},{%8,%9},{%0,%1,%2,%3};"
        : "+f"(d[0]),"+f"(d[1]),"+f"(d[2]),"+f"(d[3])
        : "r"(a[0]),"r"(a[1]),"r"(a[2]),"r"(a[3]),"r"(b[0]),"r"(b[1]));
}
__device__ __forceinline__ uint32_t ld32h(const __half* p){
    return *(const uint32_t*)p;
}

// ---------------------------------------------------------------------------
// fp16 mma NT GEMM: O[M,N] = epi(A[M,K]*B[NloadB,K]^T + bias), fp32 accum.
// CTA 128x128x32, 8 warps (4M x 2N), warp tile 32x64, 2-stage cp.async.
// EPI: 0 none, 1 silu, 2 +res, 3 +res+gate*v.  WF: write float Of. WH: half Oh.
// ---------------------------------------------------------------------------
constexpr int LDPH    = 40;               // halves per smem row (80B, conflict-free)
constexpr int TILE_H  = 128 * LDPH;       // halves per tile
constexpr int STAGE_H = 2 * TILE_H;
constexpr int MM_SMEM = 2 * STAGE_H * 2;  // 40960 bytes (<48K, no attribute needed)

template<bool BIAS, int EPI, bool WF, bool WH>
__global__ __launch_bounds__(256)
void mma_gemm(const __half* A, const __half* Bw, const float* bias,
              const float* res, const float* gate,
              float* Of, __half* Oh,
              int Mrows, int NloadB, int Nstore, int K,
              int lda, int ldb, int ldo,
              int HB, long aBs, long aHs, long bBs, long bHs, long oBs, long oHs,
              int gateStride)
{
    extern __shared__ __half smh[];
    uint32_t sbase = smem_u32(smh);
    int tid = threadIdx.x, wid = tid >> 5, lane = tid & 31;
    int warpM = wid >> 1, warpN = wid & 1;
    int m0 = blockIdx.y * 128, n0 = blockIdx.x * 128;

    if (gridDim.z > 1) {
        int z = blockIdx.z;
        int bI = z / HB, hI = z % HB;
        A  += bI * aBs + hI * aHs;
        Bw += bI * bBs + hI * bHs;
        if (WF) Of += bI * oBs + hI * oHs;
        if (WH) Oh += bI * oBs + hI * oHs;
    }

    const int T = (K + 31) >> 5;

    auto load_tile = [&](int t, int buf) {
        uint32_t base = sbase + (uint32_t)buf * STAGE_H * 2;
        int k0 = t << 5;
        #pragma unroll
        for (int i = 0; i < 2; i++) {
            int c = tid + (i << 8);             // 0..511
            int row = c >> 2, ch = c & 3;
            int gk = k0 + ch * 8;
            uint32_t dst = base + (uint32_t)(row * LDPH * 2 + ch * 16);
            const __half* ga = A + (size_t)(m0 + row) * lda + gk;
            cp16(dst, ga, ((m0 + row) < Mrows && gk < K) ? 16 : 0);
            uint32_t dstB = dst + TILE_H * 2;
            const __half* gb = Bw + (size_t)(n0 + row) * ldb + gk;
            cp16(dstB, gb, ((n0 + row) < NloadB && gk < K) ? 16 : 0);
        }
    };

    float acc[2][8][4];
    #pragma unroll
    for (int mt = 0; mt < 2; mt++)
        #pragma unroll
        for (int nt = 0; nt < 8; nt++)
            #pragma unroll
            for (int q = 0; q < 4; q++) acc[mt][nt][q] = 0.f;

    load_tile(0, 0); CP_COMMIT();

    int rA = warpM * 32 + (lane >> 2);
    int rB = warpN * 64 + (lane >> 2);
    int kq = lane & 3;

    for (int t = 0; t < T; t++) {
        int buf = t & 1;
        if (t + 1 < T) load_tile(t + 1, buf ^ 1);
        CP_COMMIT();
        CP_WAIT1();
        __syncthreads();

        const __half* sA = smh + buf * STAGE_H;
        const __half* sB = sA + TILE_H;

        #pragma unroll
        for (int kk = 0; kk < 2; kk++) {
            int c0 = kk * 16 + kq * 2;
            uint32_t af[2][4];
            #pragma unroll
            for (int mt = 0; mt < 2; mt++) {
                int r = rA + mt * 16;
                af[mt][0] = ld32h(&sA[r * LDPH + c0]);
                af[mt][1] = ld32h(&sA[(r + 8) * LDPH + c0]);
                af[mt][2] = ld32h(&sA[r * LDPH + c0 + 8]);
                af[mt][3] = ld32h(&sA[(r + 8) * LDPH + c0 + 8]);
            }
            uint32_t bf[8][2];
            #pragma unroll
            for (int nt = 0; nt < 8; nt++) {
                int r = rB + nt * 8;
                bf[nt][0] = ld32h(&sB[r * LDPH + c0]);
                bf[nt][1] = ld32h(&sB[r * LDPH + c0 + 8]);
            }
            #pragma unroll
            for (int mt = 0; mt < 2; mt++)
                #pragma unroll
                for (int nt = 0; nt < 8; nt++)
                    mma16(acc[mt][nt], af[mt], bf[nt]);
        }
        __syncthreads();
    }

    #pragma unroll
    for (int mt = 0; mt < 2; mt++) {
        #pragma unroll
        for (int half_ = 0; half_ < 2; half_++) {
            int row = m0 + warpM * 32 + mt * 16 + (lane >> 2) + half_ * 8;
            if (row >= Mrows) continue;
            int bI = (row >= Nn) ? 1 : 0;
            #pragma unroll
            for (int nt = 0; nt < 8; nt++) {
                int col = n0 + warpN * 64 + nt * 8 + (lane & 3) * 2;
                if (col >= Nstore) continue;
                float v0 = acc[mt][nt][half_ * 2];
                float v1 = acc[mt][nt][half_ * 2 + 1];
                if (BIAS) { v0 += bias[col]; v1 += bias[col + 1]; }
                if (EPI == 1) {
                    v0 = v0 / (1.f + __expf(-v0));
                    v1 = v1 / (1.f + __expf(-v1));
                }
                if (EPI == 2) {
                    v0 += res[(size_t)row * ldo + col];
                    v1 += res[(size_t)row * ldo + col + 1];
                }
                if (EPI == 3) {
                    v0 = res[(size_t)row * ldo + col]     + gate[bI * gateStride + col]     * v0;
                    v1 = res[(size_t)row * ldo + col + 1] + gate[bI * gateStride + col + 1] * v1;
                }
                if (WF) *(float2*)&Of[(size_t)row * ldo + col] = make_float2(v0, v1);
                if (WH) *(__half2*)&Oh[(size_t)row * ldo + col] = __floats2half2_rn(v0, v1);
            }
        }
    }
}

// ---------------------------------------------------------------------------
// m = sst + t
// ---------------------------------------------------------------------------
__global__ void mod_kernel(const float* __restrict__ t, const float* __restrict__ sst)
{
    int i = blockIdx.x * 256 + threadIdx.x;
    if (i < Bb * 6 * Cc) g_mb[i] = sst[i % (6 * Cc)] + t[i];
}

// ---------------------------------------------------------------------------
// all weight (and y) fp16 conversion in ONE launch
// ---------------------------------------------------------------------------
__global__ void round_all_kernel(const float* qkv_w, const float* aproj_w,
                                 const float* q_w, const float* kv_w,
                                 const float* cproj_w, const float* inv_w,
                                 const float* pw_w, const float* y)
{
    long i = (long)blockIdx.x * 256 + threadIdx.x;
    long n;
    n = (long)3 * Cc * Cc;   if (i < n) { g_wts[W_QKV + i] = __float2half_rn(qkv_w[i]);   return; } i -= n;
    n = (long)Cc * Cc;       if (i < n) { g_wts[W_APR + i] = __float2half_rn(aproj_w[i]); return; } i -= n;
    n = (long)Cc * Cc;       if (i < n) { g_wts[W_Q   + i] = __float2half_rn(q_w[i]);     return; } i -= n;
    n = (long)2 * Cc * Cc;   if (i < n) { g_wts[W_KV  + i] = __float2half_rn(kv_w[i]);    return; } i -= n;
    n = (long)Cc * Cc;       if (i < n) { g_wts[W_CPR + i] = __float2half_rn(cproj_w[i]); return; } i -= n;
    n = (long)2 * HIDd * Cc; if (i < n) { g_wts[W_INV + i] = __float2half_rn(inv_w[i]);   return; } i -= n;
    n = (long)Cc * HIDd;     if (i < n) { g_wts[W_PW  + i] = __float2half_rn(pw_w[i]);    return; } i -= n;
    n = (long)Bb * Mkv * Cc; if (i < n) { g_yh[i] = __float2half_rn(y[i]); }
}

// ---------------------------------------------------------------------------
// LayerNorm + adaLN modulate (writes half)
// ---------------------------------------------------------------------------
__global__ __launch_bounds__(256)
void ln_mod_kernel(const float* __restrict__ in, __half* __restrict__ out,
                   int scRow, int shRow)
{
    int row = blockIdx.x;
    int b   = row / Nn;
    const float* xr = in + (size_t)row * Cc;

    float s = 0.f, s2 = 0.f;
    for (int c = threadIdx.x; c < Cc; c += blockDim.x) {
        float v = xr[c]; s += v; s2 += v * v;
    }
    __shared__ float sh1[8], sh2[8];
    int lane = threadIdx.x & 31, wid = threadIdx.x >> 5;
    #pragma unroll
    for (int o = 16; o > 0; o >>= 1) {
        s  += __shfl_down_sync(0xffffffffu, s,  o);
        s2 += __shfl_down_sync(0xffffffffu, s2, o);
    }
    if (lane == 0) { sh1[wid] = s; sh2[wid] = s2; }
    __syncthreads();
    if (wid == 0) {
        s  = (lane < 8) ? sh1[lane] : 0.f;
        s2 = (lane < 8) ? sh2[lane] : 0.f;
        #pragma unroll
        for (int o = 4; o > 0; o >>= 1) {
            s  += __shfl_down_sync(0xffffffffu, s,  o);
            s2 += __shfl_down_sync(0xffffffffu, s2, o);
        }
        if (lane == 0) { sh1[0] = s; sh2[0] = s2; }
    }
    __syncthreads();
    float mu   = sh1[0] * (1.f / Cc);
    float var  = sh2[0] * (1.f / Cc) - mu * mu;
    float rstd = rsqrtf(var + 1e-6f);
    const float* mbp = g_mb + (size_t)b * 6 * Cc;
    for (int c = threadIdx.x; c < Cc; c += blockDim.x) {
        float sc = mbp[scRow * Cc + c];
        float sv = mbp[shRow * Cc + c];
        out[(size_t)row * Cc + c] =
            __float2half_rn((xr[c] - mu) * rstd * (1.f + sc) + sv);
    }
}

// ---------------------------------------------------------------------------
// LiteLA vk accumulation (reads half qkv) + epilogue
// ---------------------------------------------------------------------------
__global__ void zero_vk_kernel()
{
    int i = blockIdx.x * 256 + threadIdx.x;
    if (i < Bb * HLA * 33 * 32) g_vk[i] = 0.f;
}

__global__ __launch_bounds__(256)
void vk_kernel(const __half* __restrict__ qkv, float* __restrict__ vkout)
{
    int bh = blockIdx.x;
    int b  = bh / HLA, h = bh % HLA;
    int split = blockIdx.y;
    __shared__ float ks[32][33];
    __shared__ float vs[32][33];
    float acc[5] = {0.f, 0.f, 0.f, 0.f, 0.f};
    int tid = threadIdx.x;
    const size_t base = (size_t)b * Nn * 3 * Cc;
    int nStart = split * (Nn / 16);
    for (int n0 = nStart; n0 < nStart + Nn / 16; n0 += 32) {
        for (int li = tid; li < 1024; li += 256) {
            int nn = li >> 5, dc = li & 31;
            size_t off = base + (size_t)(n0 + nn) * 3 * Cc + h * 32 + dc;
            ks[nn][dc] = fmaxf(__half2float(qkv[off + Cc]), 0.f);
            vs[nn][dc] = __half2float(qkv[off + 2 * Cc]);
        }
        __syncthreads();
        #pragma unroll
        for (int u = 0; u < 5; u++) {
            int idx = tid + 256 * u;
            if (idx < 1056) {
                int e = idx >> 5, dc = idx & 31;
                float a = acc[u];
                if (e == 32) {
                    #pragma unroll
                    for (int nn = 0; nn < 32; nn++) a += ks[nn][dc];
                } else {
                    #pragma unroll
                    for (int nn = 0; nn < 32; nn++) a += vs[nn][e] * ks[nn][dc];
                }
                acc[u] = a;
            }
        }
        __syncthreads();
    }
    #pragma unroll
    for (int u = 0; u < 5; u++) {
        int idx = tid + 256 * u;
        if (idx < 1056) {
            int e = idx >> 5, dc = idx & 31;
            atomicAdd(&vkout[((size_t)bh * 33 + e) * 32 + dc], acc[u]);
        }
    }
}

__global__ __launch_bounds__(256)
void la_out_kernel(const __half* __restrict__ qkv, const float* __restrict__ vk,
                   __half* __restrict__ out)
{
    int row = blockIdx.x;
    int b   = row / Nn;
    __shared__ float q[Cc];
    __shared__ float den[HLA];
    const __half* qr = qkv + (size_t)row * 3 * Cc;
    for (int c = threadIdx.x; c < Cc; c += blockDim.x)
        q[c] = fmaxf(__half2float(qr[c]), 0.f);
    __syncthreads();
    if (threadIdx.x < HLA) {
        int h = threadIdx.x;
        const float* vkh = vk + ((size_t)(b * HLA + h) * 33 + 32) * 32;
        float s = 0.f;
        #pragma unroll
        for (int d = 0; d < 32; d++) s += vkh[d] * q[h * 32 + d];
        den[h] = s + 1e-8f;
    }
    __syncthreads();
    for (int c = threadIdx.x; c < Cc; c += blockDim.x) {
        int h = c >> 5, dd = c & 31;
        const float* vkr = vk + ((size_t)(b * HLA + h) * 33 + dd) * 32;
        const float* qh  = q + h * 32;
        float s = 0.f;
        #pragma unroll
        for (int d = 0; d < 32; d++) s += vkr[d] * qh[d];
        out[(size_t)row * Cc + c] = __float2half_rn(s / den[h]);
    }
}

// ---------------------------------------------------------------------------
// v^T materialization (half): vt[z][d][m], m padded to SLD with zeros
// ---------------------------------------------------------------------------
__global__ void vt_kernel(const __half* __restrict__ kv, __half* __restrict__ vt)
{
    long idx = (long)blockIdx.x * 256 + threadIdx.x;
    if (idx >= (long)Bb * HX * 72 * SLD) return;
    int  m = (int)(idx % SLD);
    long r = idx / SLD;
    int  d = (int)(r % 72);
    int  z = (int)(r / 72);
    int  b = z / HX, h = z % HX;
    __half v = __float2half_rn(0.f);
    if (m < Mkv) v = kv[((size_t)b * Mkv + m) * 2 * Cc + Cc + h * 72 + d];
    vt[idx] = v;
}

// ---------------------------------------------------------------------------
// Cross-attn softmax: reads float scores, writes half probs (pad cols -> 0)
// ---------------------------------------------------------------------------
__global__ __launch_bounds__(256)
void softmax_kernel(const float* __restrict__ s, __half* __restrict__ p, long rows)
{
    long gw  = ((long)blockIdx.x * blockDim.x + threadIdx.x) >> 5;
    int lane = threadIdx.x & 31;
    if (gw >= rows) return;
    const float* r = s + gw * SLD;
    __half* rp = p + gw * SLD;
    const float scale = 0.11785113019775793f;
    float v[10];
    float mx = -1e30f;
    #pragma unroll
    for (int i = 0; i < 10; i++) {
        int m = lane + 32 * i;
        v[i] = (m < Mkv) ? r[m] * scale : -1e30f;
        mx = fmaxf(mx, v[i]);
    }
    #pragma unroll
    for (int o = 16; o > 0; o >>= 1) mx = fmaxf(mx, __shfl_xor_sync(0xffffffffu, mx, o));
    float sum = 0.f;
    #pragma unroll
    for (int i = 0; i < 10; i++) { v[i] = __expf(v[i] - mx); sum += v[i]; }
    #pragma unroll
    for (int o = 16; o > 0; o >>= 1) sum += __shfl_xor_sync(0xffffffffu, sum, o);
    float inv = 1.f / sum;
    #pragma unroll
    for (int i = 0; i < 10; i++) {
        int m = lane + 32 * i;
        rp[m] = __float2half_rn((m < Mkv) ? v[i] * inv : 0.f);
    }
}

// ---------------------------------------------------------------------------
// depthwise 3x3 + bias + GLU, smem-tiled, half in / half out
// ---------------------------------------------------------------------------
__global__ __launch_bounds__(256)
void dwglu_kernel(const __half* __restrict__ h, const float* __restrict__ dww,
                  const float* __restrict__ dwb, __half* __restrict__ out)
{
    __shared__ float sa[100][64];
    __shared__ float sg[100][64];
    int tid = threadIdx.x;
    int c0  = blockIdx.x * 64;
    int y0  = (blockIdx.y >> 3) * 8, x0 = (blockIdx.y & 7) * 8;
    int b   = blockIdx.z;

    int ch = tid & 63;
    float wA[9], wG[9];
    #pragma unroll
    for (int tp = 0; tp < 9; tp++) {
        wA[tp] = dww[(size_t)(c0 + ch) * 9 + tp];
        wG[tp] = dww[(size_t)(c0 + ch + HIDd) * 9 + tp];
    }
    float bA = dwb[c0 + ch], bG = dwb[c0 + ch + HIDd];

    for (int li = tid; li < 1600; li += 256) {
        int pos = li >> 4, q = li & 15;
        int py = pos / 10, px = pos % 10;
        int yy = y0 + py - 1, xx = x0 + px - 1;
        float4 va = make_float4(0.f, 0.f, 0.f, 0.f), vg = va;
        if (yy >= 0 && yy < 64 && xx >= 0 && xx < 64) {
            const __half* src = h + ((size_t)b * Nn + yy * 64 + xx) * (2 * HIDd) + c0 + q * 4;
            float2 a01 = __half22float2(*(const __half2*)src);
            float2 a23 = __half22float2(*(const __half2*)(src + 2));
            float2 g01 = __half22float2(*(const __half2*)(src + HIDd));
            float2 g23 = __half22float2(*(const __half2*)(src + HIDd + 2));
            va = make_float4(a01.x, a01.y, a23.x, a23.y);
            vg = make_float4(g01.x, g01.y, g23.x, g23.y);
        }
        *(float4*)&sa[pos][q * 4] = va;
        *(float4*)&sg[pos][q * 4] = vg;
    }
    __syncthreads();

    #pragma unroll
    for (int i = 0; i < 16; i++) {
        int pos = (tid >> 6) + i * 4;
        int py = pos >> 3, px = pos & 7;
        int s0 = (py + 1) * 10 + (px + 1);
        float accA = bA, accG = bG;
        #pragma unroll
        for (int dy = -1; dy <= 1; dy++)
            #pragma unroll
            for (int dx = -1; dx <= 1; dx++) {
                int s = s0 + dy * 10 + dx;
                int tp = (dy + 1) * 3 + (dx + 1);
                accA = fmaf(sa[s][ch], wA[tp], accA);
                accG = fmaf(sg[s][ch], wG[tp], accG);
            }
        int n = (y0 + py) * 64 + (x0 + px);
        out[((size_t)b * Nn + n) * HIDd + c0 + ch] =
            __float2half_rn(accA * (accG / (1.f + __expf(-accG))));
    }
}

// ---------------------------------------------------------------------------
extern "C" void kernel_launch(void* const* d_in, const int* /*in_sizes*/, int /*n_in*/,
                              void* d_out, int /*out_size*/)
{
    const float* x       = (const float*)d_in[0];
    const float* y       = (const float*)d_in[1];
    const float* t       = (const float*)d_in[2];
    const float* sst     = (const float*)d_in[3];
    const float* qkv_w   = (const float*)d_in[4];
    const float* aproj_w = (const float*)d_in[5];
    const float* aproj_b = (const float*)d_in[6];
    const float* q_w     = (const float*)d_in[7];
    const float* q_b     = (const float*)d_in[8];
    const float* kv_w    = (const float*)d_in[9];
    const float* kv_b    = (const float*)d_in[10];
    const float* cproj_w = (const float*)d_in[11];
    const float* cproj_b = (const float*)d_in[12];
    const float* inv_w   = (const float*)d_in[13];
    const float* inv_b   = (const float*)d_in[14];
    const float* dw_w    = (const float*)d_in[15];
    const float* dw_b    = (const float*)d_in[16];
    const float* pw_w    = (const float*)d_in[17];
    float* out = (float*)d_out;

    float  *p_big, *p_x1, *p_x2, *p_vk, *p_m;
    __half *p_shh, *p_x1h, *p_glu, *p_kvh, *p_vt, *p_prb, *p_yh, *p_w;
    cudaGetSymbolAddress((void**)&p_big, g_big);
    cudaGetSymbolAddress((void**)&p_shh, g_shh);
    cudaGetSymbolAddress((void**)&p_x1,  g_x1);
    cudaGetSymbolAddress((void**)&p_x1h, g_x1h);
    cudaGetSymbolAddress((void**)&p_x2,  g_x2);
    cudaGetSymbolAddress((void**)&p_glu, g_glu);
    cudaGetSymbolAddress((void**)&p_kvh, g_kvb);
    cudaGetSymbolAddress((void**)&p_vt,  g_vt);
    cudaGetSymbolAddress((void**)&p_prb, g_prb);
    cudaGetSymbolAddress((void**)&p_yh,  g_yh);
    cudaGetSymbolAddress((void**)&p_vk,  g_vk);
    cudaGetSymbolAddress((void**)&p_m,   g_mb);
    cudaGetSymbolAddress((void**)&p_w,   g_wts);

    __half* p_bigh = (__half*)p_big;      // qkv (then h) half view of g_big

    const int ROWS = Bb * Nn;  // 8192
    const long RN_TOTAL = (long)3*Cc*Cc + 5L*Cc*Cc + 2L*HIDd*Cc + (long)Cc*HIDd
                        + (long)Bb*Mkv*Cc;

    // order chosen so the ncu capture slot (index 3) lands on the qkv GEMM
    mod_kernel<<<(Bb * 6 * Cc + 255) / 256, 256>>>(t, sst);
    round_all_kernel<<<(int)((RN_TOTAL + 255) / 256), 256>>>(
        qkv_w, aproj_w, q_w, kv_w, cproj_w, inv_w, pw_w, y);
    ln_mod_kernel<<<ROWS, 256>>>(x, p_shh, 1, 0);

    // qkv = xmod1 @ qkv_w.T  (half out)
    mma_gemm<false,0,false,true><<<dim3(27, 64), 256, MM_SMEM>>>(
        p_shh, p_w + W_QKV, nullptr, nullptr, nullptr, nullptr, p_bigh,
        ROWS, 3 * Cc, 3 * Cc, Cc, Cc, Cc, 3 * Cc,
        1, 0, 0, 0, 0, 0, 0, 0);

    zero_vk_kernel<<<(Bb * HLA * 33 * 32 + 255) / 256, 256>>>();
    vk_kernel<<<dim3(Bb * HLA, 16), 256>>>(p_bigh, p_vk);
    la_out_kernel<<<ROWS, 256>>>(p_bigh, p_vk, p_shh);

    // x1 = x + g_a * (la @ aproj_w.T + b)  (float x1 + half x1h)
    mma_gemm<true,3,true,true><<<dim3(9, 64), 256, MM_SMEM>>>(
        p_shh, p_w + W_APR, aproj_b, x, p_m + 2 * Cc, p_x1, p_x1h,
        ROWS, Cc, Cc, Cc, Cc, Cc, Cc,
        1, 0, 0, 0, 0, 0, 0, 6 * Cc);

    // q = x1 @ q_w.T + q_b  (half out)
    mma_gemm<true,0,false,true><<<dim3(9, 64), 256, MM_SMEM>>>(
        p_x1h, p_w + W_Q, q_b, nullptr, nullptr, nullptr, p_shh,
        ROWS, Cc, Cc, Cc, Cc, Cc, Cc,
        1, 0, 0, 0, 0, 0, 0, 0);

    // kv = y @ kv_w.T + kv_b  (half out)
    mma_gemm<true,0,false,true><<<dim3(18, 5), 256, MM_SMEM>>>(
        p_yh, p_w + W_KV, kv_b, nullptr, nullptr, nullptr, p_kvh,
        Bb * Mkv, 2 * Cc, 2 * Cc, Cc, Cc, Cc, 2 * Cc,
        1, 0, 0, 0, 0, 0, 0, 0);

    vt_kernel<<<(int)(((long)Bb * HX * 72 * SLD + 255) / 256), 256>>>(p_kvh, p_vt);

    // scores[z] = q_h @ k_h.T  (float out; all SLD cols written finite)
    mma_gemm<false,0,true,false><<<dim3(3, 32, Bb * HX), 256, MM_SMEM>>>(
        p_shh, p_kvh, nullptr, nullptr, nullptr, p_big, nullptr,
        Nn, Mkv, SLD, 72, Cc, 2 * Cc, SLD,
        HX, (long)Nn * Cc, 72, (long)Mkv * 2 * Cc, 72,
        (long)HX * Nn * SLD, (long)Nn * SLD, 0);

    softmax_kernel<<<(Bb * HX * Nn) / 8, 256>>>(p_big, p_prb, (long)Bb * HX * Nn);

    // o[z] = probs @ v^T  (half out)
    mma_gemm<false,0,false,true><<<dim3(1, 32, Bb * HX), 256, MM_SMEM>>>(
        p_prb, p_vt, nullptr, nullptr, nullptr, nullptr, p_shh,
        Nn, 72, 72, SLD, SLD, SLD, Cc,
        HX, (long)HX * Nn * SLD, (long)Nn * SLD, (long)72 * SLD * HX, (long)72 * SLD,
        (long)Nn * Cc, 72, 0);

    // x2 = x1 + o @ cproj_w.T + b  (float out)
    mma_gemm<true,2,true,false><<<dim3(9, 64), 256, MM_SMEM>>>(
        p_shh, p_w + W_CPR, cproj_b, p_x1, nullptr, p_x2, nullptr,
        ROWS, Cc, Cc, Cc, Cc, Cc, Cc,
        1, 0, 0, 0, 0, 0, 0, 0);

    ln_mod_kernel<<<ROWS, 256>>>(p_x2, p_shh, 4, 3);

    // h = silu(xmod2 @ inv_w.T + b)  (half out, into g_big)
    mma_gemm<true,1,false,true><<<dim3(45, 64), 256, MM_SMEM>>>(
        p_shh, p_w + W_INV, inv_b, nullptr, nullptr, nullptr, p_bigh,
        ROWS, 2 * HIDd, 2 * HIDd, Cc, Cc, Cc, 2 * HIDd,
        1, 0, 0, 0, 0, 0, 0, 0);

    dwglu_kernel<<<dim3(HIDd / 64, 64, Bb), 256>>>(p_bigh, dw_w, dw_b, p_glu);

    // out = x2 + g_m * (glu @ pw_w.T)  (float out)
    mma_gemm<false,3,true,false><<<dim3(9, 64), 256, MM_SMEM>>>(
        p_glu, p_w + W_PW, nullptr, p_x2, p_m + 5 * Cc, out, nullptr,
        ROWS, Cc, Cc, HIDd, HIDd, HIDd, Cc,
        1, 0, 0, 0, 0, 0, 0, 6 * Cc);
}

// round 8
// speedup vs baseline: 2.6306x; 1.0675x over previous
#include <cuda_runtime.h>
#include <cuda_fp16.h>
#include <cstdint>
#include <math.h>

// ---------------------------------------------------------------------------
// SanaBlock: LN+adaLN -> LiteLA -> cross-attn -> GLUMBConv, B=2,N=4096,C=1152
// R8: fp16 mma GEMM with ldmatrix.x4 fragment loads (48 LDS -> 12 LDSM /K-tile)
// ---------------------------------------------------------------------------
constexpr int Bb   = 2;
constexpr int Nn   = 4096;
constexpr int Cc   = 1152;
constexpr int Mkv  = 300;
constexpr int HIDd = 2880;
constexpr int HLA  = 36;
constexpr int HX   = 16;
constexpr int SLD  = 320;

__device__ __align__(256) float  g_big [47185920];
__device__ __align__(256) __half g_shh [(size_t)Bb * Nn * Cc];
__device__ __align__(256) float  g_x1  [(size_t)Bb * Nn * Cc];
__device__ __align__(256) __half g_x1h [(size_t)Bb * Nn * Cc];
__device__ __align__(256) float  g_x2  [(size_t)Bb * Nn * Cc];
__device__ __align__(256) __half g_glu [(size_t)Bb * Nn * HIDd];
__device__ __align__(256) __half g_kvb [(size_t)Bb * Mkv * 2 * Cc];
__device__ __align__(256) __half g_vt  [(size_t)Bb * HX * 72 * SLD];
__device__ __align__(256) __half g_prb [(size_t)Bb * HX * Nn * SLD];
__device__ __align__(256) __half g_yh  [(size_t)Bb * Mkv * Cc];
__device__ __align__(256) __half g_wts [20570112];
__device__ float g_vk [Bb * HLA * 33 * 32];
__device__ float g_mb [Bb * 6 * Cc];

constexpr size_t W_QKV = 0;
constexpr size_t W_APR = W_QKV + (size_t)3 * Cc * Cc;
constexpr size_t W_Q   = W_APR + (size_t)Cc * Cc;
constexpr size_t W_KV  = W_Q   + (size_t)Cc * Cc;
constexpr size_t W_CPR = W_KV  + (size_t)2 * Cc * Cc;
constexpr size_t W_INV = W_CPR + (size_t)Cc * Cc;
constexpr size_t W_PW  = W_INV + (size_t)2 * HIDd * Cc;

// ---------------------------------------------------------------------------
// helpers
// ---------------------------------------------------------------------------
__device__ __forceinline__ uint32_t smem_u32(const void* p){
    uint32_t a;
    asm("{ .reg .u64 t; cvta.to.shared.u64 t, %1; cvt.u32.u64 %0, t; }"
        : "=r"(a) : "l"(p));
    return a;
}
__device__ __forceinline__ void cp16(uint32_t dst, const void* src, int srcsz){
    asm volatile("cp.async.cg.shared.global [%0], [%1], 16, %2;"
        ::"r"(dst),"l"(src),"r"(srcsz):"memory");
}
#define CP_COMMIT() asm volatile("cp.async.commit_group;":::"memory")
#define CP_WAIT1()  asm volatile("cp.async.wait_group 1;":::"memory")

__device__ __forceinline__ void mma16(float* d, const uint32_t* a, const uint32_t* b){
    asm volatile("mma.sync.aligned.m16n8k16.row.col.f32.f16.f16.f32 "
        "{%0,%1,%2,%3},{%4,%5,%6,%7},{%8,%9},{%0,%1,%2,%3};"
        : "+f"(d[0]),"+f"(d[1]),"+f"(d[2]),"+f"(d[3])
        : "r"(a[0]),"r"(a[1]),"r"(a[2]),"r"(a[3]),"r"(b[0]),"r"(b[1]));
}
__device__ __forceinline__ void ldsm4(uint32_t& r0, uint32_t& r1, uint32_t& r2,
                                      uint32_t& r3, uint32_t addr){
    asm volatile("ldmatrix.sync.aligned.m8n8.x4.shared.b16 {%0,%1,%2,%3}, [%4];"
        : "=r"(r0),"=r"(r1),"=r"(r2),"=r"(r3) : "r"(addr));
}

// ---------------------------------------------------------------------------
// fp16 mma NT GEMM: O[M,N] = epi(A[M,K]*B[NloadB,K]^T + bias), fp32 accum.
// CTA 128x128x32, 8 warps (4M x 2N), warp tile 32x64, 2-stage cp.async,
// ldmatrix.x4 fragment loads.
// ---------------------------------------------------------------------------
constexpr int LDPH    = 40;
constexpr int TILE_H  = 128 * LDPH;
constexpr int STAGE_H = 2 * TILE_H;
constexpr int MM_SMEM = 2 * STAGE_H * 2;  // 40960 bytes

template<bool BIAS, int EPI, bool WF, bool WH>
__global__ __launch_bounds__(256, 2)
void mma_gemm(const __half* A, const __half* Bw, const float* bias,
              const float* res, const float* gate,
              float* Of, __half* Oh,
              int Mrows, int NloadB, int Nstore, int K,
              int lda, int ldb, int ldo,
              int HB, long aBs, long aHs, long bBs, long bHs, long oBs, long oHs,
              int gateStride)
{
    extern __shared__ __half smh[];
    uint32_t sbase = smem_u32(smh);
    int tid = threadIdx.x, wid = tid >> 5, lane = tid & 31;
    int warpM = wid >> 1, warpN = wid & 1;
    int m0 = blockIdx.y * 128, n0 = blockIdx.x * 128;

    if (gridDim.z > 1) {
        int z = blockIdx.z;
        int bI = z / HB, hI = z % HB;
        A  += bI * aBs + hI * aHs;
        Bw += bI * bBs + hI * bHs;
        if (WF) Of += bI * oBs + hI * oHs;
        if (WH) Oh += bI * oBs + hI * oHs;
    }

    const int T = (K + 31) >> 5;

    auto load_tile = [&](int t, int buf) {
        uint32_t base = sbase + (uint32_t)buf * STAGE_H * 2;
        int k0 = t << 5;
        #pragma unroll
        for (int i = 0; i < 2; i++) {
            int c = tid + (i << 8);
            int row = c >> 2, ch = c & 3;
            int gk = k0 + ch * 8;
            uint32_t dst = base + (uint32_t)(row * LDPH * 2 + ch * 16);
            const __half* ga = A + (size_t)(m0 + row) * lda + gk;
            cp16(dst, ga, ((m0 + row) < Mrows && gk < K) ? 16 : 0);
            uint32_t dstB = dst + TILE_H * 2;
            const __half* gb = Bw + (size_t)(n0 + row) * ldb + gk;
            cp16(dstB, gb, ((n0 + row) < NloadB && gk < K) ? 16 : 0);
        }
    };

    float acc[2][8][4];
    #pragma unroll
    for (int mt = 0; mt < 2; mt++)
        #pragma unroll
        for (int nt = 0; nt < 8; nt++)
            #pragma unroll
            for (int q = 0; q < 4; q++) acc[mt][nt][q] = 0.f;

    load_tile(0, 0); CP_COMMIT();

    // ldmatrix per-thread source coordinates
    int rowA = warpM * 32 + (lane & 15);          // + mt*16
    int colA = (lane >> 4) << 3;                  // + kk*16
    int rowB = warpN * 64 + (lane & 7) + ((lane >> 4) << 3);   // + ntp*16
    int colB = ((lane >> 3) & 1) << 3;            // + kk*16

    for (int t = 0; t < T; t++) {
        int buf = t & 1;
        if (t + 1 < T) load_tile(t + 1, buf ^ 1);
        CP_COMMIT();
        CP_WAIT1();
        __syncthreads();

        uint32_t sA = sbase + (uint32_t)buf * STAGE_H * 2;
        uint32_t sB = sA + TILE_H * 2;

        #pragma unroll
        for (int kk = 0; kk < 2; kk++) {
            uint32_t af[2][4];
            #pragma unroll
            for (int mt = 0; mt < 2; mt++) {
                uint32_t addr = sA + (uint32_t)(((rowA + mt * 16) * LDPH)
                                                + colA + kk * 16) * 2;
                ldsm4(af[mt][0], af[mt][1], af[mt][2], af[mt][3], addr);
            }
            uint32_t bf[8][2];
            #pragma unroll
            for (int ntp = 0; ntp < 4; ntp++) {
                uint32_t addr = sB + (uint32_t)(((rowB + ntp * 16) * LDPH)
                                                + colB + kk * 16) * 2;
                ldsm4(bf[2 * ntp][0], bf[2 * ntp][1],
                      bf[2 * ntp + 1][0], bf[2 * ntp + 1][1], addr);
            }
            #pragma unroll
            for (int mt = 0; mt < 2; mt++)
                #pragma unroll
                for (int nt = 0; nt < 8; nt++)
                    mma16(acc[mt][nt], af[mt], bf[nt]);
        }
        __syncthreads();
    }

    #pragma unroll
    for (int mt = 0; mt < 2; mt++) {
        #pragma unroll
        for (int half_ = 0; half_ < 2; half_++) {
            int row = m0 + warpM * 32 + mt * 16 + (lane >> 2) + half_ * 8;
            if (row >= Mrows) continue;
            int bI = (row >= Nn) ? 1 : 0;
            #pragma unroll
            for (int nt = 0; nt < 8; nt++) {
                int col = n0 + warpN * 64 + nt * 8 + (lane & 3) * 2;
                if (col >= Nstore) continue;
                float v0 = acc[mt][nt][half_ * 2];
                float v1 = acc[mt][nt][half_ * 2 + 1];
                if (BIAS) { v0 += bias[col]; v1 += bias[col + 1]; }
                if (EPI == 1) {
                    v0 = v0 / (1.f + __expf(-v0));
                    v1 = v1 / (1.f + __expf(-v1));
                }
                if (EPI == 2) {
                    v0 += res[(size_t)row * ldo + col];
                    v1 += res[(size_t)row * ldo + col + 1];
                }
                if (EPI == 3) {
                    v0 = res[(size_t)row * ldo + col]     + gate[bI * gateStride + col]     * v0;
                    v1 = res[(size_t)row * ldo + col + 1] + gate[bI * gateStride + col + 1] * v1;
                }
                if (WF) *(float2*)&Of[(size_t)row * ldo + col] = make_float2(v0, v1);
                if (WH) *(__half2*)&Oh[(size_t)row * ldo + col] = __floats2half2_rn(v0, v1);
            }
        }
    }
}

// ---------------------------------------------------------------------------
// m = sst + t
// ---------------------------------------------------------------------------
__global__ void mod_kernel(const float* __restrict__ t, const float* __restrict__ sst)
{
    int i = blockIdx.x * 256 + threadIdx.x;
    if (i < Bb * 6 * Cc) g_mb[i] = sst[i % (6 * Cc)] + t[i];
}

// ---------------------------------------------------------------------------
// all weight (and y) fp16 conversion in ONE launch
// ---------------------------------------------------------------------------
__global__ void round_all_kernel(const float* qkv_w, const float* aproj_w,
                                 const float* q_w, const float* kv_w,
                                 const float* cproj_w, const float* inv_w,
                                 const float* pw_w, const float* y)
{
    long i = (long)blockIdx.x * 256 + threadIdx.x;
    long n;
    n = (long)3 * Cc * Cc;   if (i < n) { g_wts[W_QKV + i] = __float2half_rn(qkv_w[i]);   return; } i -= n;
    n = (long)Cc * Cc;       if (i < n) { g_wts[W_APR + i] = __float2half_rn(aproj_w[i]); return; } i -= n;
    n = (long)Cc * Cc;       if (i < n) { g_wts[W_Q   + i] = __float2half_rn(q_w[i]);     return; } i -= n;
    n = (long)2 * Cc * Cc;   if (i < n) { g_wts[W_KV  + i] = __float2half_rn(kv_w[i]);    return; } i -= n;
    n = (long)Cc * Cc;       if (i < n) { g_wts[W_CPR + i] = __float2half_rn(cproj_w[i]); return; } i -= n;
    n = (long)2 * HIDd * Cc; if (i < n) { g_wts[W_INV + i] = __float2half_rn(inv_w[i]);   return; } i -= n;
    n = (long)Cc * HIDd;     if (i < n) { g_wts[W_PW  + i] = __float2half_rn(pw_w[i]);    return; } i -= n;
    n = (long)Bb * Mkv * Cc; if (i < n) { g_yh[i] = __float2half_rn(y[i]); }
}

// ---------------------------------------------------------------------------
// LayerNorm + adaLN modulate (writes half)
// ---------------------------------------------------------------------------
__global__ __launch_bounds__(256)
void ln_mod_kernel(const float* __restrict__ in, __half* __restrict__ out,
                   int scRow, int shRow)
{
    int row = blockIdx.x;
    int b   = row / Nn;
    const float* xr = in + (size_t)row * Cc;

    float s = 0.f, s2 = 0.f;
    for (int c = threadIdx.x; c < Cc; c += blockDim.x) {
        float v = xr[c]; s += v; s2 += v * v;
    }
    __shared__ float sh1[8], sh2[8];
    int lane = threadIdx.x & 31, wid = threadIdx.x >> 5;
    #pragma unroll
    for (int o = 16; o > 0; o >>= 1) {
        s  += __shfl_down_sync(0xffffffffu, s,  o);
        s2 += __shfl_down_sync(0xffffffffu, s2, o);
    }
    if (lane == 0) { sh1[wid] = s; sh2[wid] = s2; }
    __syncthreads();
    if (wid == 0) {
        s  = (lane < 8) ? sh1[lane] : 0.f;
        s2 = (lane < 8) ? sh2[lane] : 0.f;
        #pragma unroll
        for (int o = 4; o > 0; o >>= 1) {
            s  += __shfl_down_sync(0xffffffffu, s,  o);
            s2 += __shfl_down_sync(0xffffffffu, s2, o);
        }
        if (lane == 0) { sh1[0] = s; sh2[0] = s2; }
    }
    __syncthreads();
    float mu   = sh1[0] * (1.f / Cc);
    float var  = sh2[0] * (1.f / Cc) - mu * mu;
    float rstd = rsqrtf(var + 1e-6f);
    const float* mbp = g_mb + (size_t)b * 6 * Cc;
    for (int c = threadIdx.x; c < Cc; c += blockDim.x) {
        float sc = mbp[scRow * Cc + c];
        float sv = mbp[shRow * Cc + c];
        out[(size_t)row * Cc + c] =
            __float2half_rn((xr[c] - mu) * rstd * (1.f + sc) + sv);
    }
}

// ---------------------------------------------------------------------------
// LiteLA vk accumulation + epilogue
// ---------------------------------------------------------------------------
__global__ void zero_vk_kernel()
{
    int i = blockIdx.x * 256 + threadIdx.x;
    if (i < Bb * HLA * 33 * 32) g_vk[i] = 0.f;
}

__global__ __launch_bounds__(256)
void vk_kernel(const __half* __restrict__ qkv, float* __restrict__ vkout)
{
    int bh = blockIdx.x;
    int b  = bh / HLA, h = bh % HLA;
    int split = blockIdx.y;
    __shared__ float ks[32][33];
    __shared__ float vs[32][33];
    float acc[5] = {0.f, 0.f, 0.f, 0.f, 0.f};
    int tid = threadIdx.x;
    const size_t base = (size_t)b * Nn * 3 * Cc;
    int nStart = split * (Nn / 16);
    for (int n0 = nStart; n0 < nStart + Nn / 16; n0 += 32) {
        for (int li = tid; li < 1024; li += 256) {
            int nn = li >> 5, dc = li & 31;
            size_t off = base + (size_t)(n0 + nn) * 3 * Cc + h * 32 + dc;
            ks[nn][dc] = fmaxf(__half2float(qkv[off + Cc]), 0.f);
            vs[nn][dc] = __half2float(qkv[off + 2 * Cc]);
        }
        __syncthreads();
        #pragma unroll
        for (int u = 0; u < 5; u++) {
            int idx = tid + 256 * u;
            if (idx < 1056) {
                int e = idx >> 5, dc = idx & 31;
                float a = acc[u];
                if (e == 32) {
                    #pragma unroll
                    for (int nn = 0; nn < 32; nn++) a += ks[nn][dc];
                } else {
                    #pragma unroll
                    for (int nn = 0; nn < 32; nn++) a += vs[nn][e] * ks[nn][dc];
                }
                acc[u] = a;
            }
        }
        __syncthreads();
    }
    #pragma unroll
    for (int u = 0; u < 5; u++) {
        int idx = tid + 256 * u;
        if (idx < 1056) {
            int e = idx >> 5, dc = idx & 31;
            atomicAdd(&vkout[((size_t)bh * 33 + e) * 32 + dc], acc[u]);
        }
    }
}

__global__ __launch_bounds__(256)
void la_out_kernel(const __half* __restrict__ qkv, const float* __restrict__ vk,
                   __half* __restrict__ out)
{
    int row = blockIdx.x;
    int b   = row / Nn;
    __shared__ float q[Cc];
    __shared__ float den[HLA];
    const __half* qr = qkv + (size_t)row * 3 * Cc;
    for (int c = threadIdx.x; c < Cc; c += blockDim.x)
        q[c] = fmaxf(__half2float(qr[c]), 0.f);
    __syncthreads();
    if (threadIdx.x < HLA) {
        int h = threadIdx.x;
        const float* vkh = vk + ((size_t)(b * HLA + h) * 33 + 32) * 32;
        float s = 0.f;
        #pragma unroll
        for (int d = 0; d < 32; d++) s += vkh[d] * q[h * 32 + d];
        den[h] = s + 1e-8f;
    }
    __syncthreads();
    for (int c = threadIdx.x; c < Cc; c += blockDim.x) {
        int h = c >> 5, dd = c & 31;
        const float* vkr = vk + ((size_t)(b * HLA + h) * 33 + dd) * 32;
        const float* qh  = q + h * 32;
        float s = 0.f;
        #pragma unroll
        for (int d = 0; d < 32; d++) s += vkr[d] * qh[d];
        out[(size_t)row * Cc + c] = __float2half_rn(s / den[h]);
    }
}

// ---------------------------------------------------------------------------
// v^T materialization (half), m padded to SLD with zeros
// ---------------------------------------------------------------------------
__global__ void vt_kernel(const __half* __restrict__ kv, __half* __restrict__ vt)
{
    long idx = (long)blockIdx.x * 256 + threadIdx.x;
    if (idx >= (long)Bb * HX * 72 * SLD) return;
    int  m = (int)(idx % SLD);
    long r = idx / SLD;
    int  d = (int)(r % 72);
    int  z = (int)(r / 72);
    int  b = z / HX, h = z % HX;
    __half v = __float2half_rn(0.f);
    if (m < Mkv) v = kv[((size_t)b * Mkv + m) * 2 * Cc + Cc + h * 72 + d];
    vt[idx] = v;
}

// ---------------------------------------------------------------------------
// Cross-attn softmax: float scores -> half probs (pad cols -> 0)
// ---------------------------------------------------------------------------
__global__ __launch_bounds__(256)
void softmax_kernel(const float* __restrict__ s, __half* __restrict__ p, long rows)
{
    long gw  = ((long)blockIdx.x * blockDim.x + threadIdx.x) >> 5;
    int lane = threadIdx.x & 31;
    if (gw >= rows) return;
    const float* r = s + gw * SLD;
    __half* rp = p + gw * SLD;
    const float scale = 0.11785113019775793f;
    float v[10];
    float mx = -1e30f;
    #pragma unroll
    for (int i = 0; i < 10; i++) {
        int m = lane + 32 * i;
        v[i] = (m < Mkv) ? r[m] * scale : -1e30f;
        mx = fmaxf(mx, v[i]);
    }
    #pragma unroll
    for (int o = 16; o > 0; o >>= 1) mx = fmaxf(mx, __shfl_xor_sync(0xffffffffu, mx, o));
    float sum = 0.f;
    #pragma unroll
    for (int i = 0; i < 10; i++) { v[i] = __expf(v[i] - mx); sum += v[i]; }
    #pragma unroll
    for (int o = 16; o > 0; o >>= 1) sum += __shfl_xor_sync(0xffffffffu, sum, o);
    float inv = 1.f / sum;
    #pragma unroll
    for (int i = 0; i < 10; i++) {
        int m = lane + 32 * i;
        rp[m] = __float2half_rn((m < Mkv) ? v[i] * inv : 0.f);
    }
}

// ---------------------------------------------------------------------------
// depthwise 3x3 + bias + GLU, smem-tiled, half in / half out
// ---------------------------------------------------------------------------
__global__ __launch_bounds__(256)
void dwglu_kernel(const __half* __restrict__ h, const float* __restrict__ dww,
                  const float* __restrict__ dwb, __half* __restrict__ out)
{
    __shared__ float sa[100][64];
    __shared__ float sg[100][64];
    int tid = threadIdx.x;
    int c0  = blockIdx.x * 64;
    int y0  = (blockIdx.y >> 3) * 8, x0 = (blockIdx.y & 7) * 8;
    int b   = blockIdx.z;

    int ch = tid & 63;
    float wA[9], wG[9];
    #pragma unroll
    for (int tp = 0; tp < 9; tp++) {
        wA[tp] = dww[(size_t)(c0 + ch) * 9 + tp];
        wG[tp] = dww[(size_t)(c0 + ch + HIDd) * 9 + tp];
    }
    float bA = dwb[c0 + ch], bG = dwb[c0 + ch + HIDd];

    for (int li = tid; li < 1600; li += 256) {
        int pos = li >> 4, q = li & 15;
        int py = pos / 10, px = pos % 10;
        int yy = y0 + py - 1, xx = x0 + px - 1;
        float4 va = make_float4(0.f, 0.f, 0.f, 0.f), vg = va;
        if (yy >= 0 && yy < 64 && xx >= 0 && xx < 64) {
            const __half* src = h + ((size_t)b * Nn + yy * 64 + xx) * (2 * HIDd) + c0 + q * 4;
            float2 a01 = __half22float2(*(const __half2*)src);
            float2 a23 = __half22float2(*(const __half2*)(src + 2));
            float2 g01 = __half22float2(*(const __half2*)(src + HIDd));
            float2 g23 = __half22float2(*(const __half2*)(src + HIDd + 2));
            va = make_float4(a01.x, a01.y, a23.x, a23.y);
            vg = make_float4(g01.x, g01.y, g23.x, g23.y);
        }
        *(float4*)&sa[pos][q * 4] = va;
        *(float4*)&sg[pos][q * 4] = vg;
    }
    __syncthreads();

    #pragma unroll
    for (int i = 0; i < 16; i++) {
        int pos = (tid >> 6) + i * 4;
        int py = pos >> 3, px = pos & 7;
        int s0 = (py + 1) * 10 + (px + 1);
        float accA = bA, accG = bG;
        #pragma unroll
        for (int dy = -1; dy <= 1; dy++)
            #pragma unroll
            for (int dx = -1; dx <= 1; dx++) {
                int s = s0 + dy * 10 + dx;
                int tp = (dy + 1) * 3 + (dx + 1);
                accA = fmaf(sa[s][ch], wA[tp], accA);
                accG = fmaf(sg[s][ch], wG[tp], accG);
            }
        int n = (y0 + py) * 64 + (x0 + px);
        out[((size_t)b * Nn + n) * HIDd + c0 + ch] =
            __float2half_rn(accA * (accG / (1.f + __expf(-accG))));
    }
}

// ---------------------------------------------------------------------------
extern "C" void kernel_launch(void* const* d_in, const int* /*in_sizes*/, int /*n_in*/,
                              void* d_out, int /*out_size*/)
{
    const float* x       = (const float*)d_in[0];
    const float* y       = (const float*)d_in[1];
    const float* t       = (const float*)d_in[2];
    const float* sst     = (const float*)d_in[3];
    const float* qkv_w   = (const float*)d_in[4];
    const float* aproj_w = (const float*)d_in[5];
    const float* aproj_b = (const float*)d_in[6];
    const float* q_w     = (const float*)d_in[7];
    const float* q_b     = (const float*)d_in[8];
    const float* kv_w    = (const float*)d_in[9];
    const float* kv_b    = (const float*)d_in[10];
    const float* cproj_w = (const float*)d_in[11];
    const float* cproj_b = (const float*)d_in[12];
    const float* inv_w   = (const float*)d_in[13];
    const float* inv_b   = (const float*)d_in[14];
    const float* dw_w    = (const float*)d_in[15];
    const float* dw_b    = (const float*)d_in[16];
    const float* pw_w    = (const float*)d_in[17];
    float* out = (float*)d_out;

    float  *p_big, *p_x1, *p_x2, *p_vk, *p_m;
    __half *p_shh, *p_x1h, *p_glu, *p_kvh, *p_vt, *p_prb, *p_yh, *p_w;
    cudaGetSymbolAddress((void**)&p_big, g_big);
    cudaGetSymbolAddress((void**)&p_shh, g_shh);
    cudaGetSymbolAddress((void**)&p_x1,  g_x1);
    cudaGetSymbolAddress((void**)&p_x1h, g_x1h);
    cudaGetSymbolAddress((void**)&p_x2,  g_x2);
    cudaGetSymbolAddress((void**)&p_glu, g_glu);
    cudaGetSymbolAddress((void**)&p_kvh, g_kvb);
    cudaGetSymbolAddress((void**)&p_vt,  g_vt);
    cudaGetSymbolAddress((void**)&p_prb, g_prb);
    cudaGetSymbolAddress((void**)&p_yh,  g_yh);
    cudaGetSymbolAddress((void**)&p_vk,  g_vk);
    cudaGetSymbolAddress((void**)&p_m,   g_mb);
    cudaGetSymbolAddress((void**)&p_w,   g_wts);

    __half* p_bigh = (__half*)p_big;

    const int ROWS = Bb * Nn;
    const long RN_TOTAL = (long)3*Cc*Cc + 5L*Cc*Cc + 2L*HIDd*Cc + (long)Cc*HIDd
                        + (long)Bb*Mkv*Cc;

    mod_kernel<<<(Bb * 6 * Cc + 255) / 256, 256>>>(t, sst);
    round_all_kernel<<<(int)((RN_TOTAL + 255) / 256), 256>>>(
        qkv_w, aproj_w, q_w, kv_w, cproj_w, inv_w, pw_w, y);
    ln_mod_kernel<<<ROWS, 256>>>(x, p_shh, 1, 0);

    // qkv = xmod1 @ qkv_w.T  (half out)
    mma_gemm<false,0,false,true><<<dim3(27, 64), 256, MM_SMEM>>>(
        p_shh, p_w + W_QKV, nullptr, nullptr, nullptr, nullptr, p_bigh,
        ROWS, 3 * Cc, 3 * Cc, Cc, Cc, Cc, 3 * Cc,
        1, 0, 0, 0, 0, 0, 0, 0);

    zero_vk_kernel<<<(Bb * HLA * 33 * 32 + 255) / 256, 256>>>();
    vk_kernel<<<dim3(Bb * HLA, 16), 256>>>(p_bigh, p_vk);
    la_out_kernel<<<ROWS, 256>>>(p_bigh, p_vk, p_shh);

    // x1 = x + g_a * (la @ aproj_w.T + b)
    mma_gemm<true,3,true,true><<<dim3(9, 64), 256, MM_SMEM>>>(
        p_shh, p_w + W_APR, aproj_b, x, p_m + 2 * Cc, p_x1, p_x1h,
        ROWS, Cc, Cc, Cc, Cc, Cc, Cc,
        1, 0, 0, 0, 0, 0, 0, 6 * Cc);

    // q = x1 @ q_w.T + q_b
    mma_gemm<true,0,false,true><<<dim3(9, 64), 256, MM_SMEM>>>(
        p_x1h, p_w + W_Q, q_b, nullptr, nullptr, nullptr, p_shh,
        ROWS, Cc, Cc, Cc, Cc, Cc, Cc,
        1, 0, 0, 0, 0, 0, 0, 0);

    // kv = y @ kv_w.T + kv_b
    mma_gemm<true,0,false,true><<<dim3(18, 5), 256, MM_SMEM>>>(
        p_yh, p_w + W_KV, kv_b, nullptr, nullptr, nullptr, p_kvh,
        Bb * Mkv, 2 * Cc, 2 * Cc, Cc, Cc, Cc, 2 * Cc,
        1, 0, 0, 0, 0, 0, 0, 0);

    vt_kernel<<<(int)(((long)Bb * HX * 72 * SLD + 255) / 256), 256>>>(p_kvh, p_vt);

    // scores[z] = q_h @ k_h.T  (float out)
    mma_gemm<false,0,true,false><<<dim3(3, 32, Bb * HX), 256, MM_SMEM>>>(
        p_shh, p_kvh, nullptr, nullptr, nullptr, p_big, nullptr,
        Nn, Mkv, SLD, 72, Cc, 2 * Cc, SLD,
        HX, (long)Nn * Cc, 72, (long)Mkv * 2 * Cc, 72,
        (long)HX * Nn * SLD, (long)Nn * SLD, 0);

    softmax_kernel<<<(Bb * HX * Nn) / 8, 256>>>(p_big, p_prb, (long)Bb * HX * Nn);

    // o[z] = probs @ v^T  (half out)
    mma_gemm<false,0,false,true><<<dim3(1, 32, Bb * HX), 256, MM_SMEM>>>(
        p_prb, p_vt, nullptr, nullptr, nullptr, nullptr, p_shh,
        Nn, 72, 72, SLD, SLD, SLD, Cc,
        HX, (long)HX * Nn * SLD, (long)Nn * SLD, (long)72 * SLD * HX, (long)72 * SLD,
        (long)Nn * Cc, 72, 0);

    // x2 = x1 + o @ cproj_w.T + b
    mma_gemm<true,2,true,false><<<dim3(9, 64), 256, MM_SMEM>>>(
        p_shh, p_w + W_CPR, cproj_b, p_x1, nullptr, p_x2, nullptr,
        ROWS, Cc, Cc, Cc, Cc, Cc, Cc,
        1, 0, 0, 0, 0, 0, 0, 0);

    ln_mod_kernel<<<ROWS, 256>>>(p_x2, p_shh, 4, 3);

    // h = silu(xmod2 @ inv_w.T + b)
    mma_gemm<true,1,false,true><<<dim3(45, 64), 256, MM_SMEM>>>(
        p_shh, p_w + W_INV, inv_b, nullptr, nullptr, nullptr, p_bigh,
        ROWS, 2 * HIDd, 2 * HIDd, Cc, Cc, Cc, 2 * HIDd,
        1, 0, 0, 0, 0, 0, 0, 0);

    dwglu_kernel<<<dim3(HIDd / 64, 64, Bb), 256>>>(p_bigh, dw_w, dw_b, p_glu);

    // out = x2 + g_m * (glu @ pw_w.T)
    mma_gemm<false,3,true,false><<<dim3(9, 64), 256, MM_SMEM>>>(
        p_glu, p_w + W_PW, nullptr, p_x2, p_m + 5 * Cc, out, nullptr,
        ROWS, Cc, Cc, HIDd, HIDd, HIDd, Cc,
        1, 0, 0, 0, 0, 0, 0, 6 * Cc);
}

// round 9
// speedup vs baseline: 2.6351x; 1.0017x over previous
#include <cuda_runtime.h>
#include <cuda_fp16.h>
#include <cstdint>
#include <math.h>

// ---------------------------------------------------------------------------
// SanaBlock: LN+adaLN -> LiteLA -> cross-attn -> GLUMBConv, B=2,N=4096,C=1152
// R9: 3-stage cp.async pipeline, ONE __syncthreads per K-tile (was 2-stage/2).
// ---------------------------------------------------------------------------
constexpr int Bb   = 2;
constexpr int Nn   = 4096;
constexpr int Cc   = 1152;
constexpr int Mkv  = 300;
constexpr int HIDd = 2880;
constexpr int HLA  = 36;
constexpr int HX   = 16;
constexpr int SLD  = 320;

__device__ __align__(256) float  g_big [47185920];
__device__ __align__(256) __half g_shh [(size_t)Bb * Nn * Cc];
__device__ __align__(256) float  g_x1  [(size_t)Bb * Nn * Cc];
__device__ __align__(256) __half g_x1h [(size_t)Bb * Nn * Cc];
__device__ __align__(256) float  g_x2  [(size_t)Bb * Nn * Cc];
__device__ __align__(256) __half g_glu [(size_t)Bb * Nn * HIDd];
__device__ __align__(256) __half g_kvb [(size_t)Bb * Mkv * 2 * Cc];
__device__ __align__(256) __half g_vt  [(size_t)Bb * HX * 72 * SLD];
__device__ __align__(256) __half g_prb [(size_t)Bb * HX * Nn * SLD];
__device__ __align__(256) __half g_yh  [(size_t)Bb * Mkv * Cc];
__device__ __align__(256) __half g_wts [20570112];
__device__ float g_vk [Bb * HLA * 33 * 32];
__device__ float g_mb [Bb * 6 * Cc];

constexpr size_t W_QKV = 0;
constexpr size_t W_APR = W_QKV + (size_t)3 * Cc * Cc;
constexpr size_t W_Q   = W_APR + (size_t)Cc * Cc;
constexpr size_t W_KV  = W_Q   + (size_t)Cc * Cc;
constexpr size_t W_CPR = W_KV  + (size_t)2 * Cc * Cc;
constexpr size_t W_INV = W_CPR + (size_t)Cc * Cc;
constexpr size_t W_PW  = W_INV + (size_t)2 * HIDd * Cc;

// ---------------------------------------------------------------------------
// helpers
// ---------------------------------------------------------------------------
__device__ __forceinline__ uint32_t smem_u32(const void* p){
    uint32_t a;
    asm("{ .reg .u64 t; cvta.to.shared.u64 t, %1; cvt.u32.u64 %0, t; }"
        : "=r"(a) : "l"(p));
    return a;
}
__device__ __forceinline__ void cp16(uint32_t dst, const void* src, int srcsz){
    asm volatile("cp.async.cg.shared.global [%0], [%1], 16, %2;"
        ::"r"(dst),"l"(src),"r"(srcsz):"memory");
}
#define CP_COMMIT() asm volatile("cp.async.commit_group;":::"memory")
#define CP_WAIT1()  asm volatile("cp.async.wait_group 1;":::"memory")

__device__ __forceinline__ void mma16(float* d, const uint32_t* a, const uint32_t* b){
    asm volatile("mma.sync.aligned.m16n8k16.row.col.f32.f16.f16.f32 "
        "{%0,%1,%2,%3},{%4,%5,%6,%7},{%8,%9},{%0,%1,%2,%3};"
        : "+f"(d[0]),"+f"(d[1]),"+f"(d[2]),"+f"(d[3])
        : "r"(a[0]),"r"(a[1]),"r"(a[2]),"r"(a[3]),"r"(b[0]),"r"(b[1]));
}
__device__ __forceinline__ void ldsm4(uint32_t& r0, uint32_t& r1, uint32_t& r2,
                                      uint32_t& r3, uint32_t addr){
    asm volatile("ldmatrix.sync.aligned.m8n8.x4.shared.b16 {%0,%1,%2,%3}, [%4];"
        : "=r"(r0),"=r"(r1),"=r"(r2),"=r"(r3) : "r"(addr));
}

// ---------------------------------------------------------------------------
// fp16 mma NT GEMM: O[M,N] = epi(A[M,K]*B[NloadB,K]^T + bias), fp32 accum.
// CTA 128x128x32, 8 warps (4M x 2N), warp tile 32x64, 3-stage cp.async,
// ldmatrix.x4 fragment loads, single barrier per K-tile.
// ---------------------------------------------------------------------------
constexpr int LDPH    = 40;
constexpr int TILE_H  = 128 * LDPH;
constexpr int STAGE_H = 2 * TILE_H;
constexpr int MM_SMEM = 3 * STAGE_H * 2;  // 61440 bytes, needs attribute

template<bool BIAS, int EPI, bool WF, bool WH>
__global__ __launch_bounds__(256, 2)
void mma_gemm(const __half* A, const __half* Bw, const float* bias,
              const float* res, const float* gate,
              float* Of, __half* Oh,
              int Mrows, int NloadB, int Nstore, int K,
              int lda, int ldb, int ldo,
              int HB, long aBs, long aHs, long bBs, long bHs, long oBs, long oHs,
              int gateStride)
{
    extern __shared__ __half smh[];
    uint32_t sbase = smem_u32(smh);
    int tid = threadIdx.x, wid = tid >> 5, lane = tid & 31;
    int warpM = wid >> 1, warpN = wid & 1;
    int m0 = blockIdx.y * 128, n0 = blockIdx.x * 128;

    if (gridDim.z > 1) {
        int z = blockIdx.z;
        int bI = z / HB, hI = z % HB;
        A  += bI * aBs + hI * aHs;
        Bw += bI * bBs + hI * bHs;
        if (WF) Of += bI * oBs + hI * oHs;
        if (WH) Oh += bI * oBs + hI * oHs;
    }

    const int T = (K + 31) >> 5;

    auto load_tile = [&](int t, int buf) {
        uint32_t base = sbase + (uint32_t)buf * STAGE_H * 2;
        int k0 = t << 5;
        #pragma unroll
        for (int i = 0; i < 2; i++) {
            int c = tid + (i << 8);
            int row = c >> 2, ch = c & 3;
            int gk = k0 + ch * 8;
            uint32_t dst = base + (uint32_t)(row * LDPH * 2 + ch * 16);
            const __half* ga = A + (size_t)(m0 + row) * lda + gk;
            cp16(dst, ga, ((m0 + row) < Mrows && gk < K) ? 16 : 0);
            uint32_t dstB = dst + TILE_H * 2;
            const __half* gb = Bw + (size_t)(n0 + row) * ldb + gk;
            cp16(dstB, gb, ((n0 + row) < NloadB && gk < K) ? 16 : 0);
        }
    };

    float acc[2][8][4];
    #pragma unroll
    for (int mt = 0; mt < 2; mt++)
        #pragma unroll
        for (int nt = 0; nt < 8; nt++)
            #pragma unroll
            for (int q = 0; q < 4; q++) acc[mt][nt][q] = 0.f;

    // preload stages 0,1
    load_tile(0, 0); CP_COMMIT();
    load_tile(1, 1); CP_COMMIT();

    int rowA = warpM * 32 + (lane & 15);
    int colA = (lane >> 4) << 3;
    int rowB = warpN * 64 + (lane & 7) + ((lane >> 4) << 3);
    int colB = ((lane >> 3) & 1) << 3;

    for (int t = 0; t < T; t++) {
        int buf = t % 3;
        CP_WAIT1();          // tile t resident (pending: t+1's group)
        __syncthreads();     // stage (t+2)%3 == (t-1)%3 fully consumed
        if (t + 2 < T) load_tile(t + 2, (t + 2) % 3);
        CP_COMMIT();         // uniform one group per iteration

        uint32_t sA = sbase + (uint32_t)buf * STAGE_H * 2;
        uint32_t sB = sA + TILE_H * 2;

        #pragma unroll
        for (int kk = 0; kk < 2; kk++) {
            uint32_t af[2][4];
            #pragma unroll
            for (int mt = 0; mt < 2; mt++) {
                uint32_t addr = sA + (uint32_t)(((rowA + mt * 16) * LDPH)
                                                + colA + kk * 16) * 2;
                ldsm4(af[mt][0], af[mt][1], af[mt][2], af[mt][3], addr);
            }
            uint32_t bf[8][2];
            #pragma unroll
            for (int ntp = 0; ntp < 4; ntp++) {
                uint32_t addr = sB + (uint32_t)(((rowB + ntp * 16) * LDPH)
                                                + colB + kk * 16) * 2;
                ldsm4(bf[2 * ntp][0], bf[2 * ntp][1],
                      bf[2 * ntp + 1][0], bf[2 * ntp + 1][1], addr);
            }
            #pragma unroll
            for (int mt = 0; mt < 2; mt++)
                #pragma unroll
                for (int nt = 0; nt < 8; nt++)
                    mma16(acc[mt][nt], af[mt], bf[nt]);
        }
        // no trailing barrier: next iteration's top barrier protects reuse
    }

    #pragma unroll
    for (int mt = 0; mt < 2; mt++) {
        #pragma unroll
        for (int half_ = 0; half_ < 2; half_++) {
            int row = m0 + warpM * 32 + mt * 16 + (lane >> 2) + half_ * 8;
            if (row >= Mrows) continue;
            int bI = (row >= Nn) ? 1 : 0;
            #pragma unroll
            for (int nt = 0; nt < 8; nt++) {
                int col = n0 + warpN * 64 + nt * 8 + (lane & 3) * 2;
                if (col >= Nstore) continue;
                float v0 = acc[mt][nt][half_ * 2];
                float v1 = acc[mt][nt][half_ * 2 + 1];
                if (BIAS) { v0 += bias[col]; v1 += bias[col + 1]; }
                if (EPI == 1) {
                    v0 = v0 / (1.f + __expf(-v0));
                    v1 = v1 / (1.f + __expf(-v1));
                }
                if (EPI == 2) {
                    v0 += res[(size_t)row * ldo + col];
                    v1 += res[(size_t)row * ldo + col + 1];
                }
                if (EPI == 3) {
                    v0 = res[(size_t)row * ldo + col]     + gate[bI * gateStride + col]     * v0;
                    v1 = res[(size_t)row * ldo + col + 1] + gate[bI * gateStride + col + 1] * v1;
                }
                if (WF) *(float2*)&Of[(size_t)row * ldo + col] = make_float2(v0, v1);
                if (WH) *(__half2*)&Oh[(size_t)row * ldo + col] = __floats2half2_rn(v0, v1);
            }
        }
    }
}

// ---------------------------------------------------------------------------
// m = sst + t
// ---------------------------------------------------------------------------
__global__ void mod_kernel(const float* __restrict__ t, const float* __restrict__ sst)
{
    int i = blockIdx.x * 256 + threadIdx.x;
    if (i < Bb * 6 * Cc) g_mb[i] = sst[i % (6 * Cc)] + t[i];
}

// ---------------------------------------------------------------------------
// all weight (and y) fp16 conversion in ONE launch
// ---------------------------------------------------------------------------
__global__ void round_all_kernel(const float* qkv_w, const float* aproj_w,
                                 const float* q_w, const float* kv_w,
                                 const float* cproj_w, const float* inv_w,
                                 const float* pw_w, const float* y)
{
    long i = (long)blockIdx.x * 256 + threadIdx.x;
    long n;
    n = (long)3 * Cc * Cc;   if (i < n) { g_wts[W_QKV + i] = __float2half_rn(qkv_w[i]);   return; } i -= n;
    n = (long)Cc * Cc;       if (i < n) { g_wts[W_APR + i] = __float2half_rn(aproj_w[i]); return; } i -= n;
    n = (long)Cc * Cc;       if (i < n) { g_wts[W_Q   + i] = __float2half_rn(q_w[i]);     return; } i -= n;
    n = (long)2 * Cc * Cc;   if (i < n) { g_wts[W_KV  + i] = __float2half_rn(kv_w[i]);    return; } i -= n;
    n = (long)Cc * Cc;       if (i < n) { g_wts[W_CPR + i] = __float2half_rn(cproj_w[i]); return; } i -= n;
    n = (long)2 * HIDd * Cc; if (i < n) { g_wts[W_INV + i] = __float2half_rn(inv_w[i]);   return; } i -= n;
    n = (long)Cc * HIDd;     if (i < n) { g_wts[W_PW  + i] = __float2half_rn(pw_w[i]);    return; } i -= n;
    n = (long)Bb * Mkv * Cc; if (i < n) { g_yh[i] = __float2half_rn(y[i]); }
}

// ---------------------------------------------------------------------------
// LayerNorm + adaLN modulate (writes half)
// ---------------------------------------------------------------------------
__global__ __launch_bounds__(256)
void ln_mod_kernel(const float* __restrict__ in, __half* __restrict__ out,
                   int scRow, int shRow)
{
    int row = blockIdx.x;
    int b   = row / Nn;
    const float* xr = in + (size_t)row * Cc;

    float s = 0.f, s2 = 0.f;
    for (int c = threadIdx.x; c < Cc; c += blockDim.x) {
        float v = xr[c]; s += v; s2 += v * v;
    }
    __shared__ float sh1[8], sh2[8];
    int lane = threadIdx.x & 31, wid = threadIdx.x >> 5;
    #pragma unroll
    for (int o = 16; o > 0; o >>= 1) {
        s  += __shfl_down_sync(0xffffffffu, s,  o);
        s2 += __shfl_down_sync(0xffffffffu, s2, o);
    }
    if (lane == 0) { sh1[wid] = s; sh2[wid] = s2; }
    __syncthreads();
    if (wid == 0) {
        s  = (lane < 8) ? sh1[lane] : 0.f;
        s2 = (lane < 8) ? sh2[lane] : 0.f;
        #pragma unroll
        for (int o = 4; o > 0; o >>= 1) {
            s  += __shfl_down_sync(0xffffffffu, s,  o);
            s2 += __shfl_down_sync(0xffffffffu, s2, o);
        }
        if (lane == 0) { sh1[0] = s; sh2[0] = s2; }
    }
    __syncthreads();
    float mu   = sh1[0] * (1.f / Cc);
    float var  = sh2[0] * (1.f / Cc) - mu * mu;
    float rstd = rsqrtf(var + 1e-6f);
    const float* mbp = g_mb + (size_t)b * 6 * Cc;
    for (int c = threadIdx.x; c < Cc; c += blockDim.x) {
        float sc = mbp[scRow * Cc + c];
        float sv = mbp[shRow * Cc + c];
        out[(size_t)row * Cc + c] =
            __float2half_rn((xr[c] - mu) * rstd * (1.f + sc) + sv);
    }
}

// ---------------------------------------------------------------------------
// LiteLA vk accumulation + epilogue
// ---------------------------------------------------------------------------
__global__ void zero_vk_kernel()
{
    int i = blockIdx.x * 256 + threadIdx.x;
    if (i < Bb * HLA * 33 * 32) g_vk[i] = 0.f;
}

__global__ __launch_bounds__(256)
void vk_kernel(const __half* __restrict__ qkv, float* __restrict__ vkout)
{
    int bh = blockIdx.x;
    int b  = bh / HLA, h = bh % HLA;
    int split = blockIdx.y;
    __shared__ float ks[32][33];
    __shared__ float vs[32][33];
    float acc[5] = {0.f, 0.f, 0.f, 0.f, 0.f};
    int tid = threadIdx.x;
    const size_t base = (size_t)b * Nn * 3 * Cc;
    int nStart = split * (Nn / 16);
    for (int n0 = nStart; n0 < nStart + Nn / 16; n0 += 32) {
        for (int li = tid; li < 1024; li += 256) {
            int nn = li >> 5, dc = li & 31;
            size_t off = base + (size_t)(n0 + nn) * 3 * Cc + h * 32 + dc;
            ks[nn][dc] = fmaxf(__half2float(qkv[off + Cc]), 0.f);
            vs[nn][dc] = __half2float(qkv[off + 2 * Cc]);
        }
        __syncthreads();
        #pragma unroll
        for (int u = 0; u < 5; u++) {
            int idx = tid + 256 * u;
            if (idx < 1056) {
                int e = idx >> 5, dc = idx & 31;
                float a = acc[u];
                if (e == 32) {
                    #pragma unroll
                    for (int nn = 0; nn < 32; nn++) a += ks[nn][dc];
                } else {
                    #pragma unroll
                    for (int nn = 0; nn < 32; nn++) a += vs[nn][e] * ks[nn][dc];
                }
                acc[u] = a;
            }
        }
        __syncthreads();
    }
    #pragma unroll
    for (int u = 0; u < 5; u++) {
        int idx = tid + 256 * u;
        if (idx < 1056) {
            int e = idx >> 5, dc = idx & 31;
            atomicAdd(&vkout[((size_t)bh * 33 + e) * 32 + dc], acc[u]);
        }
    }
}

__global__ __launch_bounds__(256)
void la_out_kernel(const __half* __restrict__ qkv, const float* __restrict__ vk,
                   __half* __restrict__ out)
{
    int row = blockIdx.x;
    int b   = row / Nn;
    __shared__ float q[Cc];
    __shared__ float den[HLA];
    const __half* qr = qkv + (size_t)row * 3 * Cc;
    for (int c = threadIdx.x; c < Cc; c += blockDim.x)
        q[c] = fmaxf(__half2float(qr[c]), 0.f);
    __syncthreads();
    if (threadIdx.x < HLA) {
        int h = threadIdx.x;
        const float* vkh = vk + ((size_t)(b * HLA + h) * 33 + 32) * 32;
        float s = 0.f;
        #pragma unroll
        for (int d = 0; d < 32; d++) s += vkh[d] * q[h * 32 + d];
        den[h] = s + 1e-8f;
    }
    __syncthreads();
    for (int c = threadIdx.x; c < Cc; c += blockDim.x) {
        int h = c >> 5, dd = c & 31;
        const float* vkr = vk + ((size_t)(b * HLA + h) * 33 + dd) * 32;
        const float* qh  = q + h * 32;
        float s = 0.f;
        #pragma unroll
        for (int d = 0; d < 32; d++) s += vkr[d] * qh[d];
        out[(size_t)row * Cc + c] = __float2half_rn(s / den[h]);
    }
}

// ---------------------------------------------------------------------------
// v^T materialization (half), m padded to SLD with zeros
// ---------------------------------------------------------------------------
__global__ void vt_kernel(const __half* __restrict__ kv, __half* __restrict__ vt)
{
    long idx = (long)blockIdx.x * 256 + threadIdx.x;
    if (idx >= (long)Bb * HX * 72 * SLD) return;
    int  m = (int)(idx % SLD);
    long r = idx / SLD;
    int  d = (int)(r % 72);
    int  z = (int)(r / 72);
    int  b = z / HX, h = z % HX;
    __half v = __float2half_rn(0.f);
    if (m < Mkv) v = kv[((size_t)b * Mkv + m) * 2 * Cc + Cc + h * 72 + d];
    vt[idx] = v;
}

// ---------------------------------------------------------------------------
// Cross-attn softmax: float scores -> half probs (pad cols -> 0)
// ---------------------------------------------------------------------------
__global__ __launch_bounds__(256)
void softmax_kernel(const float* __restrict__ s, __half* __restrict__ p, long rows)
{
    long gw  = ((long)blockIdx.x * blockDim.x + threadIdx.x) >> 5;
    int lane = threadIdx.x & 31;
    if (gw >= rows) return;
    const float* r = s + gw * SLD;
    __half* rp = p + gw * SLD;
    const float scale = 0.11785113019775793f;
    float v[10];
    float mx = -1e30f;
    #pragma unroll
    for (int i = 0; i < 10; i++) {
        int m = lane + 32 * i;
        v[i] = (m < Mkv) ? r[m] * scale : -1e30f;
        mx = fmaxf(mx, v[i]);
    }
    #pragma unroll
    for (int o = 16; o > 0; o >>= 1) mx = fmaxf(mx, __shfl_xor_sync(0xffffffffu, mx, o));
    float sum = 0.f;
    #pragma unroll
    for (int i = 0; i < 10; i++) { v[i] = __expf(v[i] - mx); sum += v[i]; }
    #pragma unroll
    for (int o = 16; o > 0; o >>= 1) sum += __shfl_xor_sync(0xffffffffu, sum, o);
    float inv = 1.f / sum;
    #pragma unroll
    for (int i = 0; i < 10; i++) {
        int m = lane + 32 * i;
        rp[m] = __float2half_rn((m < Mkv) ? v[i] * inv : 0.f);
    }
}

// ---------------------------------------------------------------------------
// depthwise 3x3 + bias + GLU, smem-tiled, half in / half out
// ---------------------------------------------------------------------------
__global__ __launch_bounds__(256)
void dwglu_kernel(const __half* __restrict__ h, const float* __restrict__ dww,
                  const float* __restrict__ dwb, __half* __restrict__ out)
{
    __shared__ float sa[100][64];
    __shared__ float sg[100][64];
    int tid = threadIdx.x;
    int c0  = blockIdx.x * 64;
    int y0  = (blockIdx.y >> 3) * 8, x0 = (blockIdx.y & 7) * 8;
    int b   = blockIdx.z;

    int ch = tid & 63;
    float wA[9], wG[9];
    #pragma unroll
    for (int tp = 0; tp < 9; tp++) {
        wA[tp] = dww[(size_t)(c0 + ch) * 9 + tp];
        wG[tp] = dww[(size_t)(c0 + ch + HIDd) * 9 + tp];
    }
    float bA = dwb[c0 + ch], bG = dwb[c0 + ch + HIDd];

    for (int li = tid; li < 1600; li += 256) {
        int pos = li >> 4, q = li & 15;
        int py = pos / 10, px = pos % 10;
        int yy = y0 + py - 1, xx = x0 + px - 1;
        float4 va = make_float4(0.f, 0.f, 0.f, 0.f), vg = va;
        if (yy >= 0 && yy < 64 && xx >= 0 && xx < 64) {
            const __half* src = h + ((size_t)b * Nn + yy * 64 + xx) * (2 * HIDd) + c0 + q * 4;
            float2 a01 = __half22float2(*(const __half2*)src);
            float2 a23 = __half22float2(*(const __half2*)(src + 2));
            float2 g01 = __half22float2(*(const __half2*)(src + HIDd));
            float2 g23 = __half22float2(*(const __half2*)(src + HIDd + 2));
            va = make_float4(a01.x, a01.y, a23.x, a23.y);
            vg = make_float4(g01.x, g01.y, g23.x, g23.y);
        }
        *(float4*)&sa[pos][q * 4] = va;
        *(float4*)&sg[pos][q * 4] = vg;
    }
    __syncthreads();

    #pragma unroll
    for (int i = 0; i < 16; i++) {
        int pos = (tid >> 6) + i * 4;
        int py = pos >> 3, px = pos & 7;
        int s0 = (py + 1) * 10 + (px + 1);
        float accA = bA, accG = bG;
        #pragma unroll
        for (int dy = -1; dy <= 1; dy++)
            #pragma unroll
            for (int dx = -1; dx <= 1; dx++) {
                int s = s0 + dy * 10 + dx;
                int tp = (dy + 1) * 3 + (dx + 1);
                accA = fmaf(sa[s][ch], wA[tp], accA);
                accG = fmaf(sg[s][ch], wG[tp], accG);
            }
        int n = (y0 + py) * 64 + (x0 + px);
        out[((size_t)b * Nn + n) * HIDd + c0 + ch] =
            __float2half_rn(accA * (accG / (1.f + __expf(-accG))));
    }
}

// ---------------------------------------------------------------------------
extern "C" void kernel_launch(void* const* d_in, const int* /*in_sizes*/, int /*n_in*/,
                              void* d_out, int /*out_size*/)
{
    const float* x       = (const float*)d_in[0];
    const float* y       = (const float*)d_in[1];
    const float* t       = (const float*)d_in[2];
    const float* sst     = (const float*)d_in[3];
    const float* qkv_w   = (const float*)d_in[4];
    const float* aproj_w = (const float*)d_in[5];
    const float* aproj_b = (const float*)d_in[6];
    const float* q_w     = (const float*)d_in[7];
    const float* q_b     = (const float*)d_in[8];
    const float* kv_w    = (const float*)d_in[9];
    const float* kv_b    = (const float*)d_in[10];
    const float* cproj_w = (const float*)d_in[11];
    const float* cproj_b = (const float*)d_in[12];
    const float* inv_w   = (const float*)d_in[13];
    const float* inv_b   = (const float*)d_in[14];
    const float* dw_w    = (const float*)d_in[15];
    const float* dw_b    = (const float*)d_in[16];
    const float* pw_w    = (const float*)d_in[17];
    float* out = (float*)d_out;

    float  *p_big, *p_x1, *p_x2, *p_vk, *p_m;
    __half *p_shh, *p_x1h, *p_glu, *p_kvh, *p_vt, *p_prb, *p_yh, *p_w;
    cudaGetSymbolAddress((void**)&p_big, g_big);
    cudaGetSymbolAddress((void**)&p_shh, g_shh);
    cudaGetSymbolAddress((void**)&p_x1,  g_x1);
    cudaGetSymbolAddress((void**)&p_x1h, g_x1h);
    cudaGetSymbolAddress((void**)&p_x2,  g_x2);
    cudaGetSymbolAddress((void**)&p_glu, g_glu);
    cudaGetSymbolAddress((void**)&p_kvh, g_kvb);
    cudaGetSymbolAddress((void**)&p_vt,  g_vt);
    cudaGetSymbolAddress((void**)&p_prb, g_prb);
    cudaGetSymbolAddress((void**)&p_yh,  g_yh);
    cudaGetSymbolAddress((void**)&p_vk,  g_vk);
    cudaGetSymbolAddress((void**)&p_m,   g_mb);
    cudaGetSymbolAddress((void**)&p_w,   g_wts);

    __half* p_bigh = (__half*)p_big;

    cudaFuncSetAttribute(mma_gemm<false,0,false,true>, cudaFuncAttributeMaxDynamicSharedMemorySize, MM_SMEM);
    cudaFuncSetAttribute(mma_gemm<true, 3,true, true>, cudaFuncAttributeMaxDynamicSharedMemorySize, MM_SMEM);
    cudaFuncSetAttribute(mma_gemm<true, 0,false,true>, cudaFuncAttributeMaxDynamicSharedMemorySize, MM_SMEM);
    cudaFuncSetAttribute(mma_gemm<false,0,true,false>, cudaFuncAttributeMaxDynamicSharedMemorySize, MM_SMEM);
    cudaFuncSetAttribute(mma_gemm<true, 2,true,false>, cudaFuncAttributeMaxDynamicSharedMemorySize, MM_SMEM);
    cudaFuncSetAttribute(mma_gemm<true, 1,false,true>, cudaFuncAttributeMaxDynamicSharedMemorySize, MM_SMEM);
    cudaFuncSetAttribute(mma_gemm<false,3,true,false>, cudaFuncAttributeMaxDynamicSharedMemorySize, MM_SMEM);

    const int ROWS = Bb * Nn;
    const long RN_TOTAL = (long)3*Cc*Cc + 5L*Cc*Cc + 2L*HIDd*Cc + (long)Cc*HIDd
                        + (long)Bb*Mkv*Cc;

    mod_kernel<<<(Bb * 6 * Cc + 255) / 256, 256>>>(t, sst);
    round_all_kernel<<<(int)((RN_TOTAL + 255) / 256), 256>>>(
        qkv_w, aproj_w, q_w, kv_w, cproj_w, inv_w, pw_w, y);
    ln_mod_kernel<<<ROWS, 256>>>(x, p_shh, 1, 0);

    // qkv = xmod1 @ qkv_w.T  (half out)
    mma_gemm<false,0,false,true><<<dim3(27, 64), 256, MM_SMEM>>>(
        p_shh, p_w + W_QKV, nullptr, nullptr, nullptr, nullptr, p_bigh,
        ROWS, 3 * Cc, 3 * Cc, Cc, Cc, Cc, 3 * Cc,
        1, 0, 0, 0, 0, 0, 0, 0);

    zero_vk_kernel<<<(Bb * HLA * 33 * 32 + 255) / 256, 256>>>();
    vk_kernel<<<dim3(Bb * HLA, 16), 256>>>(p_bigh, p_vk);
    la_out_kernel<<<ROWS, 256>>>(p_bigh, p_vk, p_shh);

    // x1 = x + g_a * (la @ aproj_w.T + b)
    mma_gemm<true,3,true,true><<<dim3(9, 64), 256, MM_SMEM>>>(
        p_shh, p_w + W_APR, aproj_b, x, p_m + 2 * Cc, p_x1, p_x1h,
        ROWS, Cc, Cc, Cc, Cc, Cc, Cc,
        1, 0, 0, 0, 0, 0, 0, 6 * Cc);

    // q = x1 @ q_w.T + q_b
    mma_gemm<true,0,false,true><<<dim3(9, 64), 256, MM_SMEM>>>(
        p_x1h, p_w + W_Q, q_b, nullptr, nullptr, nullptr, p_shh,
        ROWS, Cc, Cc, Cc, Cc, Cc, Cc,
        1, 0, 0, 0, 0, 0, 0, 0);

    // kv = y @ kv_w.T + kv_b
    mma_gemm<true,0,false,true><<<dim3(18, 5), 256, MM_SMEM>>>(
        p_yh, p_w + W_KV, kv_b, nullptr, nullptr, nullptr, p_kvh,
        Bb * Mkv, 2 * Cc, 2 * Cc, Cc, Cc, Cc, 2 * Cc,
        1, 0, 0, 0, 0, 0, 0, 0);

    vt_kernel<<<(int)(((long)Bb * HX * 72 * SLD + 255) / 256), 256>>>(p_kvh, p_vt);

    // scores[z] = q_h @ k_h.T  (float out)
    mma_gemm<false,0,true,false><<<dim3(3, 32, Bb * HX), 256, MM_SMEM>>>(
        p_shh, p_kvh, nullptr, nullptr, nullptr, p_big, nullptr,
        Nn, Mkv, SLD, 72, Cc, 2 * Cc, SLD,
        HX, (long)Nn * Cc, 72, (long)Mkv * 2 * Cc, 72,
        (long)HX * Nn * SLD, (long)Nn * SLD, 0);

    softmax_kernel<<<(Bb * HX * Nn) / 8, 256>>>(p_big, p_prb, (long)Bb * HX * Nn);

    // o[z] = probs @ v^T  (half out)
    mma_gemm<false,0,false,true><<<dim3(1, 32, Bb * HX), 256, MM_SMEM>>>(
        p_prb, p_vt, nullptr, nullptr, nullptr, nullptr, p_shh,
        Nn, 72, 72, SLD, SLD, SLD, Cc,
        HX, (long)HX * Nn * SLD, (long)Nn * SLD, (long)72 * SLD * HX, (long)72 * SLD,
        (long)Nn * Cc, 72, 0);

    // x2 = x1 + o @ cproj_w.T + b
    mma_gemm<true,2,true,false><<<dim3(9, 64), 256, MM_SMEM>>>(
        p_shh, p_w + W_CPR, cproj_b, p_x1, nullptr, p_x2, nullptr,
        ROWS, Cc, Cc, Cc, Cc, Cc, Cc,
        1, 0, 0, 0, 0, 0, 0, 0);

    ln_mod_kernel<<<ROWS, 256>>>(p_x2, p_shh, 4, 3);

    // h = silu(xmod2 @ inv_w.T + b)
    mma_gemm<true,1,false,true><<<dim3(45, 64), 256, MM_SMEM>>>(
        p_shh, p_w + W_INV, inv_b, nullptr, nullptr, nullptr, p_bigh,
        ROWS, 2 * HIDd, 2 * HIDd, Cc, Cc, Cc, 2 * HIDd,
        1, 0, 0, 0, 0, 0, 0, 0);

    dwglu_kernel<<<dim3(HIDd / 64, 64, Bb), 256>>>(p_bigh, dw_w, dw_b, p_glu);

    // out = x2 + g_m * (glu @ pw_w.T)
    mma_gemm<false,3,true,false><<<dim3(9, 64), 256, MM_SMEM>>>(
        p_glu, p_w + W_PW, nullptr, p_x2, p_m + 5 * Cc, out, nullptr,
        ROWS, Cc, Cc, HIDd, HIDd, HIDd, Cc,
        1, 0, 0, 0, 0, 0, 0, 6 * Cc);
}

// round 12
// speedup vs baseline: 2.6353x; 1.0001x over previous
#include <cuda_runtime.h>
#include <cuda_fp16.h>
#include <cstdint>
#include <math.h>

// ---------------------------------------------------------------------------
// SanaBlock: LN+adaLN -> LiteLA -> cross-attn -> GLUMBConv, B=2,N=4096,C=1152
// R11: R10 (MUFU-free exp/sigmoid) with FIXED reciprocal seed for z in [1,2].
// ---------------------------------------------------------------------------
constexpr int Bb   = 2;
constexpr int Nn   = 4096;
constexpr int Cc   = 1152;
constexpr int Mkv  = 300;
constexpr int HIDd = 2880;
constexpr int HLA  = 36;
constexpr int HX   = 16;
constexpr int SLD  = 320;

__device__ __align__(256) float  g_big [47185920];
__device__ __align__(256) __half g_shh [(size_t)Bb * Nn * Cc];
__device__ __align__(256) float  g_x1  [(size_t)Bb * Nn * Cc];
__device__ __align__(256) __half g_x1h [(size_t)Bb * Nn * Cc];
__device__ __align__(256) float  g_x2  [(size_t)Bb * Nn * Cc];
__device__ __align__(256) __half g_glu [(size_t)Bb * Nn * HIDd];
__device__ __align__(256) __half g_kvb [(size_t)Bb * Mkv * 2 * Cc];
__device__ __align__(256) __half g_vt  [(size_t)Bb * HX * 72 * SLD];
__device__ __align__(256) __half g_prb [(size_t)Bb * HX * Nn * SLD];
__device__ __align__(256) __half g_yh  [(size_t)Bb * Mkv * Cc];
__device__ __align__(256) __half g_wts [20570112];
__device__ float g_vk [Bb * HLA * 33 * 32];
__device__ float g_mb [Bb * 6 * Cc];

constexpr size_t W_QKV = 0;
constexpr size_t W_APR = W_QKV + (size_t)3 * Cc * Cc;
constexpr size_t W_Q   = W_APR + (size_t)Cc * Cc;
constexpr size_t W_KV  = W_Q   + (size_t)Cc * Cc;
constexpr size_t W_CPR = W_KV  + (size_t)2 * Cc * Cc;
constexpr size_t W_INV = W_CPR + (size_t)Cc * Cc;
constexpr size_t W_PW  = W_INV + (size_t)2 * HIDd * Cc;

// ---------------------------------------------------------------------------
// FMA-only transcendentals (no MUFU)
// ---------------------------------------------------------------------------
__device__ __forceinline__ float fexp(float t){
    t = fminf(fmaxf(t, -87.0f), 87.0f);
    float z = t * 1.4426950408889634f;
    float n = floorf(z);
    float f = z - n;                       // [0,1)
    float p = 1.5403530e-4f;               // Taylor of 2^f = e^{f ln2}
    p = fmaf(p, f, 1.3333558e-3f);
    p = fmaf(p, f, 9.6181291e-3f);
    p = fmaf(p, f, 5.5504109e-2f);
    p = fmaf(p, f, 2.4022651e-1f);
    p = fmaf(p, f, 6.9314718e-1f);
    p = fmaf(p, f, 1.0f);
    int i = (int)n;
    return p * __int_as_float((i + 127) << 23);
}
__device__ __forceinline__ float fsigmoid(float x){
    float u = fexp(-fabsf(x));             // (0,1]
    float z = 1.0f + u;                    // [1,2]
    // reciprocal seed valid on [1,2]: y0 = 1.4117647 - 0.47058824*z
    float y = fmaf(-0.47058824f, z, 1.4117647f);
    y = y * fmaf(-z, y, 2.0f);             // Newton 1
    y = y * fmaf(-z, y, 2.0f);             // Newton 2 (~1e-5)
    return (x >= 0.f) ? y : 1.0f - y;
}
__device__ __forceinline__ float fsilu(float x){ return x * fsigmoid(x); }

// ---------------------------------------------------------------------------
// helpers
// ---------------------------------------------------------------------------
__device__ __forceinline__ uint32_t smem_u32(const void* p){
    uint32_t a;
    asm("{ .reg .u64 t; cvta.to.shared.u64 t, %1; cvt.u32.u64 %0, t; }"
        : "=r"(a) : "l"(p));
    return a;
}
__device__ __forceinline__ void cp16(uint32_t dst, const void* src, int srcsz){
    asm volatile("cp.async.cg.shared.global [%0], [%1], 16, %2;"
        ::"r"(dst),"l"(src),"r"(srcsz):"memory");
}
#define CP_COMMIT() asm volatile("cp.async.commit_group;":::"memory")
#define CP_WAIT1()  asm volatile("cp.async.wait_group 1;":::"memory")

__device__ __forceinline__ void mma16(float* d, const uint32_t* a, const uint32_t* b){
    asm volatile("mma.sync.aligned.m16n8k16.row.col.f32.f16.f16.f32 "
        "{%0,%1,%2,%3},{%4,%5,%6,%7},{%8,%9},{%0,%1,%2,%3};"
        : "+f"(d[0]),"+f"(d[1]),"+f"(d[2]),"+f"(d[3])
        : "r"(a[0]),"r"(a[1]),"r"(a[2]),"r"(a[3]),"r"(b[0]),"r"(b[1]));
}
__device__ __forceinline__ void ldsm4(uint32_t& r0, uint32_t& r1, uint32_t& r2,
                                      uint32_t& r3, uint32_t addr){
    asm volatile("ldmatrix.sync.aligned.m8n8.x4.shared.b16 {%0,%1,%2,%3}, [%4];"
        : "=r"(r0),"=r"(r1),"=r"(r2),"=r"(r3) : "r"(addr));
}

// ---------------------------------------------------------------------------
// fp16 mma NT GEMM (3-stage cp.async, 1 barrier per K-tile)
// ---------------------------------------------------------------------------
constexpr int LDPH    = 40;
constexpr int TILE_H  = 128 * LDPH;
constexpr int STAGE_H = 2 * TILE_H;
constexpr int MM_SMEM = 3 * STAGE_H * 2;  // 61440 bytes

template<bool BIAS, int EPI, bool WF, bool WH>
__global__ __launch_bounds__(256, 2)
void mma_gemm(const __half* A, const __half* Bw, const float* bias,
              const float* res, const float* gate,
              float* Of, __half* Oh,
              int Mrows, int NloadB, int Nstore, int K,
              int lda, int ldb, int ldo,
              int HB, long aBs, long aHs, long bBs, long bHs, long oBs, long oHs,
              int gateStride)
{
    extern __shared__ __half smh[];
    uint32_t sbase = smem_u32(smh);
    int tid = threadIdx.x, wid = tid >> 5, lane = tid & 31;
    int warpM = wid >> 1, warpN = wid & 1;
    int m0 = blockIdx.y * 128, n0 = blockIdx.x * 128;

    if (gridDim.z > 1) {
        int z = blockIdx.z;
        int bI = z / HB, hI = z % HB;
        A  += bI * aBs + hI * aHs;
        Bw += bI * bBs + hI * bHs;
        if (WF) Of += bI * oBs + hI * oHs;
        if (WH) Oh += bI * oBs + hI * oHs;
    }

    const int T = (K + 31) >> 5;

    auto load_tile = [&](int t, int buf) {
        uint32_t base = sbase + (uint32_t)buf * STAGE_H * 2;
        int k0 = t << 5;
        #pragma unroll
        for (int i = 0; i < 2; i++) {
            int c = tid + (i << 8);
            int row = c >> 2, ch = c & 3;
            int gk = k0 + ch * 8;
            uint32_t dst = base + (uint32_t)(row * LDPH * 2 + ch * 16);
            const __half* ga = A + (size_t)(m0 + row) * lda + gk;
            cp16(dst, ga, ((m0 + row) < Mrows && gk < K) ? 16 : 0);
            uint32_t dstB = dst + TILE_H * 2;
            const __half* gb = Bw + (size_t)(n0 + row) * ldb + gk;
            cp16(dstB, gb, ((n0 + row) < NloadB && gk < K) ? 16 : 0);
        }
    };

    float acc[2][8][4];
    #pragma unroll
    for (int mt = 0; mt < 2; mt++)
        #pragma unroll
        for (int nt = 0; nt < 8; nt++)
            #pragma unroll
            for (int q = 0; q < 4; q++) acc[mt][nt][q] = 0.f;

    load_tile(0, 0); CP_COMMIT();
    load_tile(1, 1); CP_COMMIT();

    int rowA = warpM * 32 + (lane & 15);
    int colA = (lane >> 4) << 3;
    int rowB = warpN * 64 + (lane & 7) + ((lane >> 4) << 3);
    int colB = ((lane >> 3) & 1) << 3;

    for (int t = 0; t < T; t++) {
        int buf = t % 3;
        CP_WAIT1();
        __syncthreads();
        if (t + 2 < T) load_tile(t + 2, (t + 2) % 3);
        CP_COMMIT();

        uint32_t sA = sbase + (uint32_t)buf * STAGE_H * 2;
        uint32_t sB = sA + TILE_H * 2;

        #pragma unroll
        for (int kk = 0; kk < 2; kk++) {
            uint32_t af[2][4];
            #pragma unroll
            for (int mt = 0; mt < 2; mt++) {
                uint32_t addr = sA + (uint32_t)(((rowA + mt * 16) * LDPH)
                                                + colA + kk * 16) * 2;
                ldsm4(af[mt][0], af[mt][1], af[mt][2], af[mt][3], addr);
            }
            uint32_t bf[8][2];
            #pragma unroll
            for (int ntp = 0; ntp < 4; ntp++) {
                uint32_t addr = sB + (uint32_t)(((rowB + ntp * 16) * LDPH)
                                                + colB + kk * 16) * 2;
                ldsm4(bf[2 * ntp][0], bf[2 * ntp][1],
                      bf[2 * ntp + 1][0], bf[2 * ntp + 1][1], addr);
            }
            #pragma unroll
            for (int mt = 0; mt < 2; mt++)
                #pragma unroll
                for (int nt = 0; nt < 8; nt++)
                    mma16(acc[mt][nt], af[mt], bf[nt]);
        }
    }

    #pragma unroll
    for (int mt = 0; mt < 2; mt++) {
        #pragma unroll
        for (int half_ = 0; half_ < 2; half_++) {
            int row = m0 + warpM * 32 + mt * 16 + (lane >> 2) + half_ * 8;
            if (row >= Mrows) continue;
            int bI = (row >= Nn) ? 1 : 0;
            #pragma unroll
            for (int nt = 0; nt < 8; nt++) {
                int col = n0 + warpN * 64 + nt * 8 + (lane & 3) * 2;
                if (col >= Nstore) continue;
                float v0 = acc[mt][nt][half_ * 2];
                float v1 = acc[mt][nt][half_ * 2 + 1];
                if (BIAS) { v0 += bias[col]; v1 += bias[col + 1]; }
                if (EPI == 1) { v0 = fsilu(v0); v1 = fsilu(v1); }
                if (EPI == 2) {
                    v0 += res[(size_t)row * ldo + col];
                    v1 += res[(size_t)row * ldo + col + 1];
                }
                if (EPI == 3) {
                    v0 = res[(size_t)row * ldo + col]     + gate[bI * gateStride + col]     * v0;
                    v1 = res[(size_t)row * ldo + col + 1] + gate[bI * gateStride + col + 1] * v1;
                }
                if (WF) *(float2*)&Of[(size_t)row * ldo + col] = make_float2(v0, v1);
                if (WH) *(__half2*)&Oh[(size_t)row * ldo + col] = __floats2half2_rn(v0, v1);
            }
        }
    }
}

// ---------------------------------------------------------------------------
// m = sst + t
// ---------------------------------------------------------------------------
__global__ void mod_kernel(const float* __restrict__ t, const float* __restrict__ sst)
{
    int i = blockIdx.x * 256 + threadIdx.x;
    if (i < Bb * 6 * Cc) g_mb[i] = sst[i % (6 * Cc)] + t[i];
}

// ---------------------------------------------------------------------------
// all weight (and y) fp16 conversion in ONE launch
// ---------------------------------------------------------------------------
__global__ void round_all_kernel(const float* qkv_w, const float* aproj_w,
                                 const float* q_w, const float* kv_w,
                                 const float* cproj_w, const float* inv_w,
                                 const float* pw_w, const float* y)
{
    long i = (long)blockIdx.x * 256 + threadIdx.x;
    long n;
    n = (long)3 * Cc * Cc;   if (i < n) { g_wts[W_QKV + i] = __float2half_rn(qkv_w[i]);   return; } i -= n;
    n = (long)Cc * Cc;       if (i < n) { g_wts[W_APR + i] = __float2half_rn(aproj_w[i]); return; } i -= n;
    n = (long)Cc * Cc;       if (i < n) { g_wts[W_Q   + i] = __float2half_rn(q_w[i]);     return; } i -= n;
    n = (long)2 * Cc * Cc;   if (i < n) { g_wts[W_KV  + i] = __float2half_rn(kv_w[i]);    return; } i -= n;
    n = (long)Cc * Cc;       if (i < n) { g_wts[W_CPR + i] = __float2half_rn(cproj_w[i]); return; } i -= n;
    n = (long)2 * HIDd * Cc; if (i < n) { g_wts[W_INV + i] = __float2half_rn(inv_w[i]);   return; } i -= n;
    n = (long)Cc * HIDd;     if (i < n) { g_wts[W_PW  + i] = __float2half_rn(pw_w[i]);    return; } i -= n;
    n = (long)Bb * Mkv * Cc; if (i < n) { g_yh[i] = __float2half_rn(y[i]); }
}

// ---------------------------------------------------------------------------
// LayerNorm + adaLN modulate (writes half)
// ---------------------------------------------------------------------------
__global__ __launch_bounds__(256)
void ln_mod_kernel(const float* __restrict__ in, __half* __restrict__ out,
                   int scRow, int shRow)
{
    int row = blockIdx.x;
    int b   = row / Nn;
    const float* xr = in + (size_t)row * Cc;

    float s = 0.f, s2 = 0.f;
    for (int c = threadIdx.x; c < Cc; c += blockDim.x) {
        float v = xr[c]; s += v; s2 += v * v;
    }
    __shared__ float sh1[8], sh2[8];
    int lane = threadIdx.x & 31, wid = threadIdx.x >> 5;
    #pragma unroll
    for (int o = 16; o > 0; o >>= 1) {
        s  += __shfl_down_sync(0xffffffffu, s,  o);
        s2 += __shfl_down_sync(0xffffffffu, s2, o);
    }
    if (lane == 0) { sh1[wid] = s; sh2[wid] = s2; }
    __syncthreads();
    if (wid == 0) {
        s  = (lane < 8) ? sh1[lane] : 0.f;
        s2 = (lane < 8) ? sh2[lane] : 0.f;
        #pragma unroll
        for (int o = 4; o > 0; o >>= 1) {
            s  += __shfl_down_sync(0xffffffffu, s,  o);
            s2 += __shfl_down_sync(0xffffffffu, s2, o);
        }
        if (lane == 0) { sh1[0] = s; sh2[0] = s2; }
    }
    __syncthreads();
    float mu   = sh1[0] * (1.f / Cc);
    float var  = sh2[0] * (1.f / Cc) - mu * mu;
    float rstd = rsqrtf(var + 1e-6f);
    const float* mbp = g_mb + (size_t)b * 6 * Cc;
    for (int c = threadIdx.x; c < Cc; c += blockDim.x) {
        float sc = mbp[scRow * Cc + c];
        float sv = mbp[shRow * Cc + c];
        out[(size_t)row * Cc + c] =
            __float2half_rn((xr[c] - mu) * rstd * (1.f + sc) + sv);
    }
}

// ---------------------------------------------------------------------------
// LiteLA vk accumulation + epilogue
// ---------------------------------------------------------------------------
__global__ void zero_vk_kernel()
{
    int i = blockIdx.x * 256 + threadIdx.x;
    if (i < Bb * HLA * 33 * 32) g_vk[i] = 0.f;
}

__global__ __launch_bounds__(256)
void vk_kernel(const __half* __restrict__ qkv, float* __restrict__ vkout)
{
    int bh = blockIdx.x;
    int b  = bh / HLA, h = bh % HLA;
    int split = blockIdx.y;
    __shared__ float ks[32][33];
    __shared__ float vs[32][33];
    float acc[5] = {0.f, 0.f, 0.f, 0.f, 0.f};
    int tid = threadIdx.x;
    const size_t base = (size_t)b * Nn * 3 * Cc;
    int nStart = split * (Nn / 16);
    for (int n0 = nStart; n0 < nStart + Nn / 16; n0 += 32) {
        for (int li = tid; li < 1024; li += 256) {
            int nn = li >> 5, dc = li & 31;
            size_t off = base + (size_t)(n0 + nn) * 3 * Cc + h * 32 + dc;
            ks[nn][dc] = fmaxf(__half2float(qkv[off + Cc]), 0.f);
            vs[nn][dc] = __half2float(qkv[off + 2 * Cc]);
        }
        __syncthreads();
        #pragma unroll
        for (int u = 0; u < 5; u++) {
            int idx = tid + 256 * u;
            if (idx < 1056) {
                int e = idx >> 5, dc = idx & 31;
                float a = acc[u];
                if (e == 32) {
                    #pragma unroll
                    for (int nn = 0; nn < 32; nn++) a += ks[nn][dc];
                } else {
                    #pragma unroll
                    for (int nn = 0; nn < 32; nn++) a += vs[nn][e] * ks[nn][dc];
                }
                acc[u] = a;
            }
        }
        __syncthreads();
    }
    #pragma unroll
    for (int u = 0; u < 5; u++) {
        int idx = tid + 256 * u;
        if (idx < 1056) {
            int e = idx >> 5, dc = idx & 31;
            atomicAdd(&vkout[((size_t)bh * 33 + e) * 32 + dc], acc[u]);
        }
    }
}

__global__ __launch_bounds__(256)
void la_out_kernel(const __half* __restrict__ qkv, const float* __restrict__ vk,
                   __half* __restrict__ out)
{
    int row = blockIdx.x;
    int b   = row / Nn;
    __shared__ float q[Cc];
    __shared__ float rden[HLA];
    const __half* qr = qkv + (size_t)row * 3 * Cc;
    for (int c = threadIdx.x; c < Cc; c += blockDim.x)
        q[c] = fmaxf(__half2float(qr[c]), 0.f);
    __syncthreads();
    if (threadIdx.x < HLA) {
        int h = threadIdx.x;
        const float* vkh = vk + ((size_t)(b * HLA + h) * 33 + 32) * 32;
        float s = 0.f;
        #pragma unroll
        for (int d = 0; d < 32; d++) s += vkh[d] * q[h * 32 + d];
        rden[h] = 1.0f / (s + 1e-8f);
    }
    __syncthreads();
    for (int c = threadIdx.x; c < Cc; c += blockDim.x) {
        int h = c >> 5, dd = c & 31;
        const float* vkr = vk + ((size_t)(b * HLA + h) * 33 + dd) * 32;
        const float* qh  = q + h * 32;
        float s = 0.f;
        #pragma unroll
        for (int d = 0; d < 32; d++) s += vkr[d] * qh[d];
        out[(size_t)row * Cc + c] = __float2half_rn(s * rden[h]);
    }
}

// ---------------------------------------------------------------------------
// v^T materialization (half), m padded to SLD with zeros
// ---------------------------------------------------------------------------
__global__ void vt_kernel(const __half* __restrict__ kv, __half* __restrict__ vt)
{
    long idx = (long)blockIdx.x * 256 + threadIdx.x;
    if (idx >= (long)Bb * HX * 72 * SLD) return;
    int  m = (int)(idx % SLD);
    long r = idx / SLD;
    int  d = (int)(r % 72);
    int  z = (int)(r / 72);
    int  b = z / HX, h = z % HX;
    __half v = __float2half_rn(0.f);
    if (m < Mkv) v = kv[((size_t)b * Mkv + m) * 2 * Cc + Cc + h * 72 + d];
    vt[idx] = v;
}

// ---------------------------------------------------------------------------
// Cross-attn softmax: float scores -> half probs, FMA-only exp
// ---------------------------------------------------------------------------
__global__ __launch_bounds__(256)
void softmax_kernel(const float* __restrict__ s, __half* __restrict__ p, long rows)
{
    long gw  = ((long)blockIdx.x * blockDim.x + threadIdx.x) >> 5;
    int lane = threadIdx.x & 31;
    if (gw >= rows) return;
    const float* r = s + gw * SLD;
    __half* rp = p + gw * SLD;
    const float scale = 0.11785113019775793f;
    float v[10];
    float mx = -1e30f;
    #pragma unroll
    for (int i = 0; i < 10; i++) {
        int m = lane + 32 * i;
        v[i] = (m < Mkv) ? r[m] * scale : -1e30f;
        mx = fmaxf(mx, v[i]);
    }
    #pragma unroll
    for (int o = 16; o > 0; o >>= 1) mx = fmaxf(mx, __shfl_xor_sync(0xffffffffu, mx, o));
    float sum = 0.f;
    #pragma unroll
    for (int i = 0; i < 10; i++) { v[i] = fexp(v[i] - mx); sum += v[i]; }
    #pragma unroll
    for (int o = 16; o > 0; o >>= 1) sum += __shfl_xor_sync(0xffffffffu, sum, o);
    float inv = 1.f / sum;
    #pragma unroll
    for (int i = 0; i < 10; i++) {
        int m = lane + 32 * i;
        rp[m] = __float2half_rn((m < Mkv) ? v[i] * inv : 0.f);
    }
}

// ---------------------------------------------------------------------------
// depthwise 3x3 + bias + GLU, smem-tiled, FMA-only silu
// ---------------------------------------------------------------------------
__global__ __launch_bounds__(256)
void dwglu_kernel(const __half* __restrict__ h, const float* __restrict__ dww,
                  const float* __restrict__ dwb, __half* __restrict__ out)
{
    __shared__ float sa[100][64];
    __shared__ float sg[100][64];
    int tid = threadIdx.x;
    int c0  = blockIdx.x * 64;
    int y0  = (blockIdx.y >> 3) * 8, x0 = (blockIdx.y & 7) * 8;
    int b   = blockIdx.z;

    int ch = tid & 63;
    float wA[9], wG[9];
    #pragma unroll
    for (int tp = 0; tp < 9; tp++) {
        wA[tp] = dww[(size_t)(c0 + ch) * 9 + tp];
        wG[tp] = dww[(size_t)(c0 + ch + HIDd) * 9 + tp];
    }
    float bA = dwb[c0 + ch], bG = dwb[c0 + ch + HIDd];

    for (int li = tid; li < 1600; li += 256) {
        int pos = li >> 4, q = li & 15;
        int py = pos / 10, px = pos % 10;
        int yy = y0 + py - 1, xx = x0 + px - 1;
        float4 va = make_float4(0.f, 0.f, 0.f, 0.f), vg = va;
        if (yy >= 0 && yy < 64 && xx >= 0 && xx < 64) {
            const __half* src = h + ((size_t)b * Nn + yy * 64 + xx) * (2 * HIDd) + c0 + q * 4;
            float2 a01 = __half22float2(*(const __half2*)src);
            float2 a23 = __half22float2(*(const __half2*)(src + 2));
            float2 g01 = __half22float2(*(const __half2*)(src + HIDd));
            float2 g23 = __half22float2(*(const __half2*)(src + HIDd + 2));
            va = make_float4(a01.x, a01.y, a23.x, a23.y);
            vg = make_float4(g01.x, g01.y, g23.x, g23.y);
        }
        *(float4*)&sa[pos][q * 4] = va;
        *(float4*)&sg[pos][q * 4] = vg;
    }
    __syncthreads();

    #pragma unroll
    for (int i = 0; i < 16; i++) {
        int pos = (tid >> 6) + i * 4;
        int py = pos >> 3, px = pos & 7;
        int s0 = (py + 1) * 10 + (px + 1);
        float accA = bA, accG = bG;
        #pragma unroll
        for (int dy = -1; dy <= 1; dy++)
            #pragma unroll
            for (int dx = -1; dx <= 1; dx++) {
                int s = s0 + dy * 10 + dx;
                int tp = (dy + 1) * 3 + (dx + 1);
                accA = fmaf(sa[s][ch], wA[tp], accA);
                accG = fmaf(sg[s][ch], wG[tp], accG);
            }
        int n = (y0 + py) * 64 + (x0 + px);
        out[((size_t)b * Nn + n) * HIDd + c0 + ch] =
            __float2half_rn(accA * fsilu(accG));
    }
}

// ---------------------------------------------------------------------------
extern "C" void kernel_launch(void* const* d_in, const int* /*in_sizes*/, int /*n_in*/,
                              void* d_out, int /*out_size*/)
{
    const float* x       = (const float*)d_in[0];
    const float* y       = (const float*)d_in[1];
    const float* t       = (const float*)d_in[2];
    const float* sst     = (const float*)d_in[3];
    const float* qkv_w   = (const float*)d_in[4];
    const float* aproj_w = (const float*)d_in[5];
    const float* aproj_b = (const float*)d_in[6];
    const float* q_w     = (const float*)d_in[7];
    const float* q_b     = (const float*)d_in[8];
    const float* kv_w    = (const float*)d_in[9];
    const float* kv_b    = (const float*)d_in[10];
    const float* cproj_w = (const float*)d_in[11];
    const float* cproj_b = (const float*)d_in[12];
    const float* inv_w   = (const float*)d_in[13];
    const float* inv_b   = (const float*)d_in[14];
    const float* dw_w    = (const float*)d_in[15];
    const float* dw_b    = (const float*)d_in[16];
    const float* pw_w    = (const float*)d_in[17];
    float* out = (float*)d_out;

    float  *p_big, *p_x1, *p_x2, *p_vk, *p_m;
    __half *p_shh, *p_x1h, *p_glu, *p_kvh, *p_vt, *p_prb, *p_yh, *p_w;
    cudaGetSymbolAddress((void**)&p_big, g_big);
    cudaGetSymbolAddress((void**)&p_shh, g_shh);
    cudaGetSymbolAddress((void**)&p_x1,  g_x1);
    cudaGetSymbolAddress((void**)&p_x1h, g_x1h);
    cudaGetSymbolAddress((void**)&p_x2,  g_x2);
    cudaGetSymbolAddress((void**)&p_glu, g_glu);
    cudaGetSymbolAddress((void**)&p_kvh, g_kvb);
    cudaGetSymbolAddress((void**)&p_vt,  g_vt);
    cudaGetSymbolAddress((void**)&p_prb, g_prb);
    cudaGetSymbolAddress((void**)&p_yh,  g_yh);
    cudaGetSymbolAddress((void**)&p_vk,  g_vk);
    cudaGetSymbolAddress((void**)&p_m,   g_mb);
    cudaGetSymbolAddress((void**)&p_w,   g_wts);

    __half* p_bigh = (__half*)p_big;

    cudaFuncSetAttribute(mma_gemm<false,0,false,true>, cudaFuncAttributeMaxDynamicSharedMemorySize, MM_SMEM);
    cudaFuncSetAttribute(mma_gemm<true, 3,true, true>, cudaFuncAttributeMaxDynamicSharedMemorySize, MM_SMEM);
    cudaFuncSetAttribute(mma_gemm<true, 0,false,true>, cudaFuncAttributeMaxDynamicSharedMemorySize, MM_SMEM);
    cudaFuncSetAttribute(mma_gemm<false,0,true,false>, cudaFuncAttributeMaxDynamicSharedMemorySize, MM_SMEM);
    cudaFuncSetAttribute(mma_gemm<true, 2,true,false>, cudaFuncAttributeMaxDynamicSharedMemorySize, MM_SMEM);
    cudaFuncSetAttribute(mma_gemm<true, 1,false,true>, cudaFuncAttributeMaxDynamicSharedMemorySize, MM_SMEM);
    cudaFuncSetAttribute(mma_gemm<false,3,true,false>, cudaFuncAttributeMaxDynamicSharedMemorySize, MM_SMEM);

    const int ROWS = Bb * Nn;
    const long RN_TOTAL = (long)3*Cc*Cc + 5L*Cc*Cc + 2L*HIDd*Cc + (long)Cc*HIDd
                        + (long)Bb*Mkv*Cc;

    mod_kernel<<<(Bb * 6 * Cc + 255) / 256, 256>>>(t, sst);
    round_all_kernel<<<(int)((RN_TOTAL + 255) / 256), 256>>>(
        qkv_w, aproj_w, q_w, kv_w, cproj_w, inv_w, pw_w, y);
    ln_mod_kernel<<<ROWS, 256>>>(x, p_shh, 1, 0);

    // qkv = xmod1 @ qkv_w.T  (half out)
    mma_gemm<false,0,false,true><<<dim3(27, 64), 256, MM_SMEM>>>(
        p_shh, p_w + W_QKV, nullptr, nullptr, nullptr, nullptr, p_bigh,
        ROWS, 3 * Cc, 3 * Cc, Cc, Cc, Cc, 3 * Cc,
        1, 0, 0, 0, 0, 0, 0, 0);

    zero_vk_kernel<<<(Bb * HLA * 33 * 32 + 255) / 256, 256>>>();
    vk_kernel<<<dim3(Bb * HLA, 16), 256>>>(p_bigh, p_vk);
    la_out_kernel<<<ROWS, 256>>>(p_bigh, p_vk, p_shh);

    // x1 = x + g_a * (la @ aproj_w.T + b)
    mma_gemm<true,3,true,true><<<dim3(9, 64), 256, MM_SMEM>>>(
        p_shh, p_w + W_APR, aproj_b, x, p_m + 2 * Cc, p_x1, p_x1h,
        ROWS, Cc, Cc, Cc, Cc, Cc, Cc,
        1, 0, 0, 0, 0, 0, 0, 6 * Cc);

    // q = x1 @ q_w.T + q_b
    mma_gemm<true,0,false,true><<<dim3(9, 64), 256, MM_SMEM>>>(
        p_x1h, p_w + W_Q, q_b, nullptr, nullptr, nullptr, p_shh,
        ROWS, Cc, Cc, Cc, Cc, Cc, Cc,
        1, 0, 0, 0, 0, 0, 0, 0);

    // kv = y @ kv_w.T + kv_b
    mma_gemm<true,0,false,true><<<dim3(18, 5), 256, MM_SMEM>>>(
        p_yh, p_w + W_KV, kv_b, nullptr, nullptr, nullptr, p_kvh,
        Bb * Mkv, 2 * Cc, 2 * Cc, Cc, Cc, Cc, 2 * Cc,
        1, 0, 0, 0, 0, 0, 0, 0);

    vt_kernel<<<(int)(((long)Bb * HX * 72 * SLD + 255) / 256), 256>>>(p_kvh, p_vt);

    // scores[z] = q_h @ k_h.T  (float out)
    mma_gemm<false,0,true,false><<<dim3(3, 32, Bb * HX), 256, MM_SMEM>>>(
        p_shh, p_kvh, nullptr, nullptr, nullptr, p_big, nullptr,
        Nn, Mkv, SLD, 72, Cc, 2 * Cc, SLD,
        HX, (long)Nn * Cc, 72, (long)Mkv * 2 * Cc, 72,
        (long)HX * Nn * SLD, (long)Nn * SLD, 0);

    softmax_kernel<<<(Bb * HX * Nn) / 8, 256>>>(p_big, p_prb, (long)Bb * HX * Nn);

    // o[z] = probs @ v^T  (half out)
    mma_gemm<false,0,false,true><<<dim3(1, 32, Bb * HX), 256, MM_SMEM>>>(
        p_prb, p_vt, nullptr, nullptr, nullptr, nullptr, p_shh,
        Nn, 72, 72, SLD, SLD, SLD, Cc,
        HX, (long)HX * Nn * SLD, (long)Nn * SLD, (long)72 * SLD * HX, (long)72 * SLD,
        (long)Nn * Cc, 72, 0);

    // x2 = x1 + o @ cproj_w.T + b
    mma_gemm<true,2,true,false><<<dim3(9, 64), 256, MM_SMEM>>>(
        p_shh, p_w + W_CPR, cproj_b, p_x1, nullptr, p_x2, nullptr,
        ROWS, Cc, Cc, Cc, Cc, Cc, Cc,
        1, 0, 0, 0, 0, 0, 0, 0);

    ln_mod_kernel<<<ROWS, 256>>>(p_x2, p_shh, 4, 3);

    // h = silu(xmod2 @ inv_w.T + b)   (FMA-only silu epilogue)
    mma_gemm<true,1,false,true><<<dim3(45, 64), 256, MM_SMEM>>>(
        p_shh, p_w + W_INV, inv_b, nullptr, nullptr, nullptr, p_bigh,
        ROWS, 2 * HIDd, 2 * HIDd, Cc, Cc, Cc, 2 * HIDd,
        1, 0, 0, 0, 0, 0, 0, 0);

    dwglu_kernel<<<dim3(HIDd / 64, 64, Bb), 256>>>(p_bigh, dw_w, dw_b, p_glu);

    // out = x2 + g_m * (glu @ pw_w.T)
    mma_gemm<false,3,true,false><<<dim3(9, 64), 256, MM_SMEM>>>(
        p_glu, p_w + W_PW, nullptr, p_x2, p_m + 5 * Cc, out, nullptr,
        ROWS, Cc, Cc, HIDd, HIDd, HIDd, Cc,
        1, 0, 0, 0, 0, 0, 0, 6 * Cc);
}

// round 13
// speedup vs baseline: 4.4170x; 1.6761x over previous
#include <cuda_runtime.h>
#include <cuda_fp16.h>
#include <cstdint>
#include <math.h>

// ---------------------------------------------------------------------------
// SanaBlock: LN+adaLN -> LiteLA -> cross-attn -> GLUMBConv, B=2,N=4096,C=1152
// R13: BK=64 GEMM mainloop (half the per-tile overhead) + transposed vk so
//      la_out's global reads are coalesced. Everything else as R12.
// ---------------------------------------------------------------------------
constexpr int Bb   = 2;
constexpr int Nn   = 4096;
constexpr int Cc   = 1152;
constexpr int Mkv  = 300;
constexpr int HIDd = 2880;
constexpr int HLA  = 36;
constexpr int HX   = 16;
constexpr int SLD  = 320;

__device__ __align__(256) float  g_big [47185920];
__device__ __align__(256) __half g_shh [(size_t)Bb * Nn * Cc];
__device__ __align__(256) float  g_x1  [(size_t)Bb * Nn * Cc];
__device__ __align__(256) __half g_x1h [(size_t)Bb * Nn * Cc];
__device__ __align__(256) float  g_x2  [(size_t)Bb * Nn * Cc];
__device__ __align__(256) __half g_glu [(size_t)Bb * Nn * HIDd];
__device__ __align__(256) __half g_kvb [(size_t)Bb * Mkv * 2 * Cc];
__device__ __align__(256) __half g_vt  [(size_t)Bb * HX * 72 * SLD];
__device__ __align__(256) __half g_prb [(size_t)Bb * HX * Nn * SLD];
__device__ __align__(256) __half g_yh  [(size_t)Bb * Mkv * Cc];
__device__ __align__(256) __half g_wts [20570112];
__device__ float g_vk [Bb * HLA * 33 * 32];   // transposed: [bh][d:32][e:33]
__device__ float g_mb [Bb * 6 * Cc];

constexpr size_t W_QKV = 0;
constexpr size_t W_APR = W_QKV + (size_t)3 * Cc * Cc;
constexpr size_t W_Q   = W_APR + (size_t)Cc * Cc;
constexpr size_t W_KV  = W_Q   + (size_t)Cc * Cc;
constexpr size_t W_CPR = W_KV  + (size_t)2 * Cc * Cc;
constexpr size_t W_INV = W_CPR + (size_t)Cc * Cc;
constexpr size_t W_PW  = W_INV + (size_t)2 * HIDd * Cc;

// ---------------------------------------------------------------------------
// FMA-only transcendentals
// ---------------------------------------------------------------------------
__device__ __forceinline__ float fexp(float t){
    t = fminf(fmaxf(t, -87.0f), 87.0f);
    float z = t * 1.4426950408889634f;
    float n = floorf(z);
    float f = z - n;
    float p = 1.5403530e-4f;
    p = fmaf(p, f, 1.3333558e-3f);
    p = fmaf(p, f, 9.6181291e-3f);
    p = fmaf(p, f, 5.5504109e-2f);
    p = fmaf(p, f, 2.4022651e-1f);
    p = fmaf(p, f, 6.9314718e-1f);
    p = fmaf(p, f, 1.0f);
    int i = (int)n;
    return p * __int_as_float((i + 127) << 23);
}
__device__ __forceinline__ float fsigmoid(float x){
    float u = fexp(-fabsf(x));
    float z = 1.0f + u;                    // [1,2]
    float y = fmaf(-0.47058824f, z, 1.4117647f);
    y = y * fmaf(-z, y, 2.0f);
    y = y * fmaf(-z, y, 2.0f);
    return (x >= 0.f) ? y : 1.0f - y;
}
__device__ __forceinline__ float fsilu(float x){ return x * fsigmoid(x); }

// ---------------------------------------------------------------------------
// helpers
// ---------------------------------------------------------------------------
__device__ __forceinline__ uint32_t smem_u32(const void* p){
    uint32_t a;
    asm("{ .reg .u64 t; cvta.to.shared.u64 t, %1; cvt.u32.u64 %0, t; }"
        : "=r"(a) : "l"(p));
    return a;
}
__device__ __forceinline__ void cp16(uint32_t dst, const void* src, int srcsz){
    asm volatile("cp.async.cg.shared.global [%0], [%1], 16, %2;"
        ::"r"(dst),"l"(src),"r"(srcsz):"memory");
}
#define CP_COMMIT() asm volatile("cp.async.commit_group;":::"memory")
#define CP_WAIT1()  asm volatile("cp.async.wait_group 1;":::"memory")

__device__ __forceinline__ void mma16(float* d, const uint32_t* a, const uint32_t* b){
    asm volatile("mma.sync.aligned.m16n8k16.row.col.f32.f16.f16.f32 "
        "{%0,%1,%2,%3},{%4,%5,%6,%7},{%8,%9},{%0,%1,%2,%3};"
        : "+f"(d[0]),"+f"(d[1]),"+f"(d[2]),"+f"(d[3])
        : "r"(a[0]),"r"(a[1]),"r"(a[2]),"r"(a[3]),"r"(b[0]),"r"(b[1]));
}
__device__ __forceinline__ void ldsm4(uint32_t& r0, uint32_t& r1, uint32_t& r2,
                                      uint32_t& r3, uint32_t addr){
    asm volatile("ldmatrix.sync.aligned.m8n8.x4.shared.b16 {%0,%1,%2,%3}, [%4];"
        : "=r"(r0),"=r"(r1),"=r"(r2),"=r"(r3) : "r"(addr));
}

// ---------------------------------------------------------------------------
// fp16 mma NT GEMM: BK=64, 3-stage cp.async, 1 barrier per K-tile.
// CTA 128x128, 8 warps (4M x 2N), warp tile 32x64, ldmatrix.x4 fragments.
// ---------------------------------------------------------------------------
constexpr int LDPH    = 72;               // halves per row (144B: +4 banks/row)
constexpr int TILE_H  = 128 * LDPH;       // 9216 halves
constexpr int STAGE_H = 2 * TILE_H;
constexpr int MM_SMEM = 3 * STAGE_H * 2;  // 110592 bytes

template<bool BIAS, int EPI, bool WF, bool WH>
__global__ __launch_bounds__(256, 2)
void mma_gemm(const __half* A, const __half* Bw, const float* bias,
              const float* res, const float* gate,
              float* Of, __half* Oh,
              int Mrows, int NloadB, int Nstore, int K,
              int lda, int ldb, int ldo,
              int HB, long aBs, long aHs, long bBs, long bHs, long oBs, long oHs,
              int gateStride)
{
    extern __shared__ __half smh[];
    uint32_t sbase = smem_u32(smh);
    int tid = threadIdx.x, wid = tid >> 5, lane = tid & 31;
    int warpM = wid >> 1, warpN = wid & 1;
    int m0 = blockIdx.y * 128, n0 = blockIdx.x * 128;

    if (gridDim.z > 1) {
        int z = blockIdx.z;
        int bI = z / HB, hI = z % HB;
        A  += bI * aBs + hI * aHs;
        Bw += bI * bBs + hI * bHs;
        if (WF) Of += bI * oBs + hI * oHs;
        if (WH) Oh += bI * oBs + hI * oHs;
    }

    const int T = (K + 63) >> 6;

    auto load_tile = [&](int t, int buf) {
        uint32_t base = sbase + (uint32_t)buf * STAGE_H * 2;
        int k0 = t << 6;
        #pragma unroll
        for (int i = 0; i < 4; i++) {                 // A: 128 rows x 64 halves
            int c = tid + (i << 8);                   // 0..1023
            int row = c >> 3, ch = c & 7;
            int gk = k0 + ch * 8;
            uint32_t dst = base + (uint32_t)(row * LDPH + ch * 8) * 2;
            const __half* ga = A + (size_t)(m0 + row) * lda + gk;
            cp16(dst, ga, ((m0 + row) < Mrows && gk < K) ? 16 : 0);
        }
        #pragma unroll
        for (int i = 0; i < 4; i++) {                 // B: 128 rows x 64 halves
            int c = tid + (i << 8);
            int row = c >> 3, ch = c & 7;
            int gk = k0 + ch * 8;
            uint32_t dst = base + (uint32_t)(TILE_H + row * LDPH + ch * 8) * 2;
            const __half* gb = Bw + (size_t)(n0 + row) * ldb + gk;
            cp16(dst, gb, ((n0 + row) < NloadB && gk < K) ? 16 : 0);
        }
    };

    float acc[2][8][4];
    #pragma unroll
    for (int mt = 0; mt < 2; mt++)
        #pragma unroll
        for (int nt = 0; nt < 8; nt++)
            #pragma unroll
            for (int q = 0; q < 4; q++) acc[mt][nt][q] = 0.f;

    load_tile(0, 0); CP_COMMIT();
    load_tile(1, 1); CP_COMMIT();

    int rowA = warpM * 32 + (lane & 15);
    int colA = (lane >> 4) << 3;
    int rowB = warpN * 64 + (lane & 7) + ((lane >> 4) << 3);
    int colB = ((lane >> 3) & 1) << 3;
    uint32_t offA = (uint32_t)(rowA * LDPH + colA) * 2;
    uint32_t offB = (uint32_t)(TILE_H + rowB * LDPH + colB) * 2;

    for (int t = 0; t < T; t++) {
        int buf = t % 3;
        CP_WAIT1();
        __syncthreads();
        if (t + 2 < T) load_tile(t + 2, (t + 2) % 3);
        CP_COMMIT();

        uint32_t sA = sbase + (uint32_t)buf * STAGE_H * 2;

        #pragma unroll
        for (int kk = 0; kk < 4; kk++) {
            uint32_t af[2][4];
            #pragma unroll
            for (int mt = 0; mt < 2; mt++) {
                uint32_t addr = sA + offA + (uint32_t)(mt * 16 * LDPH + kk * 16) * 2;
                ldsm4(af[mt][0], af[mt][1], af[mt][2], af[mt][3], addr);
            }
            uint32_t bf[8][2];
            #pragma unroll
            for (int ntp = 0; ntp < 4; ntp++) {
                uint32_t addr = sA + offB + (uint32_t)(ntp * 16 * LDPH + kk * 16) * 2;
                ldsm4(bf[2 * ntp][0], bf[2 * ntp][1],
                      bf[2 * ntp + 1][0], bf[2 * ntp + 1][1], addr);
            }
            #pragma unroll
            for (int mt = 0; mt < 2; mt++)
                #pragma unroll
                for (int nt = 0; nt < 8; nt++)
                    mma16(acc[mt][nt], af[mt], bf[nt]);
        }
    }

    #pragma unroll
    for (int mt = 0; mt < 2; mt++) {
        #pragma unroll
        for (int half_ = 0; half_ < 2; half_++) {
            int row = m0 + warpM * 32 + mt * 16 + (lane >> 2) + half_ * 8;
            if (row >= Mrows) continue;
            int bI = (row >= Nn) ? 1 : 0;
            #pragma unroll
            for (int nt = 0; nt < 8; nt++) {
                int col = n0 + warpN * 64 + nt * 8 + (lane & 3) * 2;
                if (col >= Nstore) continue;
                float v0 = acc[mt][nt][half_ * 2];
                float v1 = acc[mt][nt][half_ * 2 + 1];
                if (BIAS) { v0 += bias[col]; v1 += bias[col + 1]; }
                if (EPI == 1) { v0 = fsilu(v0); v1 = fsilu(v1); }
                if (EPI == 2) {
                    v0 += res[(size_t)row * ldo + col];
                    v1 += res[(size_t)row * ldo + col + 1];
                }
                if (EPI == 3) {
                    v0 = res[(size_t)row * ldo + col]     + gate[bI * gateStride + col]     * v0;
                    v1 = res[(size_t)row * ldo + col + 1] + gate[bI * gateStride + col + 1] * v1;
                }
                if (WF) *(float2*)&Of[(size_t)row * ldo + col] = make_float2(v0, v1);
                if (WH) *(__half2*)&Oh[(size_t)row * ldo + col] = __floats2half2_rn(v0, v1);
            }
        }
    }
}

// ---------------------------------------------------------------------------
__global__ void mod_kernel(const float* __restrict__ t, const float* __restrict__ sst)
{
    int i = blockIdx.x * 256 + threadIdx.x;
    if (i < Bb * 6 * Cc) g_mb[i] = sst[i % (6 * Cc)] + t[i];
}

__global__ void round_all_kernel(const float* qkv_w, const float* aproj_w,
                                 const float* q_w, const float* kv_w,
                                 const float* cproj_w, const float* inv_w,
                                 const float* pw_w, const float* y)
{
    long i = (long)blockIdx.x * 256 + threadIdx.x;
    long n;
    n = (long)3 * Cc * Cc;   if (i < n) { g_wts[W_QKV + i] = __float2half_rn(qkv_w[i]);   return; } i -= n;
    n = (long)Cc * Cc;       if (i < n) { g_wts[W_APR + i] = __float2half_rn(aproj_w[i]); return; } i -= n;
    n = (long)Cc * Cc;       if (i < n) { g_wts[W_Q   + i] = __float2half_rn(q_w[i]);     return; } i -= n;
    n = (long)2 * Cc * Cc;   if (i < n) { g_wts[W_KV  + i] = __float2half_rn(kv_w[i]);    return; } i -= n;
    n = (long)Cc * Cc;       if (i < n) { g_wts[W_CPR + i] = __float2half_rn(cproj_w[i]); return; } i -= n;
    n = (long)2 * HIDd * Cc; if (i < n) { g_wts[W_INV + i] = __float2half_rn(inv_w[i]);   return; } i -= n;
    n = (long)Cc * HIDd;     if (i < n) { g_wts[W_PW  + i] = __float2half_rn(pw_w[i]);    return; } i -= n;
    n = (long)Bb * Mkv * Cc; if (i < n) { g_yh[i] = __float2half_rn(y[i]); }
}

// ---------------------------------------------------------------------------
__global__ __launch_bounds__(256)
void ln_mod_kernel(const float* __restrict__ in, __half* __restrict__ out,
                   int scRow, int shRow)
{
    int row = blockIdx.x;
    int b   = row / Nn;
    const float* xr = in + (size_t)row * Cc;

    float s = 0.f, s2 = 0.f;
    for (int c = threadIdx.x; c < Cc; c += blockDim.x) {
        float v = xr[c]; s += v; s2 += v * v;
    }
    __shared__ float sh1[8], sh2[8];
    int lane = threadIdx.x & 31, wid = threadIdx.x >> 5;
    #pragma unroll
    for (int o = 16; o > 0; o >>= 1) {
        s  += __shfl_down_sync(0xffffffffu, s,  o);
        s2 += __shfl_down_sync(0xffffffffu, s2, o);
    }
    if (lane == 0) { sh1[wid] = s; sh2[wid] = s2; }
    __syncthreads();
    if (wid == 0) {
        s  = (lane < 8) ? sh1[lane] : 0.f;
        s2 = (lane < 8) ? sh2[lane] : 0.f;
        #pragma unroll
        for (int o = 4; o > 0; o >>= 1) {
            s  += __shfl_down_sync(0xffffffffu, s,  o);
            s2 += __shfl_down_sync(0xffffffffu, s2, o);
        }
        if (lane == 0) { sh1[0] = s; sh2[0] = s2; }
    }
    __syncthreads();
    float mu   = sh1[0] * (1.f / Cc);
    float var  = sh2[0] * (1.f / Cc) - mu * mu;
    float rstd = rsqrtf(var + 1e-6f);
    const float* mbp = g_mb + (size_t)b * 6 * Cc;
    for (int c = threadIdx.x; c < Cc; c += blockDim.x) {
        float sc = mbp[scRow * Cc + c];
        float sv = mbp[shRow * Cc + c];
        out[(size_t)row * Cc + c] =
            __float2half_rn((xr[c] - mu) * rstd * (1.f + sc) + sv);
    }
}

// ---------------------------------------------------------------------------
// LiteLA vk accumulation — TRANSPOSED output: vkT[bh][d:32][e:33]
// ---------------------------------------------------------------------------
__global__ void zero_vk_kernel()
{
    int i = blockIdx.x * 256 + threadIdx.x;
    if (i < Bb * HLA * 33 * 32) g_vk[i] = 0.f;
}

__global__ __launch_bounds__(256)
void vk_kernel(const __half* __restrict__ qkv, float* __restrict__ vkout)
{
    int bh = blockIdx.x;
    int b  = bh / HLA, h = bh % HLA;
    int split = blockIdx.y;
    __shared__ float ks[32][33];
    __shared__ float vs[32][33];
    float acc[5] = {0.f, 0.f, 0.f, 0.f, 0.f};
    int tid = threadIdx.x;
    const size_t base = (size_t)b * Nn * 3 * Cc;
    int nStart = split * (Nn / 16);
    for (int n0 = nStart; n0 < nStart + Nn / 16; n0 += 32) {
        for (int li = tid; li < 1024; li += 256) {
            int nn = li >> 5, dc = li & 31;
            size_t off = base + (size_t)(n0 + nn) * 3 * Cc + h * 32 + dc;
            ks[nn][dc] = fmaxf(__half2float(qkv[off + Cc]), 0.f);
            vs[nn][dc] = __half2float(qkv[off + 2 * Cc]);
        }
        __syncthreads();
        #pragma unroll
        for (int u = 0; u < 5; u++) {
            int idx = tid + 256 * u;
            if (idx < 1056) {
                int e = idx >> 5, dc = idx & 31;
                float a = acc[u];
                if (e == 32) {
                    #pragma unroll
                    for (int nn = 0; nn < 32; nn++) a += ks[nn][dc];
                } else {
                    #pragma unroll
                    for (int nn = 0; nn < 32; nn++) a += vs[nn][e] * ks[nn][dc];
                }
                acc[u] = a;
            }
        }
        __syncthreads();
    }
    #pragma unroll
    for (int u = 0; u < 5; u++) {
        int idx = tid + 256 * u;
        if (idx < 1056) {
            int e = idx >> 5, dc = idx & 31;
            // transposed: [bh][dc][e]
            atomicAdd(&vkout[((size_t)bh * 32 + dc) * 33 + e], acc[u]);
        }
    }
}

// la_out reads transposed vk: coalesced over lanes (dd consecutive)
__global__ __launch_bounds__(256)
void la_out_kernel(const __half* __restrict__ qkv, const float* __restrict__ vk,
                   __half* __restrict__ out)
{
    int row = blockIdx.x;
    int b   = row / Nn;
    __shared__ float q[Cc];
    __shared__ float rden[HLA];
    const __half* qr = qkv + (size_t)row * 3 * Cc;
    for (int c = threadIdx.x; c < Cc; c += blockDim.x)
        q[c] = fmaxf(__half2float(qr[c]), 0.f);
    __syncthreads();
    if (threadIdx.x < HLA) {
        int h = threadIdx.x;
        const float* vkh = vk + (size_t)(b * HLA + h) * 32 * 33;
        float s = 0.f;
        #pragma unroll
        for (int d = 0; d < 32; d++) s += vkh[d * 33 + 32] * q[h * 32 + d];
        rden[h] = 1.0f / (s + 1e-8f);
    }
    __syncthreads();
    for (int c = threadIdx.x; c < Cc; c += blockDim.x) {
        int h = c >> 5, dd = c & 31;
        const float* vkr = vk + (size_t)(b * HLA + h) * 32 * 33 + dd;
        const float* qh  = q + h * 32;
        float s = 0.f;
        #pragma unroll
        for (int d = 0; d < 32; d++) s += vkr[d * 33] * qh[d];
        out[(size_t)row * Cc + c] = __float2half_rn(s * rden[h]);
    }
}

// ---------------------------------------------------------------------------
__global__ void vt_kernel(const __half* __restrict__ kv, __half* __restrict__ vt)
{
    long idx = (long)blockIdx.x * 256 + threadIdx.x;
    if (idx >= (long)Bb * HX * 72 * SLD) return;
    int  m = (int)(idx % SLD);
    long r = idx / SLD;
    int  d = (int)(r % 72);
    int  z = (int)(r / 72);
    int  b = z / HX, h = z % HX;
    __half v = __float2half_rn(0.f);
    if (m < Mkv) v = kv[((size_t)b * Mkv + m) * 2 * Cc + Cc + h * 72 + d];
    vt[idx] = v;
}

// ---------------------------------------------------------------------------
__global__ __launch_bounds__(256)
void softmax_kernel(const float* __restrict__ s, __half* __restrict__ p, long rows)
{
    long gw  = ((long)blockIdx.x * blockDim.x + threadIdx.x) >> 5;
    int lane = threadIdx.x & 31;
    if (gw >= rows) return;
    const float* r = s + gw * SLD;
    __half* rp = p + gw * SLD;
    const float scale = 0.11785113019775793f;
    float v[10];
    float mx = -1e30f;
    #pragma unroll
    for (int i = 0; i < 10; i++) {
        int m = lane + 32 * i;
        v[i] = (m < Mkv) ? r[m] * scale : -1e30f;
        mx = fmaxf(mx, v[i]);
    }
    #pragma unroll
    for (int o = 16; o > 0; o >>= 1) mx = fmaxf(mx, __shfl_xor_sync(0xffffffffu, mx, o));
    float sum = 0.f;
    #pragma unroll
    for (int i = 0; i < 10; i++) { v[i] = fexp(v[i] - mx); sum += v[i]; }
    #pragma unroll
    for (int o = 16; o > 0; o >>= 1) sum += __shfl_xor_sync(0xffffffffu, sum, o);
    float inv = 1.f / sum;
    #pragma unroll
    for (int i = 0; i < 10; i++) {
        int m = lane + 32 * i;
        rp[m] = __float2half_rn((m < Mkv) ? v[i] * inv : 0.f);
    }
}

// ---------------------------------------------------------------------------
__global__ __launch_bounds__(256)
void dwglu_kernel(const __half* __restrict__ h, const float* __restrict__ dww,
                  const float* __restrict__ dwb, __half* __restrict__ out)
{
    __shared__ float sa[100][64];
    __shared__ float sg[100][64];
    int tid = threadIdx.x;
    int c0  = blockIdx.x * 64;
    int y0  = (blockIdx.y >> 3) * 8, x0 = (blockIdx.y & 7) * 8;
    int b   = blockIdx.z;

    int ch = tid & 63;
    float wA[9], wG[9];
    #pragma unroll
    for (int tp = 0; tp < 9; tp++) {
        wA[tp] = dww[(size_t)(c0 + ch) * 9 + tp];
        wG[tp] = dww[(size_t)(c0 + ch + HIDd) * 9 + tp];
    }
    float bA = dwb[c0 + ch], bG = dwb[c0 + ch + HIDd];

    for (int li = tid; li < 1600; li += 256) {
        int pos = li >> 4, q = li & 15;
        int py = pos / 10, px = pos % 10;
        int yy = y0 + py - 1, xx = x0 + px - 1;
        float4 va = make_float4(0.f, 0.f, 0.f, 0.f), vg = va;
        if (yy >= 0 && yy < 64 && xx >= 0 && xx < 64) {
            const __half* src = h + ((size_t)b * Nn + yy * 64 + xx) * (2 * HIDd) + c0 + q * 4;
            float2 a01 = __half22float2(*(const __half2*)src);
            float2 a23 = __half22float2(*(const __half2*)(src + 2));
            float2 g01 = __half22float2(*(const __half2*)(src + HIDd));
            float2 g23 = __half22float2(*(const __half2*)(src + HIDd + 2));
            va = make_float4(a01.x, a01.y, a23.x, a23.y);
            vg = make_float4(g01.x, g01.y, g23.x, g23.y);
        }
        *(float4*)&sa[pos][q * 4] = va;
        *(float4*)&sg[pos][q * 4] = vg;
    }
    __syncthreads();

    #pragma unroll
    for (int i = 0; i < 16; i++) {
        int pos = (tid >> 6) + i * 4;
        int py = pos >> 3, px = pos & 7;
        int s0 = (py + 1) * 10 + (px + 1);
        float accA = bA, accG = bG;
        #pragma unroll
        for (int dy = -1; dy <= 1; dy++)
            #pragma unroll
            for (int dx = -1; dx <= 1; dx++) {
                int s = s0 + dy * 10 + dx;
                int tp = (dy + 1) * 3 + (dx + 1);
                accA = fmaf(sa[s][ch], wA[tp], accA);
                accG = fmaf(sg[s][ch], wG[tp], accG);
            }
        int n = (y0 + py) * 64 + (x0 + px);
        out[((size_t)b * Nn + n) * HIDd + c0 + ch] =
            __float2half_rn(accA * fsilu(accG));
    }
}

// ---------------------------------------------------------------------------
extern "C" void kernel_launch(void* const* d_in, const int* /*in_sizes*/, int /*n_in*/,
                              void* d_out, int /*out_size*/)
{
    const float* x       = (const float*)d_in[0];
    const float* y       = (const float*)d_in[1];
    const float* t       = (const float*)d_in[2];
    const float* sst     = (const float*)d_in[3];
    const float* qkv_w   = (const float*)d_in[4];
    const float* aproj_w = (const float*)d_in[5];
    const float* aproj_b = (const float*)d_in[6];
    const float* q_w     = (const float*)d_in[7];
    const float* q_b     = (const float*)d_in[8];
    const float* kv_w    = (const float*)d_in[9];
    const float* kv_b    = (const float*)d_in[10];
    const float* cproj_w = (const float*)d_in[11];
    const float* cproj_b = (const float*)d_in[12];
    const float* inv_w   = (const float*)d_in[13];
    const float* inv_b   = (const float*)d_in[14];
    const float* dw_w    = (const float*)d_in[15];
    const float* dw_b    = (const float*)d_in[16];
    const float* pw_w    = (const float*)d_in[17];
    float* out = (float*)d_out;

    float  *p_big, *p_x1, *p_x2, *p_vk, *p_m;
    __half *p_shh, *p_x1h, *p_glu, *p_kvh, *p_vt, *p_prb, *p_yh, *p_w;
    cudaGetSymbolAddress((void**)&p_big, g_big);
    cudaGetSymbolAddress((void**)&p_shh, g_shh);
    cudaGetSymbolAddress((void**)&p_x1,  g_x1);
    cudaGetSymbolAddress((void**)&p_x1h, g_x1h);
    cudaGetSymbolAddress((void**)&p_x2,  g_x2);
    cudaGetSymbolAddress((void**)&p_glu, g_glu);
    cudaGetSymbolAddress((void**)&p_kvh, g_kvb);
    cudaGetSymbolAddress((void**)&p_vt,  g_vt);
    cudaGetSymbolAddress((void**)&p_prb, g_prb);
    cudaGetSymbolAddress((void**)&p_yh,  g_yh);
    cudaGetSymbolAddress((void**)&p_vk,  g_vk);
    cudaGetSymbolAddress((void**)&p_m,   g_mb);
    cudaGetSymbolAddress((void**)&p_w,   g_wts);

    __half* p_bigh = (__half*)p_big;

    cudaFuncSetAttribute(mma_gemm<false,0,false,true>, cudaFuncAttributeMaxDynamicSharedMemorySize, MM_SMEM);
    cudaFuncSetAttribute(mma_gemm<true, 3,true, true>, cudaFuncAttributeMaxDynamicSharedMemorySize, MM_SMEM);
    cudaFuncSetAttribute(mma_gemm<true, 0,false,true>, cudaFuncAttributeMaxDynamicSharedMemorySize, MM_SMEM);
    cudaFuncSetAttribute(mma_gemm<false,0,true,false>, cudaFuncAttributeMaxDynamicSharedMemorySize, MM_SMEM);
    cudaFuncSetAttribute(mma_gemm<true, 2,true,false>, cudaFuncAttributeMaxDynamicSharedMemorySize, MM_SMEM);
    cudaFuncSetAttribute(mma_gemm<true, 1,false,true>, cudaFuncAttributeMaxDynamicSharedMemorySize, MM_SMEM);
    cudaFuncSetAttribute(mma_gemm<false,3,true,false>, cudaFuncAttributeMaxDynamicSharedMemorySize, MM_SMEM);

    const int ROWS = Bb * Nn;
    const long RN_TOTAL = (long)3*Cc*Cc + 5L*Cc*Cc + 2L*HIDd*Cc + (long)Cc*HIDd
                        + (long)Bb*Mkv*Cc;

    mod_kernel<<<(Bb * 6 * Cc + 255) / 256, 256>>>(t, sst);
    round_all_kernel<<<(int)((RN_TOTAL + 255) / 256), 256>>>(
        qkv_w, aproj_w, q_w, kv_w, cproj_w, inv_w, pw_w, y);
    ln_mod_kernel<<<ROWS, 256>>>(x, p_shh, 1, 0);

    // qkv = xmod1 @ qkv_w.T
    mma_gemm<false,0,false,true><<<dim3(27, 64), 256, MM_SMEM>>>(
        p_shh, p_w + W_QKV, nullptr, nullptr, nullptr, nullptr, p_bigh,
        ROWS, 3 * Cc, 3 * Cc, Cc, Cc, Cc, 3 * Cc,
        1, 0, 0, 0, 0, 0, 0, 0);

    zero_vk_kernel<<<(Bb * HLA * 33 * 32 + 255) / 256, 256>>>();
    vk_kernel<<<dim3(Bb * HLA, 16), 256>>>(p_bigh, p_vk);
    la_out_kernel<<<ROWS, 256>>>(p_bigh, p_vk, p_shh);

    // x1 = x + g_a * (la @ aproj_w.T + b)
    mma_gemm<true,3,true,true><<<dim3(9, 64), 256, MM_SMEM>>>(
        p_shh, p_w + W_APR, aproj_b, x, p_m + 2 * Cc, p_x1, p_x1h,
        ROWS, Cc, Cc, Cc, Cc, Cc, Cc,
        1, 0, 0, 0, 0, 0, 0, 6 * Cc);

    // q = x1 @ q_w.T + q_b
    mma_gemm<true,0,false,true><<<dim3(9, 64), 256, MM_SMEM>>>(
        p_x1h, p_w + W_Q, q_b, nullptr, nullptr, nullptr, p_shh,
        ROWS, Cc, Cc, Cc, Cc, Cc, Cc,
        1, 0, 0, 0, 0, 0, 0, 0);

    // kv = y @ kv_w.T + kv_b
    mma_gemm<true,0,false,true><<<dim3(18, 5), 256, MM_SMEM>>>(
        p_yh, p_w + W_KV, kv_b, nullptr, nullptr, nullptr, p_kvh,
        Bb * Mkv, 2 * Cc, 2 * Cc, Cc, Cc, Cc, 2 * Cc,
        1, 0, 0, 0, 0, 0, 0, 0);

    vt_kernel<<<(int)(((long)Bb * HX * 72 * SLD + 255) / 256), 256>>>(p_kvh, p_vt);

    // scores[z] = q_h @ k_h.T  (float out)
    mma_gemm<false,0,true,false><<<dim3(3, 32, Bb * HX), 256, MM_SMEM>>>(
        p_shh, p_kvh, nullptr, nullptr, nullptr, p_big, nullptr,
        Nn, Mkv, SLD, 72, Cc, 2 * Cc, SLD,
        HX, (long)Nn * Cc, 72, (long)Mkv * 2 * Cc, 72,
        (long)HX * Nn * SLD, (long)Nn * SLD, 0);

    softmax_kernel<<<(Bb * HX * Nn) / 8, 256>>>(p_big, p_prb, (long)Bb * HX * Nn);

    // o[z] = probs @ v^T  (half out)
    mma_gemm<false,0,false,true><<<dim3(1, 32, Bb * HX), 256, MM_SMEM>>>(
        p_prb, p_vt, nullptr, nullptr, nullptr, nullptr, p_shh,
        Nn, 72, 72, SLD, SLD, SLD, Cc,
        HX, (long)HX * Nn * SLD, (long)Nn * SLD, (long)72 * SLD * HX, (long)72 * SLD,
        (long)Nn * Cc, 72, 0);

    // x2 = x1 + o @ cproj_w.T + b
    mma_gemm<true,2,true,false><<<dim3(9, 64), 256, MM_SMEM>>>(
        p_shh, p_w + W_CPR, cproj_b, p_x1, nullptr, p_x2, nullptr,
        ROWS, Cc, Cc, Cc, Cc, Cc, Cc,
        1, 0, 0, 0, 0, 0, 0, 0);

    ln_mod_kernel<<<ROWS, 256>>>(p_x2, p_shh, 4, 3);

    // h = silu(xmod2 @ inv_w.T + b)
    mma_gemm<true,1,false,true><<<dim3(45, 64), 256, MM_SMEM>>>(
        p_shh, p_w + W_INV, inv_b, nullptr, nullptr, nullptr, p_bigh,
        ROWS, 2 * HIDd, 2 * HIDd, Cc, Cc, Cc, 2 * HIDd,
        1, 0, 0, 0, 0, 0, 0, 0);

    dwglu_kernel<<<dim3(HIDd / 64, 64, Bb), 256>>>(p_bigh, dw_w, dw_b, p_glu);

    // out = x2 + g_m * (glu @ pw_w.T)
    mma_gemm<false,3,true,false><<<dim3(9, 64), 256, MM_SMEM>>>(
        p_glu, p_w + W_PW, nullptr, p_x2, p_m + 5 * Cc, out, nullptr,
        ROWS, Cc, Cc, HIDd, HIDd, HIDd, Cc,
        1, 0, 0, 0, 0, 0, 0, 6 * Cc);
}

// round 14
// speedup vs baseline: 4.4689x; 1.0118x over previous
#include <cuda_runtime.h>
#include <cuda_fp16.h>
#include <cstdint>
#include <math.h>

// ---------------------------------------------------------------------------
// SanaBlock: LN+adaLN -> LiteLA -> cross-attn -> GLUMBConv, B=2,N=4096,C=1152
// R14: BK templated (scores uses BK=32 to cut K-pad waste), vt fused into the
//      kv GEMM epilogue, prologue kernels merged. GEMM core as R13.
// ---------------------------------------------------------------------------
constexpr int Bb   = 2;
constexpr int Nn   = 4096;
constexpr int Cc   = 1152;
constexpr int Mkv  = 300;
constexpr int HIDd = 2880;
constexpr int HLA  = 36;
constexpr int HX   = 16;
constexpr int SLD  = 320;

__device__ __align__(256) float  g_big [47185920];
__device__ __align__(256) __half g_shh [(size_t)Bb * Nn * Cc];
__device__ __align__(256) float  g_x1  [(size_t)Bb * Nn * Cc];
__device__ __align__(256) __half g_x1h [(size_t)Bb * Nn * Cc];
__device__ __align__(256) float  g_x2  [(size_t)Bb * Nn * Cc];
__device__ __align__(256) __half g_glu [(size_t)Bb * Nn * HIDd];
__device__ __align__(256) __half g_kvb [(size_t)Bb * Mkv * 2 * Cc];
__device__ __align__(256) __half g_vt  [(size_t)Bb * HX * 72 * SLD];
__device__ __align__(256) __half g_prb [(size_t)Bb * HX * Nn * SLD];
__device__ __align__(256) __half g_yh  [(size_t)Bb * Mkv * Cc];
__device__ __align__(256) __half g_wts [20570112];
__device__ float g_vk [Bb * HLA * 33 * 32];   // transposed: [bh][d:32][e:33]
__device__ float g_mb [Bb * 6 * Cc];

constexpr size_t W_QKV = 0;
constexpr size_t W_APR = W_QKV + (size_t)3 * Cc * Cc;
constexpr size_t W_Q   = W_APR + (size_t)Cc * Cc;
constexpr size_t W_KV  = W_Q   + (size_t)Cc * Cc;
constexpr size_t W_CPR = W_KV  + (size_t)2 * Cc * Cc;
constexpr size_t W_INV = W_CPR + (size_t)Cc * Cc;
constexpr size_t W_PW  = W_INV + (size_t)2 * HIDd * Cc;

// ---------------------------------------------------------------------------
// FMA-only transcendentals
// ---------------------------------------------------------------------------
__device__ __forceinline__ float fexp(float t){
    t = fminf(fmaxf(t, -87.0f), 87.0f);
    float z = t * 1.4426950408889634f;
    float n = floorf(z);
    float f = z - n;
    float p = 1.5403530e-4f;
    p = fmaf(p, f, 1.3333558e-3f);
    p = fmaf(p, f, 9.6181291e-3f);
    p = fmaf(p, f, 5.5504109e-2f);
    p = fmaf(p, f, 2.4022651e-1f);
    p = fmaf(p, f, 6.9314718e-1f);
    p = fmaf(p, f, 1.0f);
    int i = (int)n;
    return p * __int_as_float((i + 127) << 23);
}
__device__ __forceinline__ float fsigmoid(float x){
    float u = fexp(-fabsf(x));
    float z = 1.0f + u;                    // [1,2]
    float y = fmaf(-0.47058824f, z, 1.4117647f);
    y = y * fmaf(-z, y, 2.0f);
    y = y * fmaf(-z, y, 2.0f);
    return (x >= 0.f) ? y : 1.0f - y;
}
__device__ __forceinline__ float fsilu(float x){ return x * fsigmoid(x); }

// ---------------------------------------------------------------------------
// helpers
// ---------------------------------------------------------------------------
__device__ __forceinline__ uint32_t smem_u32(const void* p){
    uint32_t a;
    asm("{ .reg .u64 t; cvta.to.shared.u64 t, %1; cvt.u32.u64 %0, t; }"
        : "=r"(a) : "l"(p));
    return a;
}
__device__ __forceinline__ void cp16(uint32_t dst, const void* src, int srcsz){
    asm volatile("cp.async.cg.shared.global [%0], [%1], 16, %2;"
        ::"r"(dst),"l"(src),"r"(srcsz):"memory");
}
#define CP_COMMIT() asm volatile("cp.async.commit_group;":::"memory")
#define CP_WAIT1()  asm volatile("cp.async.wait_group 1;":::"memory")

__device__ __forceinline__ void mma16(float* d, const uint32_t* a, const uint32_t* b){
    asm volatile("mma.sync.aligned.m16n8k16.row.col.f32.f16.f16.f32 "
        "{%0,%1,%2,%3},{%4,%5,%6,%7},{%8,%9},{%0,%1,%2,%3};"
        : "+f"(d[0]),"+f"(d[1]),"+f"(d[2]),"+f"(d[3])
        : "r"(a[0]),"r"(a[1]),"r"(a[2]),"r"(a[3]),"r"(b[0]),"r"(b[1]));
}
__device__ __forceinline__ void ldsm4(uint32_t& r0, uint32_t& r1, uint32_t& r2,
                                      uint32_t& r3, uint32_t addr){
    asm volatile("ldmatrix.sync.aligned.m8n8.x4.shared.b16 {%0,%1,%2,%3}, [%4];"
        : "=r"(r0),"=r"(r1),"=r"(r2),"=r"(r3) : "r"(addr));
}

// ---------------------------------------------------------------------------
// fp16 mma NT GEMM, BK templated (32 or 64): 3-stage cp.async, 1 barrier/tile.
// CTA 128x128, 8 warps (4M x 2N), warp tile 32x64, ldmatrix.x4 fragments.
// VT: also scatter v-half of kv output into g_vt (transposed, padded).
// ---------------------------------------------------------------------------
template<int BK> struct GK {
    static constexpr int LDPH    = BK + 8;
    static constexpr int TILE_H  = 128 * LDPH;
    static constexpr int STAGE_H = 2 * TILE_H;
    static constexpr int SMEM    = 3 * STAGE_H * 2;
};
constexpr int MM_SMEM64 = GK<64>::SMEM;   // 110592
constexpr int MM_SMEM32 = GK<32>::SMEM;   // 61440

template<bool BIAS, int EPI, bool WF, bool WH, int BK, bool VT>
__global__ __launch_bounds__(256, 2)
void mma_gemm(const __half* A, const __half* Bw, const float* bias,
              const float* res, const float* gate,
              float* Of, __half* Oh, __half* vtout,
              int Mrows, int NloadB, int Nstore, int K,
              int lda, int ldb, int ldo,
              int HB, long aBs, long aHs, long bBs, long bHs, long oBs, long oHs,
              int gateStride)
{
    constexpr int LDPH    = GK<BK>::LDPH;
    constexpr int TILE_H  = GK<BK>::TILE_H;
    constexpr int STAGE_H = GK<BK>::STAGE_H;
    constexpr int CPR     = BK / 8;        // cp16 chunks per row
    constexpr int LITER   = BK / 16;       // load iterations (per matrix)

    extern __shared__ __half smh[];
    uint32_t sbase = smem_u32(smh);
    int tid = threadIdx.x, wid = tid >> 5, lane = tid & 31;
    int warpM = wid >> 1, warpN = wid & 1;
    int m0 = blockIdx.y * 128, n0 = blockIdx.x * 128;

    if (gridDim.z > 1) {
        int z = blockIdx.z;
        int bI = z / HB, hI = z % HB;
        A  += bI * aBs + hI * aHs;
        Bw += bI * bBs + hI * bHs;
        if (WF) Of += bI * oBs + hI * oHs;
        if (WH) Oh += bI * oBs + hI * oHs;
    }

    const int T = (K + BK - 1) / BK;

    auto load_tile = [&](int t, int buf) {
        uint32_t base = sbase + (uint32_t)buf * STAGE_H * 2;
        int k0 = t * BK;
        #pragma unroll
        for (int i = 0; i < LITER; i++) {
            int c = tid + (i << 8);
            int row = c / CPR, ch = c % CPR;
            int gk = k0 + ch * 8;
            uint32_t dst = base + (uint32_t)(row * LDPH + ch * 8) * 2;
            const __half* ga = A + (size_t)(m0 + row) * lda + gk;
            cp16(dst, ga, ((m0 + row) < Mrows && gk < K) ? 16 : 0);
        }
        #pragma unroll
        for (int i = 0; i < LITER; i++) {
            int c = tid + (i << 8);
            int row = c / CPR, ch = c % CPR;
            int gk = k0 + ch * 8;
            uint32_t dst = base + (uint32_t)(TILE_H + row * LDPH + ch * 8) * 2;
            const __half* gb = Bw + (size_t)(n0 + row) * ldb + gk;
            cp16(dst, gb, ((n0 + row) < NloadB && gk < K) ? 16 : 0);
        }
    };

    float acc[2][8][4];
    #pragma unroll
    for (int mt = 0; mt < 2; mt++)
        #pragma unroll
        for (int nt = 0; nt < 8; nt++)
            #pragma unroll
            for (int q = 0; q < 4; q++) acc[mt][nt][q] = 0.f;

    load_tile(0, 0); CP_COMMIT();
    load_tile(1, 1); CP_COMMIT();

    int rowA = warpM * 32 + (lane & 15);
    int colA = (lane >> 4) << 3;
    int rowB = warpN * 64 + (lane & 7) + ((lane >> 4) << 3);
    int colB = ((lane >> 3) & 1) << 3;
    uint32_t offA = (uint32_t)(rowA * LDPH + colA) * 2;
    uint32_t offB = (uint32_t)(TILE_H + rowB * LDPH + colB) * 2;

    for (int t = 0; t < T; t++) {
        int buf = t % 3;
        CP_WAIT1();
        __syncthreads();
        if (t + 2 < T) load_tile(t + 2, (t + 2) % 3);
        CP_COMMIT();

        uint32_t sA = sbase + (uint32_t)buf * STAGE_H * 2;

        #pragma unroll
        for (int kk = 0; kk < BK / 16; kk++) {
            uint32_t af[2][4];
            #pragma unroll
            for (int mt = 0; mt < 2; mt++) {
                uint32_t addr = sA + offA + (uint32_t)(mt * 16 * LDPH + kk * 16) * 2;
                ldsm4(af[mt][0], af[mt][1], af[mt][2], af[mt][3], addr);
            }
            uint32_t bf[8][2];
            #pragma unroll
            for (int ntp = 0; ntp < 4; ntp++) {
                uint32_t addr = sA + offB + (uint32_t)(ntp * 16 * LDPH + kk * 16) * 2;
                ldsm4(bf[2 * ntp][0], bf[2 * ntp][1],
                      bf[2 * ntp + 1][0], bf[2 * ntp + 1][1], addr);
            }
            #pragma unroll
            for (int mt = 0; mt < 2; mt++)
                #pragma unroll
                for (int nt = 0; nt < 8; nt++)
                    mma16(acc[mt][nt], af[mt], bf[nt]);
        }
    }

    #pragma unroll
    for (int mt = 0; mt < 2; mt++) {
        #pragma unroll
        for (int half_ = 0; half_ < 2; half_++) {
            int row = m0 + warpM * 32 + mt * 16 + (lane >> 2) + half_ * 8;
            if (row >= Mrows) continue;
            int bI = (row >= Nn) ? 1 : 0;
            #pragma unroll
            for (int nt = 0; nt < 8; nt++) {
                int col = n0 + warpN * 64 + nt * 8 + (lane & 3) * 2;
                if (col >= Nstore) continue;
                float v0 = acc[mt][nt][half_ * 2];
                float v1 = acc[mt][nt][half_ * 2 + 1];
                if (BIAS) { v0 += bias[col]; v1 += bias[col + 1]; }
                if (EPI == 1) { v0 = fsilu(v0); v1 = fsilu(v1); }
                if (EPI == 2) {
                    v0 += res[(size_t)row * ldo + col];
                    v1 += res[(size_t)row * ldo + col + 1];
                }
                if (EPI == 3) {
                    v0 = res[(size_t)row * ldo + col]     + gate[bI * gateStride + col]     * v0;
                    v1 = res[(size_t)row * ldo + col + 1] + gate[bI * gateStride + col + 1] * v1;
                }
                if (WF) *(float2*)&Of[(size_t)row * ldo + col] = make_float2(v0, v1);
                if (WH) *(__half2*)&Oh[(size_t)row * ldo + col] = __floats2half2_rn(v0, v1);
                if (VT) {
                    // kv GEMM only: scatter v-half into vt[(b*HX+h)*72+d][m]
                    if (col >= Cc) {
                        int bb = row / Mkv, m = row - bb * Mkv;
                        int hd = col - Cc;
                        int hh = hd / 72, dd = hd - hh * 72;   // dd even => dd+1 valid
                        __half* vb = vtout + ((size_t)(bb * HX + hh) * 72 + dd) * SLD + m;
                        vb[0]   = __float2half_rn(v0);
                        vb[SLD] = __float2half_rn(v1);
                    }
                }
            }
        }
    }
}

// ---------------------------------------------------------------------------
// prologue: weight/y fp16 conversion + m=sst+t + vk zero + vt zero, ONE launch
// ---------------------------------------------------------------------------
__global__ void round_all_kernel(const float* qkv_w, const float* aproj_w,
                                 const float* q_w, const float* kv_w,
                                 const float* cproj_w, const float* inv_w,
                                 const float* pw_w, const float* y,
                                 const float* t, const float* sst)
{
    long i = (long)blockIdx.x * 256 + threadIdx.x;
    long n;
    n = (long)3 * Cc * Cc;   if (i < n) { g_wts[W_QKV + i] = __float2half_rn(qkv_w[i]);   return; } i -= n;
    n = (long)Cc * Cc;       if (i < n) { g_wts[W_APR + i] = __float2half_rn(aproj_w[i]); return; } i -= n;
    n = (long)Cc * Cc;       if (i < n) { g_wts[W_Q   + i] = __float2half_rn(q_w[i]);     return; } i -= n;
    n = (long)2 * Cc * Cc;   if (i < n) { g_wts[W_KV  + i] = __float2half_rn(kv_w[i]);    return; } i -= n;
    n = (long)Cc * Cc;       if (i < n) { g_wts[W_CPR + i] = __float2half_rn(cproj_w[i]); return; } i -= n;
    n = (long)2 * HIDd * Cc; if (i < n) { g_wts[W_INV + i] = __float2half_rn(inv_w[i]);   return; } i -= n;
    n = (long)Cc * HIDd;     if (i < n) { g_wts[W_PW  + i] = __float2half_rn(pw_w[i]);    return; } i -= n;
    n = (long)Bb * Mkv * Cc; if (i < n) { g_yh[i] = __float2half_rn(y[i]);                return; } i -= n;
    n = (long)Bb * 6 * Cc;   if (i < n) { g_mb[i] = sst[i % (6 * Cc)] + t[i];             return; } i -= n;
    n = (long)Bb * HLA * 33 * 32; if (i < n) { g_vk[i] = 0.f;                             return; } i -= n;
    n = (long)Bb * HX * 72 * SLD; if (i < n) { g_vt[i] = __float2half_rn(0.f); }
}

// ---------------------------------------------------------------------------
__global__ __launch_bounds__(256)
void ln_mod_kernel(const float* __restrict__ in, __half* __restrict__ out,
                   int scRow, int shRow)
{
    int row = blockIdx.x;
    int b   = row / Nn;
    const float* xr = in + (size_t)row * Cc;

    float s = 0.f, s2 = 0.f;
    for (int c = threadIdx.x; c < Cc; c += blockDim.x) {
        float v = xr[c]; s += v; s2 += v * v;
    }
    __shared__ float sh1[8], sh2[8];
    int lane = threadIdx.x & 31, wid = threadIdx.x >> 5;
    #pragma unroll
    for (int o = 16; o > 0; o >>= 1) {
        s  += __shfl_down_sync(0xffffffffu, s,  o);
        s2 += __shfl_down_sync(0xffffffffu, s2, o);
    }
    if (lane == 0) { sh1[wid] = s; sh2[wid] = s2; }
    __syncthreads();
    if (wid == 0) {
        s  = (lane < 8) ? sh1[lane] : 0.f;
        s2 = (lane < 8) ? sh2[lane] : 0.f;
        #pragma unroll
        for (int o = 4; o > 0; o >>= 1) {
            s  += __shfl_down_sync(0xffffffffu, s,  o);
            s2 += __shfl_down_sync(0xffffffffu, s2, o);
        }
        if (lane == 0) { sh1[0] = s; sh2[0] = s2; }
    }
    __syncthreads();
    float mu   = sh1[0] * (1.f / Cc);
    float var  = sh2[0] * (1.f / Cc) - mu * mu;
    float rstd = rsqrtf(var + 1e-6f);
    const float* mbp = g_mb + (size_t)b * 6 * Cc;
    for (int c = threadIdx.x; c < Cc; c += blockDim.x) {
        float sc = mbp[scRow * Cc + c];
        float sv = mbp[shRow * Cc + c];
        out[(size_t)row * Cc + c] =
            __float2half_rn((xr[c] - mu) * rstd * (1.f + sc) + sv);
    }
}

// ---------------------------------------------------------------------------
// LiteLA vk accumulation (transposed out) + epilogue
// ---------------------------------------------------------------------------
__global__ __launch_bounds__(256)
void vk_kernel(const __half* __restrict__ qkv, float* __restrict__ vkout)
{
    int bh = blockIdx.x;
    int b  = bh / HLA, h = bh % HLA;
    int split = blockIdx.y;
    __shared__ float ks[32][33];
    __shared__ float vs[32][33];
    float acc[5] = {0.f, 0.f, 0.f, 0.f, 0.f};
    int tid = threadIdx.x;
    const size_t base = (size_t)b * Nn * 3 * Cc;
    int nStart = split * (Nn / 16);
    for (int n0 = nStart; n0 < nStart + Nn / 16; n0 += 32) {
        for (int li = tid; li < 1024; li += 256) {
            int nn = li >> 5, dc = li & 31;
            size_t off = base + (size_t)(n0 + nn) * 3 * Cc + h * 32 + dc;
            ks[nn][dc] = fmaxf(__half2float(qkv[off + Cc]), 0.f);
            vs[nn][dc] = __half2float(qkv[off + 2 * Cc]);
        }
        __syncthreads();
        #pragma unroll
        for (int u = 0; u < 5; u++) {
            int idx = tid + 256 * u;
            if (idx < 1056) {
                int e = idx >> 5, dc = idx & 31;
                float a = acc[u];
                if (e == 32) {
                    #pragma unroll
                    for (int nn = 0; nn < 32; nn++) a += ks[nn][dc];
                } else {
                    #pragma unroll
                    for (int nn = 0; nn < 32; nn++) a += vs[nn][e] * ks[nn][dc];
                }
                acc[u] = a;
            }
        }
        __syncthreads();
    }
    #pragma unroll
    for (int u = 0; u < 5; u++) {
        int idx = tid + 256 * u;
        if (idx < 1056) {
            int e = idx >> 5, dc = idx & 31;
            atomicAdd(&vkout[((size_t)bh * 32 + dc) * 33 + e], acc[u]);
        }
    }
}

__global__ __launch_bounds__(256)
void la_out_kernel(const __half* __restrict__ qkv, const float* __restrict__ vk,
                   __half* __restrict__ out)
{
    int row = blockIdx.x;
    int b   = row / Nn;
    __shared__ float q[Cc];
    __shared__ float rden[HLA];
    const __half* qr = qkv + (size_t)row * 3 * Cc;
    for (int c = threadIdx.x; c < Cc; c += blockDim.x)
        q[c] = fmaxf(__half2float(qr[c]), 0.f);
    __syncthreads();
    if (threadIdx.x < HLA) {
        int h = threadIdx.x;
        const float* vkh = vk + (size_t)(b * HLA + h) * 32 * 33;
        float s = 0.f;
        #pragma unroll
        for (int d = 0; d < 32; d++) s += vkh[d * 33 + 32] * q[h * 32 + d];
        rden[h] = 1.0f / (s + 1e-8f);
    }
    __syncthreads();
    for (int c = threadIdx.x; c < Cc; c += blockDim.x) {
        int h = c >> 5, dd = c & 31;
        const float* vkr = vk + (size_t)(b * HLA + h) * 32 * 33 + dd;
        const float* qh  = q + h * 32;
        float s = 0.f;
        #pragma unroll
        for (int d = 0; d < 32; d++) s += vkr[d * 33] * qh[d];
        out[(size_t)row * Cc + c] = __float2half_rn(s * rden[h]);
    }
}

// ---------------------------------------------------------------------------
__global__ __launch_bounds__(256)
void softmax_kernel(const float* __restrict__ s, __half* __restrict__ p, long rows)
{
    long gw  = ((long)blockIdx.x * blockDim.x + threadIdx.x) >> 5;
    int lane = threadIdx.x & 31;
    if (gw >= rows) return;
    const float* r = s + gw * SLD;
    __half* rp = p + gw * SLD;
    const float scale = 0.11785113019775793f;
    float v[10];
    float mx = -1e30f;
    #pragma unroll
    for (int i = 0; i < 10; i++) {
        int m = lane + 32 * i;
        v[i] = (m < Mkv) ? r[m] * scale : -1e30f;
        mx = fmaxf(mx, v[i]);
    }
    #pragma unroll
    for (int o = 16; o > 0; o >>= 1) mx = fmaxf(mx, __shfl_xor_sync(0xffffffffu, mx, o));
    float sum = 0.f;
    #pragma unroll
    for (int i = 0; i < 10; i++) { v[i] = fexp(v[i] - mx); sum += v[i]; }
    #pragma unroll
    for (int o = 16; o > 0; o >>= 1) sum += __shfl_xor_sync(0xffffffffu, sum, o);
    float inv = 1.f / sum;
    #pragma unroll
    for (int i = 0; i < 10; i++) {
        int m = lane + 32 * i;
        rp[m] = __float2half_rn((m < Mkv) ? v[i] * inv : 0.f);
    }
}

// ---------------------------------------------------------------------------
__global__ __launch_bounds__(256)
void dwglu_kernel(const __half* __restrict__ h, const float* __restrict__ dww,
                  const float* __restrict__ dwb, __half* __restrict__ out)
{
    __shared__ float sa[100][64];
    __shared__ float sg[100][64];
    int tid = threadIdx.x;
    int c0  = blockIdx.x * 64;
    int y0  = (blockIdx.y >> 3) * 8, x0 = (blockIdx.y & 7) * 8;
    int b   = blockIdx.z;

    int ch = tid & 63;
    float wA[9], wG[9];
    #pragma unroll
    for (int tp = 0; tp < 9; tp++) {
        wA[tp] = dww[(size_t)(c0 + ch) * 9 + tp];
        wG[tp] = dww[(size_t)(c0 + ch + HIDd) * 9 + tp];
    }
    float bA = dwb[c0 + ch], bG = dwb[c0 + ch + HIDd];

    for (int li = tid; li < 1600; li += 256) {
        int pos = li >> 4, q = li & 15;
        int py = pos / 10, px = pos % 10;
        int yy = y0 + py - 1, xx = x0 + px - 1;
        float4 va = make_float4(0.f, 0.f, 0.f, 0.f), vg = va;
        if (yy >= 0 && yy < 64 && xx >= 0 && xx < 64) {
            const __half* src = h + ((size_t)b * Nn + yy * 64 + xx) * (2 * HIDd) + c0 + q * 4;
            float2 a01 = __half22float2(*(const __half2*)src);
            float2 a23 = __half22float2(*(const __half2*)(src + 2));
            float2 g01 = __half22float2(*(const __half2*)(src + HIDd));
            float2 g23 = __half22float2(*(const __half2*)(src + HIDd + 2));
            va = make_float4(a01.x, a01.y, a23.x, a23.y);
            vg = make_float4(g01.x, g01.y, g23.x, g23.y);
        }
        *(float4*)&sa[pos][q * 4] = va;
        *(float4*)&sg[pos][q * 4] = vg;
    }
    __syncthreads();

    #pragma unroll
    for (int i = 0; i < 16; i++) {
        int pos = (tid >> 6) + i * 4;
        int py = pos >> 3, px = pos & 7;
        int s0 = (py + 1) * 10 + (px + 1);
        float accA = bA, accG = bG;
        #pragma unroll
        for (int dy = -1; dy <= 1; dy++)
            #pragma unroll
            for (int dx = -1; dx <= 1; dx++) {
                int s = s0 + dy * 10 + dx;
                int tp = (dy + 1) * 3 + (dx + 1);
                accA = fmaf(sa[s][ch], wA[tp], accA);
                accG = fmaf(sg[s][ch], wG[tp], accG);
            }
        int n = (y0 + py) * 64 + (x0 + px);
        out[((size_t)b * Nn + n) * HIDd + c0 + ch] =
            __float2half_rn(accA * fsilu(accG));
    }
}

// ---------------------------------------------------------------------------
extern "C" void kernel_launch(void* const* d_in, const int* /*in_sizes*/, int /*n_in*/,
                              void* d_out, int /*out_size*/)
{
    const float* x       = (const float*)d_in[0];
    const float* y       = (const float*)d_in[1];
    const float* t       = (const float*)d_in[2];
    const float* sst     = (const float*)d_in[3];
    const float* qkv_w   = (const float*)d_in[4];
    const float* aproj_w = (const float*)d_in[5];
    const float* aproj_b = (const float*)d_in[6];
    const float* q_w     = (const float*)d_in[7];
    const float* q_b     = (const float*)d_in[8];
    const float* kv_w    = (const float*)d_in[9];
    const float* kv_b    = (const float*)d_in[10];
    const float* cproj_w = (const float*)d_in[11];
    const float* cproj_b = (const float*)d_in[12];
    const float* inv_w   = (const float*)d_in[13];
    const float* inv_b   = (const float*)d_in[14];
    const float* dw_w    = (const float*)d_in[15];
    const float* dw_b    = (const float*)d_in[16];
    const float* pw_w    = (const float*)d_in[17];
    float* out = (float*)d_out;

    float  *p_big, *p_x1, *p_x2, *p_vk, *p_m;
    __half *p_shh, *p_x1h, *p_glu, *p_kvh, *p_vt, *p_prb, *p_yh, *p_w;
    cudaGetSymbolAddress((void**)&p_big, g_big);
    cudaGetSymbolAddress((void**)&p_shh, g_shh);
    cudaGetSymbolAddress((void**)&p_x1,  g_x1);
    cudaGetSymbolAddress((void**)&p_x1h, g_x1h);
    cudaGetSymbolAddress((void**)&p_x2,  g_x2);
    cudaGetSymbolAddress((void**)&p_glu, g_glu);
    cudaGetSymbolAddress((void**)&p_kvh, g_kvb);
    cudaGetSymbolAddress((void**)&p_vt,  g_vt);
    cudaGetSymbolAddress((void**)&p_prb, g_prb);
    cudaGetSymbolAddress((void**)&p_yh,  g_yh);
    cudaGetSymbolAddress((void**)&p_vk,  g_vk);
    cudaGetSymbolAddress((void**)&p_m,   g_mb);
    cudaGetSymbolAddress((void**)&p_w,   g_wts);

    __half* p_bigh = (__half*)p_big;

    cudaFuncSetAttribute(mma_gemm<false,0,false,true ,64,false>, cudaFuncAttributeMaxDynamicSharedMemorySize, MM_SMEM64);
    cudaFuncSetAttribute(mma_gemm<true ,3,true ,true ,64,false>, cudaFuncAttributeMaxDynamicSharedMemorySize, MM_SMEM64);
    cudaFuncSetAttribute(mma_gemm<true ,0,false,true ,64,false>, cudaFuncAttributeMaxDynamicSharedMemorySize, MM_SMEM64);
    cudaFuncSetAttribute(mma_gemm<true ,0,false,true ,64,true >, cudaFuncAttributeMaxDynamicSharedMemorySize, MM_SMEM64);
    cudaFuncSetAttribute(mma_gemm<false,0,true ,false,32,false>, cudaFuncAttributeMaxDynamicSharedMemorySize, MM_SMEM32);
    cudaFuncSetAttribute(mma_gemm<true ,2,true ,false,64,false>, cudaFuncAttributeMaxDynamicSharedMemorySize, MM_SMEM64);
    cudaFuncSetAttribute(mma_gemm<true ,1,false,true ,64,false>, cudaFuncAttributeMaxDynamicSharedMemorySize, MM_SMEM64);
    cudaFuncSetAttribute(mma_gemm<false,3,true ,false,64,false>, cudaFuncAttributeMaxDynamicSharedMemorySize, MM_SMEM64);

    const int ROWS = Bb * Nn;
    const long RN_TOTAL = (long)3*Cc*Cc + 5L*Cc*Cc + 2L*HIDd*Cc + (long)Cc*HIDd
                        + (long)Bb*Mkv*Cc + (long)Bb*6*Cc
                        + (long)Bb*HLA*33*32 + (long)Bb*HX*72*SLD;

    round_all_kernel<<<(int)((RN_TOTAL + 255) / 256), 256>>>(
        qkv_w, aproj_w, q_w, kv_w, cproj_w, inv_w, pw_w, y, t, sst);
    ln_mod_kernel<<<ROWS, 256>>>(x, p_shh, 1, 0);

    // qkv = xmod1 @ qkv_w.T
    mma_gemm<false,0,false,true,64,false><<<dim3(27, 64), 256, MM_SMEM64>>>(
        p_shh, p_w + W_QKV, nullptr, nullptr, nullptr, nullptr, p_bigh, nullptr,
        ROWS, 3 * Cc, 3 * Cc, Cc, Cc, Cc, 3 * Cc,
        1, 0, 0, 0, 0, 0, 0, 0);

    vk_kernel<<<dim3(Bb * HLA, 16), 256>>>(p_bigh, p_vk);
    la_out_kernel<<<ROWS, 256>>>(p_bigh, p_vk, p_shh);

    // x1 = x + g_a * (la @ aproj_w.T + b)
    mma_gemm<true,3,true,true,64,false><<<dim3(9, 64), 256, MM_SMEM64>>>(
        p_shh, p_w + W_APR, aproj_b, x, p_m + 2 * Cc, p_x1, p_x1h, nullptr,
        ROWS, Cc, Cc, Cc, Cc, Cc, Cc,
        1, 0, 0, 0, 0, 0, 0, 6 * Cc);

    // q = x1 @ q_w.T + q_b
    mma_gemm<true,0,false,true,64,false><<<dim3(9, 64), 256, MM_SMEM64>>>(
        p_x1h, p_w + W_Q, q_b, nullptr, nullptr, nullptr, p_shh, nullptr,
        ROWS, Cc, Cc, Cc, Cc, Cc, Cc,
        1, 0, 0, 0, 0, 0, 0, 0);

    // kv = y @ kv_w.T + kv_b  (+ fused v^T scatter)
    mma_gemm<true,0,false,true,64,true><<<dim3(18, 5), 256, MM_SMEM64>>>(
        p_yh, p_w + W_KV, kv_b, nullptr, nullptr, nullptr, p_kvh, p_vt,
        Bb * Mkv, 2 * Cc, 2 * Cc, Cc, Cc, Cc, 2 * Cc,
        1, 0, 0, 0, 0, 0, 0, 0);

    // scores[z] = q_h @ k_h.T  (BK=32: K=72 -> T=3, less pad waste)
    mma_gemm<false,0,true,false,32,false><<<dim3(3, 32, Bb * HX), 256, MM_SMEM32>>>(
        p_shh, p_kvh, nullptr, nullptr, nullptr, p_big, nullptr, nullptr,
        Nn, Mkv, SLD, 72, Cc, 2 * Cc, SLD,
        HX, (long)Nn * Cc, 72, (long)Mkv * 2 * Cc, 72,
        (long)HX * Nn * SLD, (long)Nn * SLD, 0);

    softmax_kernel<<<(Bb * HX * Nn) / 8, 256>>>(p_big, p_prb, (long)Bb * HX * Nn);

    // o[z] = probs @ v^T
    mma_gemm<false,0,false,true,64,false><<<dim3(1, 32, Bb * HX), 256, MM_SMEM64>>>(
        p_prb, p_vt, nullptr, nullptr, nullptr, nullptr, p_shh, nullptr,
        Nn, 72, 72, SLD, SLD, SLD, Cc,
        HX, (long)HX * Nn * SLD, (long)Nn * SLD, (long)72 * SLD * HX, (long)72 * SLD,
        (long)Nn * Cc, 72, 0);

    // x2 = x1 + o @ cproj_w.T + b
    mma_gemm<true,2,true,false,64,false><<<dim3(9, 64), 256, MM_SMEM64>>>(
        p_shh, p_w + W_CPR, cproj_b, p_x1, nullptr, p_x2, nullptr, nullptr,
        ROWS, Cc, Cc, Cc, Cc, Cc, Cc,
        1, 0, 0, 0, 0, 0, 0, 0);

    ln_mod_kernel<<<ROWS, 256>>>(p_x2, p_shh, 4, 3);

    // h = silu(xmod2 @ inv_w.T + b)
    mma_gemm<true,1,false,true,64,false><<<dim3(45, 64), 256, MM_SMEM64>>>(
        p_shh, p_w + W_INV, inv_b, nullptr, nullptr, nullptr, p_bigh, nullptr,
        ROWS, 2 * HIDd, 2 * HIDd, Cc, Cc, Cc, 2 * HIDd,
        1, 0, 0, 0, 0, 0, 0, 0);

    dwglu_kernel<<<dim3(HIDd / 64, 64, Bb), 256>>>(p_bigh, dw_w, dw_b, p_glu);

    // out = x2 + g_m * (glu @ pw_w.T)
    mma_gemm<false,3,true,false,64,false><<<dim3(9, 64), 256, MM_SMEM64>>>(
        p_glu, p_w + W_PW, nullptr, p_x2, p_m + 5 * Cc, out, nullptr, nullptr,
        ROWS, Cc, Cc, HIDd, HIDd, HIDd, Cc,
        1, 0, 0, 0, 0, 0, 0, 6 * Cc);
}